// round 8
// baseline (speedup 1.0000x reference)
#include <cuda_runtime.h>
#include <cuda_bf16.h>
#include <cstdint>

#define D 512
#define SRC 128
#define TGT_STEPS 128
#define VOCAB 50000

typedef unsigned long long u64;

// ---------------- scratch (device globals; no allocation allowed) ----------------
__device__ __align__(16) float g_xpre[SRC * D];
__device__ __align__(16) float g_epre[TGT_STEPS * D];
__device__ __align__(16) float g_fencs[SRC * D];
__device__ __align__(16) float g_fencsT[D * SRC];
__device__ __align__(16) float g_H[TGT_STEPS * D];
__device__ __align__(16) float g_scores[TGT_STEPS * SRC];
__device__ __align__(16) float g_alpha[TGT_STEPS * SRC];
__device__ __align__(16) float g_CH[TGT_STEPS * 2 * D];
__device__ __align__(16) __nv_bfloat16 g_Mbf[TGT_STEPS * D];
__device__ __align__(16) __nv_bfloat16 g_Wobf[VOCAB * D];
__device__ float g_sumexp[TGT_STEPS];
__device__ float g_picked[TGT_STEPS];

// ---------------- helpers ----------------
__device__ __forceinline__ u64 pk2(float x, float y) {
    u64 r;
    asm("mov.b64 %0, {%1, %2};" : "=l"(r) : "f"(x), "f"(y));
    return r;
}
__device__ __forceinline__ float2 upk2(u64 v) {
    float2 r;
    asm("mov.b64 {%0, %1}, %2;" : "=f"(r.x), "=f"(r.y) : "l"(v));
    return r;
}
__device__ __forceinline__ void fma2(u64& d, u64 a, u64 b) {
    asm volatile("fma.rn.f32x2 %0, %1, %2, %0;" : "+l"(d) : "l"(a), "l"(b));
}
__device__ __forceinline__ uint32_t smem_u32(const void* p) {
    uint32_t a;
    asm("{ .reg .u64 t; cvta.to.shared.u64 t, %1; cvt.u32.u64 %0, t; }" : "=r"(a) : "l"(p));
    return a;
}
__device__ __forceinline__ uint32_t mapa_u32(uint32_t saddr, uint32_t rank) {
    uint32_t r;
    asm volatile("mapa.shared::cluster.u32 %0, %1, %2;" : "=r"(r) : "r"(saddr), "r"(rank));
    return r;
}
__device__ __forceinline__ void st_cluster_f32(uint32_t raddr, float v) {
    asm volatile("st.shared::cluster.f32 [%0], %1;" :: "r"(raddr), "f"(v) : "memory");
}
__device__ __forceinline__ void ldsm4(uint32_t& r0, uint32_t& r1, uint32_t& r2, uint32_t& r3,
                                      uint32_t addr) {
    asm volatile("ldmatrix.sync.aligned.m8n8.x4.shared.b16 {%0,%1,%2,%3}, [%4];"
                 : "=r"(r0), "=r"(r1), "=r"(r2), "=r"(r3) : "r"(addr));
}
__device__ __forceinline__ void mma_bf16(float* c, uint32_t a0, uint32_t a1, uint32_t a2,
                                         uint32_t a3, uint32_t b0, uint32_t b1) {
    asm volatile(
        "mma.sync.aligned.m16n8k16.row.col.f32.bf16.bf16.f32 "
        "{%0,%1,%2,%3}, {%4,%5,%6,%7}, {%8,%9}, {%0,%1,%2,%3};"
        : "+f"(c[0]), "+f"(c[1]), "+f"(c[2]), "+f"(c[3])
        : "r"(a0), "r"(a1), "r"(a2), "r"(a3), "r"(b0), "r"(b1));
}
__device__ __forceinline__ uint32_t sw128(uint32_t off) { return off ^ ((off >> 3) & 0x70); }
__device__ __forceinline__ float fast_tanh(float x) {
    float e = __expf(2.f * x);
    return __fdividef(e - 1.f, e + 1.f);
}

// ---------------- generic tiled SGEMM: out[m, n] = act(Xrow(m) . W[n,:] + bias[n]) ----
// 32x64 tile, 256 threads, f32x2 FMA. Output stride ldo; bias may be null.
__global__ void __launch_bounds__(256) gemm_kernel(
    const float* __restrict__ X0, const int* __restrict__ idx0,
    const float* __restrict__ W0, const float* __restrict__ b0,
    const float* __restrict__ X1, const int* __restrict__ idx1,
    const float* __restrict__ W1, const float* __restrict__ b1,
    float* __restrict__ oF0, float* __restrict__ oF1,
    __nv_bfloat16* __restrict__ oB,
    int K, int applyTanh, int ldo) {
    const int z = blockIdx.z;
    const float* X = z ? X1 : X0;
    const int* idx = z ? idx1 : idx0;
    const float* W = z ? W1 : W0;
    const float* bias = z ? b1 : b0;
    float* outF = z ? oF1 : oF0;

    __shared__ __align__(16) float Xs[64][34];
    __shared__ __align__(16) float Ws[64][68];
    __shared__ int roff[32];

    const int tid = threadIdx.x;
    const int tx = tid & 15, ty = tid >> 4;
    const int mbase = blockIdx.y * 32;
    const int nbase = blockIdx.x * 64;

    // zero g_sumexp ahead of logits (done in the m-GEMM which precedes logits)
    if (oB && blockIdx.x == 0 && blockIdx.y == 0 && z == 0 && tid < TGT_STEPS)
        g_sumexp[tid] = 0.f;

    if (tid < 32) {
        int m = mbase + tid;
        roff[tid] = (idx ? idx[m] : m) * K;
    }
    __syncthreads();

    u64 acc[2][2] = {{0ull, 0ull}, {0ull, 0ull}};

    for (int kt = 0; kt < K; kt += 64) {
#pragma unroll
        for (int j = 0; j < 2; j++) {
            int id = tid * 2 + j;
            int m = id >> 4, kq = id & 15;
            float4 v = *(const float4*)&X[roff[m] + kt + kq * 4];
            Xs[kq * 4 + 0][m] = v.x;
            Xs[kq * 4 + 1][m] = v.y;
            Xs[kq * 4 + 2][m] = v.z;
            Xs[kq * 4 + 3][m] = v.w;
        }
#pragma unroll
        for (int j = 0; j < 4; j++) {
            int id = tid + 256 * j;
            int n = id >> 4, kq = id & 15;
            float4 v = *(const float4*)&W[(size_t)(nbase + n) * K + kt + kq * 4];
            Ws[kq * 4 + 0][n] = v.x;
            Ws[kq * 4 + 1][n] = v.y;
            Ws[kq * 4 + 2][n] = v.z;
            Ws[kq * 4 + 3][n] = v.w;
        }
        __syncthreads();
#pragma unroll
        for (int k = 0; k < 64; k++) {
            float2 a = *(const float2*)&Xs[k][ty * 2];
            float4 b = *(const float4*)&Ws[k][tx * 4];
            u64 bp0 = pk2(b.x, b.y), bp1 = pk2(b.z, b.w);
            u64 a0 = pk2(a.x, a.x), a1 = pk2(a.y, a.y);
            fma2(acc[0][0], a0, bp0);
            fma2(acc[0][1], a0, bp1);
            fma2(acc[1][0], a1, bp0);
            fma2(acc[1][1], a1, bp1);
        }
        __syncthreads();
    }
#pragma unroll
    for (int r = 0; r < 2; r++) {
        int m = mbase + ty * 2 + r;
        float2 v0 = upk2(acc[r][0]), v1 = upk2(acc[r][1]);
        float o[4] = {v0.x, v0.y, v1.x, v1.y};
#pragma unroll
        for (int i = 0; i < 4; i++) {
            int n = nbase + tx * 4 + i;
            float val = o[i] + (bias ? bias[n] : 0.f);
            if (applyTanh) val = fast_tanh(val);
            if (outF) outF[(size_t)m * ldo + n] = val;
            else oB[(size_t)m * ldo + n] = __float2bfloat16(val);
        }
    }
}

// ---------------- K2: recurrences (y=0,1: 8-CTA clusters) + Wo->bf16 convert (y>=2) ----
#define CONV_YS 6
__global__ void __cluster_dims__(8, 1, 1) __launch_bounds__(512, 1)
recur_kernel(const float* __restrict__ Whh_e, const float* __restrict__ Whh_d,
             const float* __restrict__ h0_e, const float* __restrict__ h0_d,
             const float* __restrict__ Wo) {
    const int tid = threadIdx.x;

    if (blockIdx.y >= 2) {
        // ---- Wo fp32 -> bf16 converter ----
        const size_t n4 = (size_t)VOCAB * D / 4;
        const size_t gt = (size_t)((blockIdx.y - 2) * 8 + blockIdx.x) * 512 + tid;
        const size_t stride = (size_t)CONV_YS * 8 * 512;
        const float4* src = (const float4*)Wo;
        uint2* dst = (uint2*)g_Wobf;
        for (size_t i = gt; i < n4; i += stride) {
            float4 f = src[i];
            __nv_bfloat162 lo = __float22bfloat162_rn(make_float2(f.x, f.y));
            __nv_bfloat162 hi = __float22bfloat162_rn(make_float2(f.z, f.w));
            uint2 u;
            u.x = *(uint32_t*)&lo;
            u.y = *(uint32_t*)&hi;
            dst[i] = u;
        }
        return;
    }

    const int ph = blockIdx.y;
    const float* W = ph ? Whh_d : Whh_e;
    const float* h0 = ph ? h0_d : h0_e;
    const float* pre = ph ? g_epre : g_xpre;
    float* outg = ph ? g_H : g_fencs;

    __shared__ __align__(16) float hbuf[2][D];
    __shared__ float pre_s[128 * 64];

    const int rl = tid >> 3;
    const int sub = tid & 7;
    const uint32_t rank = blockIdx.x;
    const int row = rank * 64 + rl;

    u64 wv2[32];
#pragma unroll
    for (int j = 0; j < 16; j++) {
        ulonglong2 t = *(const ulonglong2*)&W[row * D + j * 32 + sub * 4];
        wv2[2 * j] = t.x;
        wv2[2 * j + 1] = t.y;
    }

    for (int i = tid; i < 128 * 64; i += 512) {
        int t = i >> 6, r = i & 63;
        pre_s[i] = pre[t * D + rank * 64 + r];
    }
    if (tid < D) hbuf[0][tid] = h0[tid];
    __syncthreads();

    const uint32_t dst_remote0 = mapa_u32(smem_u32(&hbuf[0][row]), (uint32_t)sub);

    int p = 0;
    for (int t = 0; t < 128; t++) {
        const float* hp = hbuf[p];
        u64 A0 = 0ull, A1 = 0ull;
#pragma unroll
        for (int j = 0; j < 16; j++) {
            ulonglong2 hv = *(const ulonglong2*)&hp[j * 32 + sub * 4];
            fma2(A0, wv2[2 * j], hv.x);
            fma2(A1, wv2[2 * j + 1], hv.y);
        }
        float2 f0 = upk2(A0), f1 = upk2(A1);
        float acc = (f0.x + f0.y) + (f1.x + f1.y);
#pragma unroll
        for (int o = 4; o; o >>= 1) acc += __shfl_xor_sync(0xffffffffu, acc, o);
        float h = fast_tanh(acc + pre_s[t * 64 + rl]);
        st_cluster_f32(dst_remote0 + (p ^ 1) * (D * 4), h);
        if (sub == 0) {
            outg[t * D + row] = h;
            if (ph == 0) g_fencsT[row * SRC + t] = h;          // transposed for ctx GEMM
            else g_CH[t * 2 * D + D + row] = h;                // H half of CH
        }
        asm volatile("barrier.cluster.arrive.aligned;" ::: "memory");
        asm volatile("barrier.cluster.wait.aligned;" ::: "memory");
        p ^= 1;
    }
}

// ---------------- softmax over scores rows -> g_alpha ----------------
__global__ void softmax_kernel() {
    int t = blockIdx.x;
    int tid = threadIdx.x, w = tid >> 5, l = tid & 31;
    __shared__ float red[8];
    float v = g_scores[t * SRC + tid];
    float mx = v;
#pragma unroll
    for (int o = 16; o; o >>= 1) mx = fmaxf(mx, __shfl_xor_sync(0xffffffffu, mx, o));
    if (l == 0) red[w] = mx;
    __syncthreads();
    mx = fmaxf(fmaxf(red[0], red[1]), fmaxf(red[2], red[3]));
    float e = __expf(v - mx);
    float sm = e;
#pragma unroll
    for (int o = 16; o; o >>= 1) sm += __shfl_xor_sync(0xffffffffu, sm, o);
    if (l == 0) red[4 + w] = sm;
    __syncthreads();
    sm = red[4] + red[5] + red[6] + red[7];
    g_alpha[t * SRC + tid] = e / sm;
}

// ---------------- K5: logits via mma.sync bf16 (B pre-converted) ----------------
#define OFF_BO 0
#define OFF_TGT 512
#define OFF_SEXP 1024
#define OFF_B 2048
#define OFF_A (2048 + 2 * 16384)
#define LOGITS_SMEM (OFF_A + 8 * 16384)

__global__ void __launch_bounds__(256, 1) logits_kernel(const float* __restrict__ bo,
                                                        const int* __restrict__ enums) {
    extern __shared__ char smem[];
    const uint32_t sb = smem_u32(smem);
    const int tid = threadIdx.x;
    const int lane = tid & 31;
    const int wm = (tid >> 5) & 3;
    const int wn = tid >> 7;
    const int vb = blockIdx.x * 128;

    float* bo_s = (float*)(smem + OFF_BO);
    int* tgt_s = (int*)(smem + OFF_TGT);
    float* sexp_s = (float*)(smem + OFF_SEXP);

    for (int i = tid; i < 128; i += 256) {
        int v = vb + i;
        bo_s[i] = (v < VOCAB) ? bo[v] : 0.f;
        tgt_s[i] = enums[i + 1];
        sexp_s[i] = 0.f;
    }

    for (int i = tid * 8; i < TGT_STEPS * D; i += 256 * 8) {
        int t = i >> 9, k = i & 511;
        uint4 v = *(const uint4*)&g_Mbf[i];
        int c = k >> 6, kk = k & 63;
        uint32_t sw = sw128(t * 128 + kk * 2);
        *(uint4*)(smem + OFF_A + c * 16384 + sw) = v;
    }

    const int rowl = tid >> 1, q = tid & 1;
    const bool vok = (vb + rowl) < VOCAB;
    const uint4* wsrc = (const uint4*)&g_Wobf[(size_t)(vb + rowl) * D];
    const uint4 Z = make_uint4(0u, 0u, 0u, 0u);

    uint4 pf[4];
#pragma unroll
    for (int j = 0; j < 4; j++) pf[j] = vok ? wsrc[q * 4 + j] : Z;

    float cacc[2][8][4];
#pragma unroll
    for (int mi = 0; mi < 2; mi++)
#pragma unroll
        for (int nn = 0; nn < 8; nn++)
#pragma unroll
            for (int e = 0; e < 4; e++) cacc[mi][nn][e] = 0.f;

    const int rowA = wm * 32 + (lane & 15);
    const int kselA = (lane >> 4) << 4;
    const int rowB = wn * 64 + (lane & 7) + ((lane & 16) >> 1);
    const int kselB = (lane & 8) << 1;

#pragma unroll 1
    for (int c = 0; c < 8; c++) {
        char* bbuf = smem + OFF_B + (c & 1) * 16384;
#pragma unroll
        for (int j = 0; j < 4; j++) {
            uint32_t sw = sw128(rowl * 128 + q * 64 + j * 16);
            *(uint4*)(bbuf + sw) = pf[j];
        }
        __syncthreads();
        if (c < 7) {
#pragma unroll
            for (int j = 0; j < 4; j++)
                pf[j] = vok ? wsrc[(c + 1) * 8 + q * 4 + j] : Z;
        }
        const uint32_t aBase = sb + OFF_A + c * 16384;
        const uint32_t bBase = sb + OFF_B + (c & 1) * 16384;
#pragma unroll
        for (int kk = 0; kk < 4; kk++) {
            uint32_t a[2][4];
#pragma unroll
            for (int mi = 0; mi < 2; mi++) {
                uint32_t off = (rowA + mi * 16) * 128 + kk * 32 + kselA;
                ldsm4(a[mi][0], a[mi][1], a[mi][2], a[mi][3], aBase + sw128(off));
            }
            uint32_t bf[4][4];
#pragma unroll
            for (int n2 = 0; n2 < 4; n2++) {
                uint32_t off = (rowB + n2 * 16) * 128 + kk * 32 + kselB;
                ldsm4(bf[n2][0], bf[n2][1], bf[n2][2], bf[n2][3], bBase + sw128(off));
            }
#pragma unroll
            for (int mi = 0; mi < 2; mi++)
#pragma unroll
                for (int nn = 0; nn < 8; nn++) {
                    uint32_t b0 = bf[nn >> 1][(nn & 1) * 2];
                    uint32_t b1 = bf[nn >> 1][(nn & 1) * 2 + 1];
                    mma_bf16(cacc[mi][nn], a[mi][0], a[mi][1], a[mi][2], a[mi][3], b0, b1);
                }
        }
    }

#pragma unroll
    for (int mi = 0; mi < 2; mi++) {
        int r0 = wm * 32 + mi * 16 + (lane >> 2);
        int r1 = r0 + 8;
        float s0 = 0.f, s1 = 0.f;
#pragma unroll
        for (int nn = 0; nn < 8; nn++) {
            int col = wn * 64 + nn * 8 + 2 * (lane & 3);
            const float* cc = cacc[mi][nn];
#pragma unroll
            for (int e = 0; e < 2; e++) {
                int v = vb + col + e;
                if (v < VOCAB) {
                    float lg0 = cc[e] + bo_s[col + e];
                    float lg1 = cc[2 + e] + bo_s[col + e];
                    s0 += __expf(lg0);
                    s1 += __expf(lg1);
                    if (v == tgt_s[r0]) g_picked[r0] = lg0;
                    if (v == tgt_s[r1]) g_picked[r1] = lg1;
                }
            }
        }
        s0 += __shfl_xor_sync(0xffffffffu, s0, 1);
        s0 += __shfl_xor_sync(0xffffffffu, s0, 2);
        s1 += __shfl_xor_sync(0xffffffffu, s1, 1);
        s1 += __shfl_xor_sync(0xffffffffu, s1, 2);
        if ((lane & 3) == 0) {
            atomicAdd(&sexp_s[r0], s0);
            atomicAdd(&sexp_s[r1], s1);
        }
    }
    __syncthreads();
    for (int i = tid; i < 128; i += 256) atomicAdd(&g_sumexp[i], sexp_s[i]);
}

// ---------------- K6: final reduction ----------------
__global__ void finalize_kernel(float* __restrict__ out) {
    int tid = threadIdx.x;
    float v = g_picked[tid] - logf(g_sumexp[tid]);
    __shared__ float red[4];
    int w = tid >> 5, l = tid & 31;
#pragma unroll
    for (int o = 16; o; o >>= 1) v += __shfl_xor_sync(0xffffffffu, v, o);
    if (l == 0) red[w] = v;
    __syncthreads();
    if (tid == 0) out[0] = red[0] + red[1] + red[2] + red[3];
}

// ---------------- launch ----------------
extern "C" void kernel_launch(void* const* d_in, const int* in_sizes, int n_in,
                              void* d_out, int out_size) {
    const int* fnums = (const int*)d_in[0];
    const int* enums = (const int*)d_in[1];
    const float* emb_f = (const float*)d_in[2];
    const float* Wih_e = (const float*)d_in[3];
    const float* Whh_e = (const float*)d_in[4];
    const float* b_e = (const float*)d_in[5];
    const float* h0_e = (const float*)d_in[6];
    const float* emb_d = (const float*)d_in[7];
    const float* Wih_d = (const float*)d_in[8];
    const float* Whh_d = (const float*)d_in[9];
    const float* b_d = (const float*)d_in[10];
    const float* h0_d = (const float*)d_in[11];
    const float* Wm = (const float*)d_in[12];
    const float* bm = (const float*)d_in[13];
    const float* Wo = (const float*)d_in[14];
    const float* bo = (const float*)d_in[15];
    float* out = (float*)d_out;

    static int inited = 0;
    static float *p_xpre, *p_epre, *p_CH, *p_H, *p_fencs, *p_fencsT, *p_alpha, *p_scores;
    static __nv_bfloat16* p_Mbf;
    if (!inited) {
        cudaFuncSetAttribute(logits_kernel, cudaFuncAttributeMaxDynamicSharedMemorySize,
                             LOGITS_SMEM);
        cudaGetSymbolAddress((void**)&p_xpre, g_xpre);
        cudaGetSymbolAddress((void**)&p_epre, g_epre);
        cudaGetSymbolAddress((void**)&p_CH, g_CH);
        cudaGetSymbolAddress((void**)&p_H, g_H);
        cudaGetSymbolAddress((void**)&p_fencs, g_fencs);
        cudaGetSymbolAddress((void**)&p_fencsT, g_fencsT);
        cudaGetSymbolAddress((void**)&p_alpha, g_alpha);
        cudaGetSymbolAddress((void**)&p_scores, g_scores);
        cudaGetSymbolAddress((void**)&p_Mbf, g_Mbf);
        inited = 1;
    }

    // pre-activations: encoder (z=0) + decoder (z=1) concurrently
    gemm_kernel<<<dim3(8, 4, 2), 256>>>(emb_f, fnums, Wih_e, b_e,
                                        emb_d, enums, Wih_d, b_d,
                                        p_xpre, p_epre, nullptr, D, 0, D);
    // recur (y=0,1) + Wo->bf16 conversion (y=2..) overlapped in one launch
    recur_kernel<<<dim3(8, 2 + CONV_YS), 512>>>(Whh_e, Whh_d, h0_e, h0_d, Wo);
    // scores[t,s] = H[t] . fencs[s]  (128x128x512 GEMM)
    gemm_kernel<<<dim3(2, 4, 1), 256>>>(p_H, nullptr, p_fencs, nullptr,
                                        p_H, nullptr, p_fencs, nullptr,
                                        p_scores, p_scores, nullptr, D, 0, SRC);
    softmax_kernel<<<128, 128>>>();
    // C = alpha @ fencs  (128x512x128 GEMM via fencsT), writes CH first half
    gemm_kernel<<<dim3(8, 4, 1), 256>>>(p_alpha, nullptr, p_fencsT, nullptr,
                                        p_alpha, nullptr, p_fencsT, nullptr,
                                        p_CH, p_CH, nullptr, SRC, 0, 2 * D);
    // M = tanh(CH @ Wm^T + bm) -> bf16 (also zeroes g_sumexp)
    gemm_kernel<<<dim3(8, 4, 1), 256>>>(p_CH, nullptr, Wm, bm,
                                        p_CH, nullptr, Wm, bm,
                                        nullptr, nullptr, p_Mbf, 2 * D, 1, D);
    logits_kernel<<<(VOCAB + 127) / 128, 256, LOGITS_SMEM>>>(bo, enums);
    finalize_kernel<<<1, 128>>>(out);
}

// round 9
// speedup vs baseline: 1.0285x; 1.0285x over previous
#include <cuda_runtime.h>
#include <cuda_bf16.h>
#include <cstdint>

#define D 512
#define SRC 128
#define TGT_STEPS 128
#define VOCAB 50000

typedef unsigned long long u64;

// ---------------- scratch (device globals; no allocation allowed) ----------------
__device__ __align__(16) float g_xpre[SRC * D];
__device__ __align__(16) float g_epre[TGT_STEPS * D];
__device__ __align__(16) float g_fencs[SRC * D];
__device__ __align__(16) float g_H[TGT_STEPS * D];
__device__ __align__(16) float g_scores[TGT_STEPS * SRC];
__device__ __align__(16) float g_alpha[TGT_STEPS * SRC];
__device__ __align__(16) float g_CH[TGT_STEPS * 2 * D];
__device__ __align__(16) __nv_bfloat16 g_Mbf[TGT_STEPS * D];
__device__ __align__(16) __nv_bfloat16 g_Wobf[VOCAB * D];
__device__ float g_sumexp[TGT_STEPS];
__device__ float g_picked[TGT_STEPS];

// ---------------- helpers ----------------
__device__ __forceinline__ u64 pk2(float x, float y) {
    u64 r;
    asm("mov.b64 %0, {%1, %2};" : "=l"(r) : "f"(x), "f"(y));
    return r;
}
__device__ __forceinline__ float2 upk2(u64 v) {
    float2 r;
    asm("mov.b64 {%0, %1}, %2;" : "=f"(r.x), "=f"(r.y) : "l"(v));
    return r;
}
__device__ __forceinline__ void fma2(u64& d, u64 a, u64 b) {
    asm volatile("fma.rn.f32x2 %0, %1, %2, %0;" : "+l"(d) : "l"(a), "l"(b));
}
__device__ __forceinline__ uint32_t smem_u32(const void* p) {
    uint32_t a;
    asm("{ .reg .u64 t; cvta.to.shared.u64 t, %1; cvt.u32.u64 %0, t; }" : "=r"(a) : "l"(p));
    return a;
}
__device__ __forceinline__ uint32_t mapa_u32(uint32_t saddr, uint32_t rank) {
    uint32_t r;
    asm volatile("mapa.shared::cluster.u32 %0, %1, %2;" : "=r"(r) : "r"(saddr), "r"(rank));
    return r;
}
__device__ __forceinline__ void st_cluster_f32(uint32_t raddr, float v) {
    asm volatile("st.shared::cluster.f32 [%0], %1;" :: "r"(raddr), "f"(v) : "memory");
}
__device__ __forceinline__ void ldsm4(uint32_t& r0, uint32_t& r1, uint32_t& r2, uint32_t& r3,
                                      uint32_t addr) {
    asm volatile("ldmatrix.sync.aligned.m8n8.x4.shared.b16 {%0,%1,%2,%3}, [%4];"
                 : "=r"(r0), "=r"(r1), "=r"(r2), "=r"(r3) : "r"(addr));
}
__device__ __forceinline__ void mma_bf16(float* c, uint32_t a0, uint32_t a1, uint32_t a2,
                                         uint32_t a3, uint32_t b0, uint32_t b1) {
    asm volatile(
        "mma.sync.aligned.m16n8k16.row.col.f32.bf16.bf16.f32 "
        "{%0,%1,%2,%3}, {%4,%5,%6,%7}, {%8,%9}, {%0,%1,%2,%3};"
        : "+f"(c[0]), "+f"(c[1]), "+f"(c[2]), "+f"(c[3])
        : "r"(a0), "r"(a1), "r"(a2), "r"(a3), "r"(b0), "r"(b1));
}
__device__ __forceinline__ uint32_t sw128(uint32_t off) { return off ^ ((off >> 3) & 0x70); }
__device__ __forceinline__ float fast_tanh(float x) {
    float e = __expf(2.f * x);
    return __fdividef(e - 1.f, e + 1.f);
}

// ---------------- generic tiled SGEMM: out[m, n] = act(Xrow(m) . W(n, :) + bias[n]) ----
// 32x64 tile, 256 threads, f32x2 FMA. W layout: row-major [N][K] (wKmajor=0)
// or K-major [K][N] with row stride ldw (wKmajor=1). Output stride ldo; bias nullable.
__global__ void __launch_bounds__(256) gemm_kernel(
    const float* __restrict__ X0, const int* __restrict__ idx0,
    const float* __restrict__ W0, const float* __restrict__ b0,
    const float* __restrict__ X1, const int* __restrict__ idx1,
    const float* __restrict__ W1, const float* __restrict__ b1,
    float* __restrict__ oF0, float* __restrict__ oF1,
    __nv_bfloat16* __restrict__ oB,
    int K, int applyTanh, int ldo, int wKmajor, int ldw) {
    const int z = blockIdx.z;
    const float* X = z ? X1 : X0;
    const int* idx = z ? idx1 : idx0;
    const float* W = z ? W1 : W0;
    const float* bias = z ? b1 : b0;
    float* outF = z ? oF1 : oF0;

    __shared__ __align__(16) float Xs[64][34];
    __shared__ __align__(16) float Ws[64][72];
    __shared__ int roff[32];

    const int tid = threadIdx.x;
    const int tx = tid & 15, ty = tid >> 4;
    const int mbase = blockIdx.y * 32;
    const int nbase = blockIdx.x * 64;

    // zero g_sumexp ahead of logits (done in the m-GEMM which precedes logits)
    if (oB && blockIdx.x == 0 && blockIdx.y == 0 && z == 0 && tid < TGT_STEPS)
        g_sumexp[tid] = 0.f;

    if (tid < 32) {
        int m = mbase + tid;
        roff[tid] = (idx ? idx[m] : m) * K;
    }
    __syncthreads();

    u64 acc[2][2] = {{0ull, 0ull}, {0ull, 0ull}};

    for (int kt = 0; kt < K; kt += 64) {
#pragma unroll
        for (int j = 0; j < 2; j++) {
            int id = tid * 2 + j;
            int m = id >> 4, kq = id & 15;
            float4 v = *(const float4*)&X[roff[m] + kt + kq * 4];
            Xs[kq * 4 + 0][m] = v.x;
            Xs[kq * 4 + 1][m] = v.y;
            Xs[kq * 4 + 2][m] = v.z;
            Xs[kq * 4 + 3][m] = v.w;
        }
        if (!wKmajor) {
#pragma unroll
            for (int j = 0; j < 4; j++) {
                int id = tid + 256 * j;
                int n = id >> 4, kq = id & 15;
                float4 v = *(const float4*)&W[(size_t)(nbase + n) * K + kt + kq * 4];
                Ws[kq * 4 + 0][n] = v.x;
                Ws[kq * 4 + 1][n] = v.y;
                Ws[kq * 4 + 2][n] = v.z;
                Ws[kq * 4 + 3][n] = v.w;
            }
        } else {
#pragma unroll
            for (int j = 0; j < 4; j++) {
                int id = tid + 256 * j;
                int kq = id >> 4, nq = id & 15;
                float4 v = *(const float4*)&W[(size_t)(kt + kq) * ldw + nbase + nq * 4];
                *(float4*)&Ws[kq][nq * 4] = v;
            }
        }
        __syncthreads();
#pragma unroll
        for (int k = 0; k < 64; k++) {
            float2 a = *(const float2*)&Xs[k][ty * 2];
            float4 b = *(const float4*)&Ws[k][tx * 4];
            u64 bp0 = pk2(b.x, b.y), bp1 = pk2(b.z, b.w);
            u64 a0 = pk2(a.x, a.x), a1 = pk2(a.y, a.y);
            fma2(acc[0][0], a0, bp0);
            fma2(acc[0][1], a0, bp1);
            fma2(acc[1][0], a1, bp0);
            fma2(acc[1][1], a1, bp1);
        }
        __syncthreads();
    }
#pragma unroll
    for (int r = 0; r < 2; r++) {
        int m = mbase + ty * 2 + r;
        float2 v0 = upk2(acc[r][0]), v1 = upk2(acc[r][1]);
        float o[4] = {v0.x, v0.y, v1.x, v1.y};
#pragma unroll
        for (int i = 0; i < 4; i++) {
            int n = nbase + tx * 4 + i;
            float val = o[i] + (bias ? bias[n] : 0.f);
            if (applyTanh) val = fast_tanh(val);
            if (outF) outF[(size_t)m * ldo + n] = val;
            else oB[(size_t)m * ldo + n] = __float2bfloat16(val);
        }
    }
}

// ---------------- K2: recurrences (y=0,1: 8-CTA clusters) + Wo->bf16 convert (y>=2) ----
#define CONV_YS 6
__global__ void __cluster_dims__(8, 1, 1) __launch_bounds__(512, 1)
recur_kernel(const float* __restrict__ Whh_e, const float* __restrict__ Whh_d,
             const float* __restrict__ h0_e, const float* __restrict__ h0_d,
             const float* __restrict__ Wo) {
    const int tid = threadIdx.x;

    if (blockIdx.y >= 2) {
        // ---- Wo fp32 -> bf16 converter ----
        const size_t n4 = (size_t)VOCAB * D / 4;
        const size_t gt = (size_t)((blockIdx.y - 2) * 8 + blockIdx.x) * 512 + tid;
        const size_t stride = (size_t)CONV_YS * 8 * 512;
        const float4* src = (const float4*)Wo;
        uint2* dst = (uint2*)g_Wobf;
        for (size_t i = gt; i < n4; i += stride) {
            float4 f = src[i];
            __nv_bfloat162 lo = __float22bfloat162_rn(make_float2(f.x, f.y));
            __nv_bfloat162 hi = __float22bfloat162_rn(make_float2(f.z, f.w));
            uint2 u;
            u.x = *(uint32_t*)&lo;
            u.y = *(uint32_t*)&hi;
            dst[i] = u;
        }
        return;
    }

    const int ph = blockIdx.y;
    const float* W = ph ? Whh_d : Whh_e;
    const float* h0 = ph ? h0_d : h0_e;
    const float* pre = ph ? g_epre : g_xpre;
    float* outg = ph ? g_H : g_fencs;

    __shared__ __align__(16) float hbuf[2][D];
    __shared__ float pre_s[128 * 64];

    const int rl = tid >> 3;
    const int sub = tid & 7;
    const uint32_t rank = blockIdx.x;
    const int row = rank * 64 + rl;

    u64 wv2[32];
#pragma unroll
    for (int j = 0; j < 16; j++) {
        ulonglong2 t = *(const ulonglong2*)&W[row * D + j * 32 + sub * 4];
        wv2[2 * j] = t.x;
        wv2[2 * j + 1] = t.y;
    }

    for (int i = tid; i < 128 * 64; i += 512) {
        int t = i >> 6, r = i & 63;
        pre_s[i] = pre[t * D + rank * 64 + r];
    }
    if (tid < D) hbuf[0][tid] = h0[tid];
    __syncthreads();

    const uint32_t dst_remote0 = mapa_u32(smem_u32(&hbuf[0][row]), (uint32_t)sub);

    int p = 0;
    for (int t = 0; t < 128; t++) {
        const float* hp = hbuf[p];
        u64 A0 = 0ull, A1 = 0ull;
#pragma unroll
        for (int j = 0; j < 16; j++) {
            ulonglong2 hv = *(const ulonglong2*)&hp[j * 32 + sub * 4];
            fma2(A0, wv2[2 * j], hv.x);
            fma2(A1, wv2[2 * j + 1], hv.y);
        }
        float2 f0 = upk2(A0), f1 = upk2(A1);
        float acc = (f0.x + f0.y) + (f1.x + f1.y);
#pragma unroll
        for (int o = 4; o; o >>= 1) acc += __shfl_xor_sync(0xffffffffu, acc, o);
        float h = fast_tanh(acc + pre_s[t * 64 + rl]);
        st_cluster_f32(dst_remote0 + (p ^ 1) * (D * 4), h);
        if (sub == 0) outg[t * D + row] = h;
        asm volatile("barrier.cluster.arrive.aligned;" ::: "memory");
        asm volatile("barrier.cluster.wait.aligned;" ::: "memory");
        p ^= 1;
    }
}

// ---------------- softmax over scores rows -> g_alpha; also copies H into CH[., D:] ----
__global__ void softmax_kernel() {
    int t = blockIdx.x;
    int tid = threadIdx.x, w = tid >> 5, l = tid & 31;
    __shared__ float red[8];
    float v = g_scores[t * SRC + tid];
    float mx = v;
#pragma unroll
    for (int o = 16; o; o >>= 1) mx = fmaxf(mx, __shfl_xor_sync(0xffffffffu, mx, o));
    if (l == 0) red[w] = mx;
    __syncthreads();
    mx = fmaxf(fmaxf(red[0], red[1]), fmaxf(red[2], red[3]));
    float e = __expf(v - mx);
    float sm = e;
#pragma unroll
    for (int o = 16; o; o >>= 1) sm += __shfl_xor_sync(0xffffffffu, sm, o);
    if (l == 0) red[4 + w] = sm;
    __syncthreads();
    sm = red[4] + red[5] + red[6] + red[7];
    g_alpha[t * SRC + tid] = e / sm;
    // copy H row into CH second half (4 floats/thread)
    float4 hv = *(const float4*)&g_H[t * D + tid * 4];
    *(float4*)&g_CH[t * 2 * D + D + tid * 4] = hv;
}

// ---------------- K5: logits via mma.sync bf16 (B pre-converted) ----------------
#define OFF_BO 0
#define OFF_TGT 512
#define OFF_SEXP 1024
#define OFF_B 2048
#define OFF_A (2048 + 2 * 16384)
#define LOGITS_SMEM (OFF_A + 8 * 16384)

__global__ void __launch_bounds__(256, 1) logits_kernel(const float* __restrict__ bo,
                                                        const int* __restrict__ enums) {
    extern __shared__ char smem[];
    const uint32_t sb = smem_u32(smem);
    const int tid = threadIdx.x;
    const int lane = tid & 31;
    const int wm = (tid >> 5) & 3;
    const int wn = tid >> 7;
    const int vb = blockIdx.x * 128;

    float* bo_s = (float*)(smem + OFF_BO);
    int* tgt_s = (int*)(smem + OFF_TGT);
    float* sexp_s = (float*)(smem + OFF_SEXP);

    for (int i = tid; i < 128; i += 256) {
        int v = vb + i;
        bo_s[i] = (v < VOCAB) ? bo[v] : 0.f;
        tgt_s[i] = enums[i + 1];
        sexp_s[i] = 0.f;
    }

    for (int i = tid * 8; i < TGT_STEPS * D; i += 256 * 8) {
        int t = i >> 9, k = i & 511;
        uint4 v = *(const uint4*)&g_Mbf[i];
        int c = k >> 6, kk = k & 63;
        uint32_t sw = sw128(t * 128 + kk * 2);
        *(uint4*)(smem + OFF_A + c * 16384 + sw) = v;
    }

    const int rowl = tid >> 1, q = tid & 1;
    const bool vok = (vb + rowl) < VOCAB;
    const uint4* wsrc = (const uint4*)&g_Wobf[(size_t)(vb + rowl) * D];
    const uint4 Z = make_uint4(0u, 0u, 0u, 0u);

    uint4 pf[4];
#pragma unroll
    for (int j = 0; j < 4; j++) pf[j] = vok ? wsrc[q * 4 + j] : Z;

    float cacc[2][8][4];
#pragma unroll
    for (int mi = 0; mi < 2; mi++)
#pragma unroll
        for (int nn = 0; nn < 8; nn++)
#pragma unroll
            for (int e = 0; e < 4; e++) cacc[mi][nn][e] = 0.f;

    const int rowA = wm * 32 + (lane & 15);
    const int kselA = (lane >> 4) << 4;
    const int rowB = wn * 64 + (lane & 7) + ((lane & 16) >> 1);
    const int kselB = (lane & 8) << 1;

#pragma unroll 1
    for (int c = 0; c < 8; c++) {
        char* bbuf = smem + OFF_B + (c & 1) * 16384;
#pragma unroll
        for (int j = 0; j < 4; j++) {
            uint32_t sw = sw128(rowl * 128 + q * 64 + j * 16);
            *(uint4*)(bbuf + sw) = pf[j];
        }
        __syncthreads();
        if (c < 7) {
#pragma unroll
            for (int j = 0; j < 4; j++)
                pf[j] = vok ? wsrc[(c + 1) * 8 + q * 4 + j] : Z;
        }
        const uint32_t aBase = sb + OFF_A + c * 16384;
        const uint32_t bBase = sb + OFF_B + (c & 1) * 16384;
#pragma unroll
        for (int kk = 0; kk < 4; kk++) {
            uint32_t a[2][4];
#pragma unroll
            for (int mi = 0; mi < 2; mi++) {
                uint32_t off = (rowA + mi * 16) * 128 + kk * 32 + kselA;
                ldsm4(a[mi][0], a[mi][1], a[mi][2], a[mi][3], aBase + sw128(off));
            }
            uint32_t bf[4][4];
#pragma unroll
            for (int n2 = 0; n2 < 4; n2++) {
                uint32_t off = (rowB + n2 * 16) * 128 + kk * 32 + kselB;
                ldsm4(bf[n2][0], bf[n2][1], bf[n2][2], bf[n2][3], bBase + sw128(off));
            }
#pragma unroll
            for (int mi = 0; mi < 2; mi++)
#pragma unroll
                for (int nn = 0; nn < 8; nn++) {
                    uint32_t b0 = bf[nn >> 1][(nn & 1) * 2];
                    uint32_t b1 = bf[nn >> 1][(nn & 1) * 2 + 1];
                    mma_bf16(cacc[mi][nn], a[mi][0], a[mi][1], a[mi][2], a[mi][3], b0, b1);
                }
        }
    }

#pragma unroll
    for (int mi = 0; mi < 2; mi++) {
        int r0 = wm * 32 + mi * 16 + (lane >> 2);
        int r1 = r0 + 8;
        float s0 = 0.f, s1 = 0.f;
#pragma unroll
        for (int nn = 0; nn < 8; nn++) {
            int col = wn * 64 + nn * 8 + 2 * (lane & 3);
            const float* cc = cacc[mi][nn];
#pragma unroll
            for (int e = 0; e < 2; e++) {
                int v = vb + col + e;
                if (v < VOCAB) {
                    float lg0 = cc[e] + bo_s[col + e];
                    float lg1 = cc[2 + e] + bo_s[col + e];
                    s0 += __expf(lg0);
                    s1 += __expf(lg1);
                    if (v == tgt_s[r0]) g_picked[r0] = lg0;
                    if (v == tgt_s[r1]) g_picked[r1] = lg1;
                }
            }
        }
        s0 += __shfl_xor_sync(0xffffffffu, s0, 1);
        s0 += __shfl_xor_sync(0xffffffffu, s0, 2);
        s1 += __shfl_xor_sync(0xffffffffu, s1, 1);
        s1 += __shfl_xor_sync(0xffffffffu, s1, 2);
        if ((lane & 3) == 0) {
            atomicAdd(&sexp_s[r0], s0);
            atomicAdd(&sexp_s[r1], s1);
        }
    }
    __syncthreads();
    for (int i = tid; i < 128; i += 256) atomicAdd(&g_sumexp[i], sexp_s[i]);
}

// ---------------- K6: final reduction ----------------
__global__ void finalize_kernel(float* __restrict__ out) {
    int tid = threadIdx.x;
    float v = g_picked[tid] - logf(g_sumexp[tid]);
    __shared__ float red[4];
    int w = tid >> 5, l = tid & 31;
#pragma unroll
    for (int o = 16; o; o >>= 1) v += __shfl_xor_sync(0xffffffffu, v, o);
    if (l == 0) red[w] = v;
    __syncthreads();
    if (tid == 0) out[0] = red[0] + red[1] + red[2] + red[3];
}

// ---------------- launch ----------------
extern "C" void kernel_launch(void* const* d_in, const int* in_sizes, int n_in,
                              void* d_out, int out_size) {
    const int* fnums = (const int*)d_in[0];
    const int* enums = (const int*)d_in[1];
    const float* emb_f = (const float*)d_in[2];
    const float* Wih_e = (const float*)d_in[3];
    const float* Whh_e = (const float*)d_in[4];
    const float* b_e = (const float*)d_in[5];
    const float* h0_e = (const float*)d_in[6];
    const float* emb_d = (const float*)d_in[7];
    const float* Wih_d = (const float*)d_in[8];
    const float* Whh_d = (const float*)d_in[9];
    const float* b_d = (const float*)d_in[10];
    const float* h0_d = (const float*)d_in[11];
    const float* Wm = (const float*)d_in[12];
    const float* bm = (const float*)d_in[13];
    const float* Wo = (const float*)d_in[14];
    const float* bo = (const float*)d_in[15];
    float* out = (float*)d_out;

    static int inited = 0;
    static float *p_xpre, *p_epre, *p_CH, *p_H, *p_fencs, *p_alpha, *p_scores;
    static __nv_bfloat16* p_Mbf;
    if (!inited) {
        cudaFuncSetAttribute(logits_kernel, cudaFuncAttributeMaxDynamicSharedMemorySize,
                             LOGITS_SMEM);
        cudaGetSymbolAddress((void**)&p_xpre, g_xpre);
        cudaGetSymbolAddress((void**)&p_epre, g_epre);
        cudaGetSymbolAddress((void**)&p_CH, g_CH);
        cudaGetSymbolAddress((void**)&p_H, g_H);
        cudaGetSymbolAddress((void**)&p_fencs, g_fencs);
        cudaGetSymbolAddress((void**)&p_alpha, g_alpha);
        cudaGetSymbolAddress((void**)&p_scores, g_scores);
        cudaGetSymbolAddress((void**)&p_Mbf, g_Mbf);
        inited = 1;
    }

    // pre-activations: encoder (z=0) + decoder (z=1) concurrently
    gemm_kernel<<<dim3(8, 4, 2), 256>>>(emb_f, fnums, Wih_e, b_e,
                                        emb_d, enums, Wih_d, b_d,
                                        p_xpre, p_epre, nullptr, D, 0, D, 0, 0);
    // recur (y=0,1) + Wo->bf16 conversion (y=2..) overlapped in one launch
    recur_kernel<<<dim3(8, 2 + CONV_YS), 512>>>(Whh_e, Whh_d, h0_e, h0_d, Wo);
    // scores[t,s] = H[t] . fencs[s]  (128x128x512 GEMM, W row-major)
    gemm_kernel<<<dim3(2, 4, 1), 256>>>(p_H, nullptr, p_fencs, nullptr,
                                        p_H, nullptr, p_fencs, nullptr,
                                        p_scores, p_scores, nullptr, D, 0, SRC, 0, 0);
    softmax_kernel<<<128, 128>>>();
    // C = alpha @ fencs  (128x512x128 GEMM, W = fencs K-major, ldw=D), writes CH[:, :D]
    gemm_kernel<<<dim3(8, 4, 1), 256>>>(p_alpha, nullptr, p_fencs, nullptr,
                                        p_alpha, nullptr, p_fencs, nullptr,
                                        p_CH, p_CH, nullptr, SRC, 0, 2 * D, 1, D);
    // M = tanh(CH @ Wm^T + bm) -> bf16 (also zeroes g_sumexp)
    gemm_kernel<<<dim3(8, 4, 1), 256>>>(p_CH, nullptr, Wm, bm,
                                        p_CH, nullptr, Wm, bm,
                                        nullptr, nullptr, p_Mbf, 2 * D, 1, D, 0, 0);
    logits_kernel<<<(VOCAB + 127) / 128, 256, LOGITS_SMEM>>>(bo, enums);
    finalize_kernel<<<1, 128>>>(out);
}

// round 10
// speedup vs baseline: 1.1439x; 1.1122x over previous
#include <cuda_runtime.h>
#include <cuda_bf16.h>
#include <cstdint>

#define D 512
#define SRC 128
#define TGT_STEPS 128
#define VOCAB 50000

typedef unsigned long long u64;

// ---------------- scratch (device globals; no allocation allowed) ----------------
__device__ __align__(16) float g_xpre[SRC * D];
__device__ __align__(16) float g_epre[TGT_STEPS * D];
__device__ __align__(16) float g_fencs[SRC * D];
__device__ __align__(16) float g_H[TGT_STEPS * D];
__device__ __align__(16) float g_alpha[TGT_STEPS * SRC];
__device__ __align__(16) float g_CH[TGT_STEPS * 2 * D];
__device__ __align__(16) __nv_bfloat16 g_Mbf[TGT_STEPS * D];
__device__ __align__(16) __nv_bfloat16 g_Wobf[VOCAB * D];
__device__ float g_sumexp[TGT_STEPS];
__device__ float g_picked[TGT_STEPS];

// ---------------- helpers ----------------
__device__ __forceinline__ u64 pk2(float x, float y) {
    u64 r;
    asm("mov.b64 %0, {%1, %2};" : "=l"(r) : "f"(x), "f"(y));
    return r;
}
__device__ __forceinline__ float2 upk2(u64 v) {
    float2 r;
    asm("mov.b64 {%0, %1}, %2;" : "=f"(r.x), "=f"(r.y) : "l"(v));
    return r;
}
__device__ __forceinline__ void fma2(u64& d, u64 a, u64 b) {
    asm volatile("fma.rn.f32x2 %0, %1, %2, %0;" : "+l"(d) : "l"(a), "l"(b));
}
__device__ __forceinline__ uint32_t smem_u32(const void* p) {
    uint32_t a;
    asm("{ .reg .u64 t; cvta.to.shared.u64 t, %1; cvt.u32.u64 %0, t; }" : "=r"(a) : "l"(p));
    return a;
}
__device__ __forceinline__ uint32_t mapa_u32(uint32_t saddr, uint32_t rank) {
    uint32_t r;
    asm volatile("mapa.shared::cluster.u32 %0, %1, %2;" : "=r"(r) : "r"(saddr), "r"(rank));
    return r;
}
__device__ __forceinline__ void st_cluster_f32(uint32_t raddr, float v) {
    asm volatile("st.shared::cluster.f32 [%0], %1;" :: "r"(raddr), "f"(v) : "memory");
}
__device__ __forceinline__ void ldsm4(uint32_t& r0, uint32_t& r1, uint32_t& r2, uint32_t& r3,
                                      uint32_t addr) {
    asm volatile("ldmatrix.sync.aligned.m8n8.x4.shared.b16 {%0,%1,%2,%3}, [%4];"
                 : "=r"(r0), "=r"(r1), "=r"(r2), "=r"(r3) : "r"(addr));
}
__device__ __forceinline__ void mma_bf16(float* c, uint32_t a0, uint32_t a1, uint32_t a2,
                                         uint32_t a3, uint32_t b0, uint32_t b1) {
    asm volatile(
        "mma.sync.aligned.m16n8k16.row.col.f32.bf16.bf16.f32 "
        "{%0,%1,%2,%3}, {%4,%5,%6,%7}, {%8,%9}, {%0,%1,%2,%3};"
        : "+f"(c[0]), "+f"(c[1]), "+f"(c[2]), "+f"(c[3])
        : "r"(a0), "r"(a1), "r"(a2), "r"(a3), "r"(b0), "r"(b1));
}
__device__ __forceinline__ uint32_t sw128(uint32_t off) { return off ^ ((off >> 3) & 0x70); }
__device__ __forceinline__ float fast_tanh(float x) {
    float e = __expf(2.f * x);
    return __fdividef(e - 1.f, e + 1.f);
}

// ---------------- K1/K4: tiled SGEMM  out[m, n] = act(Xrow(m) . W[n,:] + bias[n]) ----
__global__ void __launch_bounds__(256) gemm_kernel(
    const float* __restrict__ X0, const int* __restrict__ idx0,
    const float* __restrict__ W0, const float* __restrict__ b0,
    const float* __restrict__ X1, const int* __restrict__ idx1,
    const float* __restrict__ W1, const float* __restrict__ b1,
    float* __restrict__ oF0, float* __restrict__ oF1,
    __nv_bfloat16* __restrict__ oB,
    int K, int applyTanh) {
    const int z = blockIdx.z;
    const float* X = z ? X1 : X0;
    const int* idx = z ? idx1 : idx0;
    const float* W = z ? W1 : W0;
    const float* bias = z ? b1 : b0;
    float* outF = z ? oF1 : oF0;

    __shared__ __align__(16) float Xs[64][34];
    __shared__ __align__(16) float Ws[64][68];
    __shared__ int roff[32];

    const int tid = threadIdx.x;
    const int tx = tid & 15, ty = tid >> 4;
    const int mbase = blockIdx.y * 32;
    const int nbase = blockIdx.x * 64;

    // fold init: zero g_sumexp before logits runs (this kernel precedes logits)
    if (oB && blockIdx.x == 0 && blockIdx.y == 0 && z == 0 && tid < TGT_STEPS)
        g_sumexp[tid] = 0.f;

    if (tid < 32) {
        int m = mbase + tid;
        roff[tid] = (idx ? idx[m] : m) * K;
    }
    __syncthreads();

    u64 acc[2][2] = {{0ull, 0ull}, {0ull, 0ull}};

    for (int kt = 0; kt < K; kt += 64) {
#pragma unroll
        for (int j = 0; j < 2; j++) {
            int id = tid * 2 + j;
            int m = id >> 4, kq = id & 15;
            float4 v = *(const float4*)&X[roff[m] + kt + kq * 4];
            Xs[kq * 4 + 0][m] = v.x;
            Xs[kq * 4 + 1][m] = v.y;
            Xs[kq * 4 + 2][m] = v.z;
            Xs[kq * 4 + 3][m] = v.w;
        }
#pragma unroll
        for (int j = 0; j < 4; j++) {
            int id = tid + 256 * j;
            int n = id >> 4, kq = id & 15;
            float4 v = *(const float4*)&W[(size_t)(nbase + n) * K + kt + kq * 4];
            Ws[kq * 4 + 0][n] = v.x;
            Ws[kq * 4 + 1][n] = v.y;
            Ws[kq * 4 + 2][n] = v.z;
            Ws[kq * 4 + 3][n] = v.w;
        }
        __syncthreads();
#pragma unroll
        for (int k = 0; k < 64; k++) {
            float2 a = *(const float2*)&Xs[k][ty * 2];
            float4 b = *(const float4*)&Ws[k][tx * 4];
            u64 bp0 = pk2(b.x, b.y), bp1 = pk2(b.z, b.w);
            u64 a0 = pk2(a.x, a.x), a1 = pk2(a.y, a.y);
            fma2(acc[0][0], a0, bp0);
            fma2(acc[0][1], a0, bp1);
            fma2(acc[1][0], a1, bp0);
            fma2(acc[1][1], a1, bp1);
        }
        __syncthreads();
    }
#pragma unroll
    for (int r = 0; r < 2; r++) {
        int m = mbase + ty * 2 + r;
        float2 v0 = upk2(acc[r][0]), v1 = upk2(acc[r][1]);
        float o[4] = {v0.x, v0.y, v1.x, v1.y};
#pragma unroll
        for (int i = 0; i < 4; i++) {
            int n = nbase + tx * 4 + i;
            float val = o[i] + bias[n];
            if (applyTanh) val = fast_tanh(val);
            if (outF) outF[m * D + n] = val;
            else oB[m * D + n] = __float2bfloat16(val);
        }
    }
}

// ---------------- K2: recurrences (y=0,1: 8-CTA clusters) + Wo->bf16 convert (y>=2) ----
#define CONV_YS 6
__global__ void __cluster_dims__(8, 1, 1) __launch_bounds__(512, 1)
recur_kernel(const float* __restrict__ Whh_e, const float* __restrict__ Whh_d,
             const float* __restrict__ h0_e, const float* __restrict__ h0_d,
             const float* __restrict__ Wo) {
    const int tid = threadIdx.x;

    if (blockIdx.y >= 2) {
        // ---- Wo fp32 -> bf16 converter ----
        const size_t n4 = (size_t)VOCAB * D / 4;
        const size_t gt = (size_t)((blockIdx.y - 2) * 8 + blockIdx.x) * 512 + tid;
        const size_t stride = (size_t)CONV_YS * 8 * 512;
        const float4* src = (const float4*)Wo;
        uint2* dst = (uint2*)g_Wobf;
        for (size_t i = gt; i < n4; i += stride) {
            float4 f = src[i];
            __nv_bfloat162 lo = __float22bfloat162_rn(make_float2(f.x, f.y));
            __nv_bfloat162 hi = __float22bfloat162_rn(make_float2(f.z, f.w));
            uint2 u;
            u.x = *(uint32_t*)&lo;
            u.y = *(uint32_t*)&hi;
            dst[i] = u;
        }
        return;
    }

    const int ph = blockIdx.y;
    const float* W = ph ? Whh_d : Whh_e;
    const float* h0 = ph ? h0_d : h0_e;
    const float* pre = ph ? g_epre : g_xpre;
    float* outg = ph ? g_H : g_fencs;

    __shared__ __align__(16) float hbuf[2][D];
    __shared__ float pre_s[128 * 64];

    const int rl = tid >> 3;
    const int sub = tid & 7;
    const uint32_t rank = blockIdx.x;
    const int row = rank * 64 + rl;

    u64 wv2[32];
#pragma unroll
    for (int j = 0; j < 16; j++) {
        ulonglong2 t = *(const ulonglong2*)&W[row * D + j * 32 + sub * 4];
        wv2[2 * j] = t.x;
        wv2[2 * j + 1] = t.y;
    }

    for (int i = tid; i < 128 * 64; i += 512) {
        int t = i >> 6, r = i & 63;
        pre_s[i] = pre[t * D + rank * 64 + r];
    }
    if (tid < D) hbuf[0][tid] = h0[tid];
    __syncthreads();

    const uint32_t dst_remote0 = mapa_u32(smem_u32(&hbuf[0][row]), (uint32_t)sub);

    int p = 0;
    for (int t = 0; t < 128; t++) {
        const float* hp = hbuf[p];
        u64 A0 = 0ull, A1 = 0ull;
#pragma unroll
        for (int j = 0; j < 16; j++) {
            ulonglong2 hv = *(const ulonglong2*)&hp[j * 32 + sub * 4];
            fma2(A0, wv2[2 * j], hv.x);
            fma2(A1, wv2[2 * j + 1], hv.y);
        }
        float2 f0 = upk2(A0), f1 = upk2(A1);
        float acc = (f0.x + f0.y) + (f1.x + f1.y);
#pragma unroll
        for (int o = 4; o; o >>= 1) acc += __shfl_xor_sync(0xffffffffu, acc, o);
        float h = fast_tanh(acc + pre_s[t * 64 + rl]);
        st_cluster_f32(dst_remote0 + (p ^ 1) * (D * 4), h);
        if (sub == 0) outg[t * D + row] = h;
        asm volatile("barrier.cluster.arrive.aligned;" ::: "memory");
        asm volatile("barrier.cluster.wait.aligned;" ::: "memory");
        p ^= 1;
    }
}

// ---------------- K3a: scores + softmax -> g_alpha ----------------
__global__ void attn_scores_kernel() {
    int t = blockIdx.x;
    int tid = threadIdx.x, w = tid >> 5, l = tid & 31;
    __shared__ __align__(16) float hs[D];
    __shared__ float sc[SRC];
    __shared__ float red[16];
    for (int i = tid; i < D; i += 256) hs[i] = g_H[t * D + i];
    __syncthreads();
#pragma unroll 1
    for (int si = 0; si < 16; si++) {
        int s2 = w * 16 + si;
        float acc = 0.f;
#pragma unroll
        for (int j = 0; j < 4; j++) {
            float4 fv = *(const float4*)&g_fencs[s2 * D + l * 4 + j * 128];
            float4 hv = *(const float4*)&hs[l * 4 + j * 128];
            acc += fv.x * hv.x + fv.y * hv.y + fv.z * hv.z + fv.w * hv.w;
        }
#pragma unroll
        for (int o = 16; o; o >>= 1) acc += __shfl_xor_sync(0xffffffffu, acc, o);
        if (l == 0) sc[s2] = acc;
    }
    __syncthreads();
    float v = (tid < SRC) ? sc[tid] : -1e30f;
    float mx = v;
#pragma unroll
    for (int o = 16; o; o >>= 1) mx = fmaxf(mx, __shfl_xor_sync(0xffffffffu, mx, o));
    if (l == 0) red[w] = mx;
    __syncthreads();
    mx = fmaxf(fmaxf(red[0], red[1]), fmaxf(red[2], red[3]));
    float e = (tid < SRC) ? __expf(v - mx) : 0.f;
    float sm = e;
#pragma unroll
    for (int o = 16; o; o >>= 1) sm += __shfl_xor_sync(0xffffffffu, sm, o);
    if (l == 0) red[8 + w] = sm;
    __syncthreads();
    sm = red[8] + red[9] + red[10] + red[11];
    if (tid < SRC) g_alpha[t * SRC + tid] = e / sm;
}

// ---------------- K3b: context + assemble CH (one CTA per t, float4 per thread) ----
__global__ void __launch_bounds__(128) attn_ctx_kernel() {
    int t = blockIdx.x;
    int tid = threadIdx.x;
    __shared__ float al[SRC];
    al[tid] = g_alpha[t * SRC + tid];
    __syncthreads();
    const float4* f4 = (const float4*)g_fencs;
    float4 c = make_float4(0.f, 0.f, 0.f, 0.f);
#pragma unroll 8
    for (int s = 0; s < SRC; s++) {
        float a = al[s];
        float4 fv = f4[s * (D / 4) + tid];
        c.x = fmaf(a, fv.x, c.x);
        c.y = fmaf(a, fv.y, c.y);
        c.z = fmaf(a, fv.z, c.z);
        c.w = fmaf(a, fv.w, c.w);
    }
    *(float4*)&g_CH[t * 2 * D + tid * 4] = c;
    float4 hv = *(const float4*)&g_H[t * D + tid * 4];
    *(float4*)&g_CH[t * 2 * D + D + tid * 4] = hv;
}

// ---------------- K5: logits via mma.sync bf16 (B pre-converted) ----------------
#define OFF_BO 0
#define OFF_TGT 512
#define OFF_SEXP 1024
#define OFF_B 2048
#define OFF_A (2048 + 2 * 16384)
#define LOGITS_SMEM (OFF_A + 8 * 16384)

__global__ void __launch_bounds__(256, 1) logits_kernel(const float* __restrict__ bo,
                                                        const int* __restrict__ enums) {
    extern __shared__ char smem[];
    const uint32_t sb = smem_u32(smem);
    const int tid = threadIdx.x;
    const int lane = tid & 31;
    const int wm = (tid >> 5) & 3;
    const int wn = tid >> 7;
    const int vb = blockIdx.x * 128;

    float* bo_s = (float*)(smem + OFF_BO);
    int* tgt_s = (int*)(smem + OFF_TGT);
    float* sexp_s = (float*)(smem + OFF_SEXP);

    for (int i = tid; i < 128; i += 256) {
        int v = vb + i;
        bo_s[i] = (v < VOCAB) ? bo[v] : 0.f;
        tgt_s[i] = enums[i + 1];
        sexp_s[i] = 0.f;
    }

    for (int i = tid * 8; i < TGT_STEPS * D; i += 256 * 8) {
        int t = i >> 9, k = i & 511;
        uint4 v = *(const uint4*)&g_Mbf[i];
        int c = k >> 6, kk = k & 63;
        uint32_t sw = sw128(t * 128 + kk * 2);
        *(uint4*)(smem + OFF_A + c * 16384 + sw) = v;
    }

    const int rowl = tid >> 1, q = tid & 1;
    const bool vok = (vb + rowl) < VOCAB;
    const uint4* wsrc = (const uint4*)&g_Wobf[(size_t)(vb + rowl) * D];
    const uint4 Z = make_uint4(0u, 0u, 0u, 0u);

    uint4 pf[4];
#pragma unroll
    for (int j = 0; j < 4; j++) pf[j] = vok ? wsrc[q * 4 + j] : Z;

    float cacc[2][8][4];
#pragma unroll
    for (int mi = 0; mi < 2; mi++)
#pragma unroll
        for (int nn = 0; nn < 8; nn++)
#pragma unroll
            for (int e = 0; e < 4; e++) cacc[mi][nn][e] = 0.f;

    const int rowA = wm * 32 + (lane & 15);
    const int kselA = (lane >> 4) << 4;
    const int rowB = wn * 64 + (lane & 7) + ((lane & 16) >> 1);
    const int kselB = (lane & 8) << 1;

#pragma unroll 1
    for (int c = 0; c < 8; c++) {
        char* bbuf = smem + OFF_B + (c & 1) * 16384;
#pragma unroll
        for (int j = 0; j < 4; j++) {
            uint32_t sw = sw128(rowl * 128 + q * 64 + j * 16);
            *(uint4*)(bbuf + sw) = pf[j];
        }
        __syncthreads();
        if (c < 7) {
#pragma unroll
            for (int j = 0; j < 4; j++)
                pf[j] = vok ? wsrc[(c + 1) * 8 + q * 4 + j] : Z;
        }
        const uint32_t aBase = sb + OFF_A + c * 16384;
        const uint32_t bBase = sb + OFF_B + (c & 1) * 16384;
#pragma unroll
        for (int kk = 0; kk < 4; kk++) {
            uint32_t a[2][4];
#pragma unroll
            for (int mi = 0; mi < 2; mi++) {
                uint32_t off = (rowA + mi * 16) * 128 + kk * 32 + kselA;
                ldsm4(a[mi][0], a[mi][1], a[mi][2], a[mi][3], aBase + sw128(off));
            }
            uint32_t bf[4][4];
#pragma unroll
            for (int n2 = 0; n2 < 4; n2++) {
                uint32_t off = (rowB + n2 * 16) * 128 + kk * 32 + kselB;
                ldsm4(bf[n2][0], bf[n2][1], bf[n2][2], bf[n2][3], bBase + sw128(off));
            }
#pragma unroll
            for (int mi = 0; mi < 2; mi++)
#pragma unroll
                for (int nn = 0; nn < 8; nn++) {
                    uint32_t b0 = bf[nn >> 1][(nn & 1) * 2];
                    uint32_t b1 = bf[nn >> 1][(nn & 1) * 2 + 1];
                    mma_bf16(cacc[mi][nn], a[mi][0], a[mi][1], a[mi][2], a[mi][3], b0, b1);
                }
        }
    }

#pragma unroll
    for (int mi = 0; mi < 2; mi++) {
        int r0 = wm * 32 + mi * 16 + (lane >> 2);
        int r1 = r0 + 8;
        float s0 = 0.f, s1 = 0.f;
#pragma unroll
        for (int nn = 0; nn < 8; nn++) {
            int col = wn * 64 + nn * 8 + 2 * (lane & 3);
            const float* cc = cacc[mi][nn];
#pragma unroll
            for (int e = 0; e < 2; e++) {
                int v = vb + col + e;
                if (v < VOCAB) {
                    float lg0 = cc[e] + bo_s[col + e];
                    float lg1 = cc[2 + e] + bo_s[col + e];
                    s0 += __expf(lg0);
                    s1 += __expf(lg1);
                    if (v == tgt_s[r0]) g_picked[r0] = lg0;
                    if (v == tgt_s[r1]) g_picked[r1] = lg1;
                }
            }
        }
        s0 += __shfl_xor_sync(0xffffffffu, s0, 1);
        s0 += __shfl_xor_sync(0xffffffffu, s0, 2);
        s1 += __shfl_xor_sync(0xffffffffu, s1, 1);
        s1 += __shfl_xor_sync(0xffffffffu, s1, 2);
        if ((lane & 3) == 0) {
            atomicAdd(&sexp_s[r0], s0);
            atomicAdd(&sexp_s[r1], s1);
        }
    }
    __syncthreads();
    for (int i = tid; i < 128; i += 256) atomicAdd(&g_sumexp[i], sexp_s[i]);
}

// ---------------- K6: final reduction ----------------
__global__ void finalize_kernel(float* __restrict__ out) {
    int tid = threadIdx.x;
    float v = g_picked[tid] - logf(g_sumexp[tid]);
    __shared__ float red[4];
    int w = tid >> 5, l = tid & 31;
#pragma unroll
    for (int o = 16; o; o >>= 1) v += __shfl_xor_sync(0xffffffffu, v, o);
    if (l == 0) red[w] = v;
    __syncthreads();
    if (tid == 0) out[0] = red[0] + red[1] + red[2] + red[3];
}

// ---------------- launch ----------------
extern "C" void kernel_launch(void* const* d_in, const int* in_sizes, int n_in,
                              void* d_out, int out_size) {
    const int* fnums = (const int*)d_in[0];
    const int* enums = (const int*)d_in[1];
    const float* emb_f = (const float*)d_in[2];
    const float* Wih_e = (const float*)d_in[3];
    const float* Whh_e = (const float*)d_in[4];
    const float* b_e = (const float*)d_in[5];
    const float* h0_e = (const float*)d_in[6];
    const float* emb_d = (const float*)d_in[7];
    const float* Wih_d = (const float*)d_in[8];
    const float* Whh_d = (const float*)d_in[9];
    const float* b_d = (const float*)d_in[10];
    const float* h0_d = (const float*)d_in[11];
    const float* Wm = (const float*)d_in[12];
    const float* bm = (const float*)d_in[13];
    const float* Wo = (const float*)d_in[14];
    const float* bo = (const float*)d_in[15];
    float* out = (float*)d_out;

    static int inited = 0;
    static float *p_xpre, *p_epre, *p_CH;
    static __nv_bfloat16* p_Mbf;
    if (!inited) {
        cudaFuncSetAttribute(logits_kernel, cudaFuncAttributeMaxDynamicSharedMemorySize,
                             LOGITS_SMEM);
        cudaGetSymbolAddress((void**)&p_xpre, g_xpre);
        cudaGetSymbolAddress((void**)&p_epre, g_epre);
        cudaGetSymbolAddress((void**)&p_CH, g_CH);
        cudaGetSymbolAddress((void**)&p_Mbf, g_Mbf);
        inited = 1;
    }

    // pre-activations: encoder (z=0) + decoder (z=1) concurrently
    gemm_kernel<<<dim3(8, 4, 2), 256>>>(emb_f, fnums, Wih_e, b_e,
                                        emb_d, enums, Wih_d, b_d,
                                        p_xpre, p_epre, nullptr, D, 0);
    // recur (y=0,1) + Wo->bf16 conversion (y=2..) overlapped in one launch
    recur_kernel<<<dim3(8, 2 + CONV_YS), 512>>>(Whh_e, Whh_d, h0_e, h0_d, Wo);
    attn_scores_kernel<<<128, 256>>>();
    attn_ctx_kernel<<<128, 128>>>();
    // M = tanh(CH @ Wm^T + bm) -> bf16 (also zeroes g_sumexp)
    gemm_kernel<<<dim3(8, 4, 1), 256>>>(p_CH, nullptr, Wm, bm,
                                        p_CH, nullptr, Wm, bm,
                                        nullptr, nullptr, p_Mbf, 2 * D, 1);
    logits_kernel<<<(VOCAB + 127) / 128, 256, LOGITS_SMEM>>>(bo, enums);
    finalize_kernel<<<1, 128>>>(out);
}

// round 11
// speedup vs baseline: 1.4229x; 1.2439x over previous
#include <cuda_runtime.h>
#include <cuda_bf16.h>
#include <cstdint>

#define D 512
#define SRC 128
#define TGT_STEPS 128
#define VOCAB 50000

typedef unsigned long long u64;

// ---------------- scratch (device globals; no allocation allowed) ----------------
__device__ __align__(16) float g_xpre[SRC * D];
__device__ __align__(16) float g_epre[TGT_STEPS * D];
__device__ __align__(16) float g_fencs[SRC * D];
__device__ __align__(16) float g_H[TGT_STEPS * D];
__device__ __align__(16) float g_CH[TGT_STEPS * 2 * D];
__device__ __align__(16) __nv_bfloat16 g_Mbf[TGT_STEPS * D];
__device__ __align__(16) __nv_bfloat16 g_Wobf[VOCAB * D];
__device__ float g_sumexp[TGT_STEPS];
__device__ float g_picked[TGT_STEPS];

// ---------------- helpers ----------------
__device__ __forceinline__ u64 pk2(float x, float y) {
    u64 r;
    asm("mov.b64 %0, {%1, %2};" : "=l"(r) : "f"(x), "f"(y));
    return r;
}
__device__ __forceinline__ float2 upk2(u64 v) {
    float2 r;
    asm("mov.b64 {%0, %1}, %2;" : "=f"(r.x), "=f"(r.y) : "l"(v));
    return r;
}
__device__ __forceinline__ void fma2(u64& d, u64 a, u64 b) {
    asm volatile("fma.rn.f32x2 %0, %1, %2, %0;" : "+l"(d) : "l"(a), "l"(b));
}
__device__ __forceinline__ uint32_t smem_u32(const void* p) {
    uint32_t a;
    asm("{ .reg .u64 t; cvta.to.shared.u64 t, %1; cvt.u32.u64 %0, t; }" : "=r"(a) : "l"(p));
    return a;
}
__device__ __forceinline__ uint32_t mapa_u32(uint32_t saddr, uint32_t rank) {
    uint32_t r;
    asm volatile("mapa.shared::cluster.u32 %0, %1, %2;" : "=r"(r) : "r"(saddr), "r"(rank));
    return r;
}
__device__ __forceinline__ void st_async_f32(uint32_t raddr, uint32_t rmbar, float v) {
    asm volatile(
        "st.async.shared::cluster.mbarrier::complete_tx::bytes.b32 [%0], %1, [%2];"
        :: "r"(raddr), "r"(__float_as_uint(v)), "r"(rmbar) : "memory");
}
__device__ __forceinline__ void mbar_init(uint32_t addr, uint32_t cnt) {
    asm volatile("mbarrier.init.shared.b64 [%0], %1;" :: "r"(addr), "r"(cnt) : "memory");
}
__device__ __forceinline__ void mbar_expect_tx(uint32_t addr, uint32_t bytes) {
    asm volatile("mbarrier.arrive.expect_tx.shared.b64 _, [%0], %1;"
                 :: "r"(addr), "r"(bytes) : "memory");
}
__device__ __forceinline__ void mbar_wait(uint32_t addr, int parity) {
    asm volatile(
        "{\n\t.reg .pred P;\n\t"
        "W_%=:\n\t"
        "mbarrier.try_wait.parity.acquire.cta.shared::cta.b64 P, [%0], %1;\n\t"
        "@!P bra W_%=;\n\t}"
        :: "r"(addr), "r"(parity) : "memory");
}
__device__ __forceinline__ void ldsm4(uint32_t& r0, uint32_t& r1, uint32_t& r2, uint32_t& r3,
                                      uint32_t addr) {
    asm volatile("ldmatrix.sync.aligned.m8n8.x4.shared.b16 {%0,%1,%2,%3}, [%4];"
                 : "=r"(r0), "=r"(r1), "=r"(r2), "=r"(r3) : "r"(addr));
}
__device__ __forceinline__ void mma_bf16(float* c, uint32_t a0, uint32_t a1, uint32_t a2,
                                         uint32_t a3, uint32_t b0, uint32_t b1) {
    asm volatile(
        "mma.sync.aligned.m16n8k16.row.col.f32.bf16.bf16.f32 "
        "{%0,%1,%2,%3}, {%4,%5,%6,%7}, {%8,%9}, {%0,%1,%2,%3};"
        : "+f"(c[0]), "+f"(c[1]), "+f"(c[2]), "+f"(c[3])
        : "r"(a0), "r"(a1), "r"(a2), "r"(a3), "r"(b0), "r"(b1));
}
__device__ __forceinline__ uint32_t sw128(uint32_t off) { return off ^ ((off >> 3) & 0x70); }
__device__ __forceinline__ float fast_tanh(float x) {
    float e = __expf(2.f * x);
    return __fdividef(e - 1.f, e + 1.f);
}

// ---------------- K1/K4: tiled SGEMM  out[m, n] = act(Xrow(m) . W[n,:] + bias[n]) ----
__global__ void __launch_bounds__(256) gemm_kernel(
    const float* __restrict__ X0, const int* __restrict__ idx0,
    const float* __restrict__ W0, const float* __restrict__ b0,
    const float* __restrict__ X1, const int* __restrict__ idx1,
    const float* __restrict__ W1, const float* __restrict__ b1,
    float* __restrict__ oF0, float* __restrict__ oF1,
    __nv_bfloat16* __restrict__ oB,
    int K, int applyTanh) {
    const int z = blockIdx.z;
    const float* X = z ? X1 : X0;
    const int* idx = z ? idx1 : idx0;
    const float* W = z ? W1 : W0;
    const float* bias = z ? b1 : b0;
    float* outF = z ? oF1 : oF0;

    __shared__ __align__(16) float Xs[64][34];
    __shared__ __align__(16) float Ws[64][68];
    __shared__ int roff[32];

    const int tid = threadIdx.x;
    const int tx = tid & 15, ty = tid >> 4;
    const int mbase = blockIdx.y * 32;
    const int nbase = blockIdx.x * 64;

    // fold init: zero g_sumexp before logits runs (this kernel precedes logits)
    if (oB && blockIdx.x == 0 && blockIdx.y == 0 && z == 0 && tid < TGT_STEPS)
        g_sumexp[tid] = 0.f;

    if (tid < 32) {
        int m = mbase + tid;
        roff[tid] = (idx ? idx[m] : m) * K;
    }
    __syncthreads();

    u64 acc[2][2] = {{0ull, 0ull}, {0ull, 0ull}};

    for (int kt = 0; kt < K; kt += 64) {
#pragma unroll
        for (int j = 0; j < 2; j++) {
            int id = tid * 2 + j;
            int m = id >> 4, kq = id & 15;
            float4 v = *(const float4*)&X[roff[m] + kt + kq * 4];
            Xs[kq * 4 + 0][m] = v.x;
            Xs[kq * 4 + 1][m] = v.y;
            Xs[kq * 4 + 2][m] = v.z;
            Xs[kq * 4 + 3][m] = v.w;
        }
#pragma unroll
        for (int j = 0; j < 4; j++) {
            int id = tid + 256 * j;
            int n = id >> 4, kq = id & 15;
            float4 v = *(const float4*)&W[(size_t)(nbase + n) * K + kt + kq * 4];
            Ws[kq * 4 + 0][n] = v.x;
            Ws[kq * 4 + 1][n] = v.y;
            Ws[kq * 4 + 2][n] = v.z;
            Ws[kq * 4 + 3][n] = v.w;
        }
        __syncthreads();
#pragma unroll
        for (int k = 0; k < 64; k++) {
            float2 a = *(const float2*)&Xs[k][ty * 2];
            float4 b = *(const float4*)&Ws[k][tx * 4];
            u64 bp0 = pk2(b.x, b.y), bp1 = pk2(b.z, b.w);
            u64 a0 = pk2(a.x, a.x), a1 = pk2(a.y, a.y);
            fma2(acc[0][0], a0, bp0);
            fma2(acc[0][1], a0, bp1);
            fma2(acc[1][0], a1, bp0);
            fma2(acc[1][1], a1, bp1);
        }
        __syncthreads();
    }
#pragma unroll
    for (int r = 0; r < 2; r++) {
        int m = mbase + ty * 2 + r;
        float2 v0 = upk2(acc[r][0]), v1 = upk2(acc[r][1]);
        float o[4] = {v0.x, v0.y, v1.x, v1.y};
#pragma unroll
        for (int i = 0; i < 4; i++) {
            int n = nbase + tx * 4 + i;
            float val = o[i] + bias[n];
            if (applyTanh) val = fast_tanh(val);
            if (outF) outF[m * D + n] = val;
            else oB[m * D + n] = __float2bfloat16(val);
        }
    }
}

// ---------------- K2: recurrences (y=0,1: 8-CTA clusters, mbarrier pipeline)
//                    + Wo->bf16 convert (y>=2) ----------------
// Triple-buffered h; each of 512 threads st.async's 1 value to CTA 'sub'.
// Last step issues no stores/expects (avoids in-flight remote ops at exit).
#define CONV_YS 6
__global__ void __cluster_dims__(8, 1, 1) __launch_bounds__(512, 1)
recur_kernel(const float* __restrict__ Whh_e, const float* __restrict__ Whh_d,
             const float* __restrict__ h0_e, const float* __restrict__ h0_d,
             const float* __restrict__ Wo) {
    const int tid = threadIdx.x;

    if (blockIdx.y >= 2) {
        // ---- Wo fp32 -> bf16 converter ----
        const size_t n4 = (size_t)VOCAB * D / 4;
        const size_t gt = (size_t)((blockIdx.y - 2) * 8 + blockIdx.x) * 512 + tid;
        const size_t stride = (size_t)CONV_YS * 8 * 512;
        const float4* src = (const float4*)Wo;
        uint2* dst = (uint2*)g_Wobf;
        for (size_t i = gt; i < n4; i += stride) {
            float4 f = src[i];
            __nv_bfloat162 lo = __float22bfloat162_rn(make_float2(f.x, f.y));
            __nv_bfloat162 hi = __float22bfloat162_rn(make_float2(f.z, f.w));
            uint2 u;
            u.x = *(uint32_t*)&lo;
            u.y = *(uint32_t*)&hi;
            dst[i] = u;
        }
        return;
    }

    const int ph = blockIdx.y;
    const float* W = ph ? Whh_d : Whh_e;
    const float* h0 = ph ? h0_d : h0_e;
    const float* pre = ph ? g_epre : g_xpre;
    float* outg = ph ? g_H : g_fencs;

    __shared__ __align__(16) float hbuf[3][D];
    __shared__ __align__(8) u64 mbar[3];
    __shared__ float pre_s[128 * 64];

    const int rl = tid >> 3;
    const int sub = tid & 7;
    const uint32_t rank = blockIdx.x;
    const int row = rank * 64 + rl;

    u64 wv2[32];
#pragma unroll
    for (int j = 0; j < 16; j++) {
        ulonglong2 t = *(const ulonglong2*)&W[row * D + j * 32 + sub * 4];
        wv2[2 * j] = t.x;
        wv2[2 * j + 1] = t.y;
    }

    for (int i = tid; i < 128 * 64; i += 512) {
        int t = i >> 6, r = i & 63;
        pre_s[i] = pre[t * D + rank * 64 + r];
    }
    hbuf[0][tid] = h0[tid];
    if (tid < 3) mbar_init(smem_u32(&mbar[tid]), 1);
    __syncthreads();
    // all CTAs' hbuf[0] + mbarriers must be ready before any remote store
    asm volatile("barrier.cluster.arrive.aligned;" ::: "memory");
    asm volatile("barrier.cluster.wait.aligned;" ::: "memory");

    const uint32_t mb_local = smem_u32(&mbar[0]);
    const uint32_t dst_remote0 = mapa_u32(smem_u32(&hbuf[0][row]), (uint32_t)sub);
    const uint32_t mb_remote0 = mapa_u32(mb_local, (uint32_t)sub);

#pragma unroll 1
    for (int t = 0; t < 128; t++) {
        const int b = t % 3;
        const int bn = (t + 1) % 3;
        if (tid == 0 && t < 127) mbar_expect_tx(mb_local + bn * 8, (uint32_t)(D * 4));
        if (t > 0) mbar_wait(mb_local + b * 8, ((t - 1) / 3) & 1);

        const float* hp = hbuf[b];
        u64 A0 = 0ull, A1 = 0ull;
#pragma unroll
        for (int j = 0; j < 16; j++) {
            ulonglong2 hv = *(const ulonglong2*)&hp[j * 32 + sub * 4];
            fma2(A0, wv2[2 * j], hv.x);
            fma2(A1, wv2[2 * j + 1], hv.y);
        }
        float2 f0 = upk2(A0), f1 = upk2(A1);
        float acc = (f0.x + f0.y) + (f1.x + f1.y);
#pragma unroll
        for (int o = 4; o; o >>= 1) acc += __shfl_xor_sync(0xffffffffu, acc, o);
        float h = fast_tanh(acc + pre_s[t * 64 + rl]);
        if (t < 127) st_async_f32(dst_remote0 + bn * (D * 4), mb_remote0 + bn * 8, h);
        if (sub == 0) outg[t * D + row] = h;
    }
    // no CTA may exit while peers might still target its SMEM
    asm volatile("barrier.cluster.arrive.aligned;" ::: "memory");
    asm volatile("barrier.cluster.wait.aligned;" ::: "memory");
}

// ---------------- K3: fused attention per t: scores + softmax + context + CH ----
__global__ void __launch_bounds__(256) attn_kernel() {
    int t = blockIdx.x;
    int tid = threadIdx.x, w = tid >> 5, l = tid & 31;
    __shared__ __align__(16) float hs[D];
    __shared__ float al[SRC];
    __shared__ float red[16];
    __shared__ __align__(16) float cpart[D];

    *(float2*)&hs[tid * 2] = *(const float2*)&g_H[t * D + tid * 2];
    __syncthreads();

    // scores: warp w computes 16 scores
#pragma unroll 1
    for (int si = 0; si < 16; si++) {
        int s2 = w * 16 + si;
        float acc = 0.f;
#pragma unroll
        for (int j = 0; j < 4; j++) {
            float4 fv = *(const float4*)&g_fencs[s2 * D + l * 4 + j * 128];
            float4 hv = *(const float4*)&hs[l * 4 + j * 128];
            acc += fv.x * hv.x + fv.y * hv.y + fv.z * hv.z + fv.w * hv.w;
        }
#pragma unroll
        for (int o = 16; o; o >>= 1) acc += __shfl_xor_sync(0xffffffffu, acc, o);
        if (l == 0) al[s2] = acc;
    }
    __syncthreads();

    // softmax over 128 scores
    float v = (tid < SRC) ? al[tid] : -1e30f;
    float mx = v;
#pragma unroll
    for (int o = 16; o; o >>= 1) mx = fmaxf(mx, __shfl_xor_sync(0xffffffffu, mx, o));
    if (l == 0) red[w] = mx;
    __syncthreads();
    mx = fmaxf(fmaxf(red[0], red[1]), fmaxf(red[2], red[3]));
    float e = (tid < SRC) ? __expf(v - mx) : 0.f;
    float sm = e;
#pragma unroll
    for (int o = 16; o; o >>= 1) sm += __shfl_xor_sync(0xffffffffu, sm, o);
    if (l == 0) red[8 + w] = sm;
    __syncthreads();
    sm = red[8] + red[9] + red[10] + red[11];
    if (tid < SRC) al[tid] = e / sm;
    __syncthreads();

    // context: thread (d4 = tid&127, shalf = tid>>7) sums 64 s values (fencs L1-hot)
    const int d4 = tid & 127, shalf = tid >> 7;
    const float4* f4 = (const float4*)g_fencs;
    float4 c = make_float4(0.f, 0.f, 0.f, 0.f);
    int s0 = shalf * 64;
#pragma unroll 8
    for (int s = s0; s < s0 + 64; s++) {
        float a = al[s];
        float4 fv = f4[s * (D / 4) + d4];
        c.x = fmaf(a, fv.x, c.x);
        c.y = fmaf(a, fv.y, c.y);
        c.z = fmaf(a, fv.z, c.z);
        c.w = fmaf(a, fv.w, c.w);
    }
    if (shalf == 1) *(float4*)&cpart[d4 * 4] = c;
    __syncthreads();
    if (shalf == 0) {
        float4 p = *(const float4*)&cpart[d4 * 4];
        c.x += p.x; c.y += p.y; c.z += p.z; c.w += p.w;
        *(float4*)&g_CH[t * 2 * D + d4 * 4] = c;
    }
    // H half of CH
    *(float2*)&g_CH[t * 2 * D + D + tid * 2] = *(const float2*)&hs[tid * 2];
}

// ---------------- K5: logits via mma.sync bf16 (B pre-converted) ----------------
#define OFF_BO 0
#define OFF_TGT 512
#define OFF_SEXP 1024
#define OFF_B 2048
#define OFF_A (2048 + 2 * 16384)
#define LOGITS_SMEM (OFF_A + 8 * 16384)

__global__ void __launch_bounds__(256, 1) logits_kernel(const float* __restrict__ bo,
                                                        const int* __restrict__ enums) {
    extern __shared__ char smem[];
    const uint32_t sb = smem_u32(smem);
    const int tid = threadIdx.x;
    const int lane = tid & 31;
    const int wm = (tid >> 5) & 3;
    const int wn = tid >> 7;
    const int vb = blockIdx.x * 128;

    float* bo_s = (float*)(smem + OFF_BO);
    int* tgt_s = (int*)(smem + OFF_TGT);
    float* sexp_s = (float*)(smem + OFF_SEXP);

    for (int i = tid; i < 128; i += 256) {
        int v = vb + i;
        bo_s[i] = (v < VOCAB) ? bo[v] : 0.f;
        tgt_s[i] = enums[i + 1];
        sexp_s[i] = 0.f;
    }

    for (int i = tid * 8; i < TGT_STEPS * D; i += 256 * 8) {
        int t = i >> 9, k = i & 511;
        uint4 v = *(const uint4*)&g_Mbf[i];
        int c = k >> 6, kk = k & 63;
        uint32_t sw = sw128(t * 128 + kk * 2);
        *(uint4*)(smem + OFF_A + c * 16384 + sw) = v;
    }

    const int rowl = tid >> 1, q = tid & 1;
    const bool vok = (vb + rowl) < VOCAB;
    const uint4* wsrc = (const uint4*)&g_Wobf[(size_t)(vb + rowl) * D];
    const uint4 Z = make_uint4(0u, 0u, 0u, 0u);

    uint4 pf[4];
#pragma unroll
    for (int j = 0; j < 4; j++) pf[j] = vok ? wsrc[q * 4 + j] : Z;

    float cacc[2][8][4];
#pragma unroll
    for (int mi = 0; mi < 2; mi++)
#pragma unroll
        for (int nn = 0; nn < 8; nn++)
#pragma unroll
            for (int e = 0; e < 4; e++) cacc[mi][nn][e] = 0.f;

    const int rowA = wm * 32 + (lane & 15);
    const int kselA = (lane >> 4) << 4;
    const int rowB = wn * 64 + (lane & 7) + ((lane & 16) >> 1);
    const int kselB = (lane & 8) << 1;

#pragma unroll 1
    for (int c = 0; c < 8; c++) {
        char* bbuf = smem + OFF_B + (c & 1) * 16384;
#pragma unroll
        for (int j = 0; j < 4; j++) {
            uint32_t sw = sw128(rowl * 128 + q * 64 + j * 16);
            *(uint4*)(bbuf + sw) = pf[j];
        }
        __syncthreads();
        if (c < 7) {
#pragma unroll
            for (int j = 0; j < 4; j++)
                pf[j] = vok ? wsrc[(c + 1) * 8 + q * 4 + j] : Z;
        }
        const uint32_t aBase = sb + OFF_A + c * 16384;
        const uint32_t bBase = sb + OFF_B + (c & 1) * 16384;
#pragma unroll
        for (int kk = 0; kk < 4; kk++) {
            uint32_t a[2][4];
#pragma unroll
            for (int mi = 0; mi < 2; mi++) {
                uint32_t off = (rowA + mi * 16) * 128 + kk * 32 + kselA;
                ldsm4(a[mi][0], a[mi][1], a[mi][2], a[mi][3], aBase + sw128(off));
            }
            uint32_t bf[4][4];
#pragma unroll
            for (int n2 = 0; n2 < 4; n2++) {
                uint32_t off = (rowB + n2 * 16) * 128 + kk * 32 + kselB;
                ldsm4(bf[n2][0], bf[n2][1], bf[n2][2], bf[n2][3], bBase + sw128(off));
            }
#pragma unroll
            for (int mi = 0; mi < 2; mi++)
#pragma unroll
                for (int nn = 0; nn < 8; nn++) {
                    uint32_t b0 = bf[nn >> 1][(nn & 1) * 2];
                    uint32_t b1 = bf[nn >> 1][(nn & 1) * 2 + 1];
                    mma_bf16(cacc[mi][nn], a[mi][0], a[mi][1], a[mi][2], a[mi][3], b0, b1);
                }
        }
    }

#pragma unroll
    for (int mi = 0; mi < 2; mi++) {
        int r0 = wm * 32 + mi * 16 + (lane >> 2);
        int r1 = r0 + 8;
        float s0 = 0.f, s1 = 0.f;
#pragma unroll
        for (int nn = 0; nn < 8; nn++) {
            int col = wn * 64 + nn * 8 + 2 * (lane & 3);
            const float* cc = cacc[mi][nn];
#pragma unroll
            for (int e = 0; e < 2; e++) {
                int v = vb + col + e;
                if (v < VOCAB) {
                    float lg0 = cc[e] + bo_s[col + e];
                    float lg1 = cc[2 + e] + bo_s[col + e];
                    s0 += __expf(lg0);
                    s1 += __expf(lg1);
                    if (v == tgt_s[r0]) g_picked[r0] = lg0;
                    if (v == tgt_s[r1]) g_picked[r1] = lg1;
                }
            }
        }
        s0 += __shfl_xor_sync(0xffffffffu, s0, 1);
        s0 += __shfl_xor_sync(0xffffffffu, s0, 2);
        s1 += __shfl_xor_sync(0xffffffffu, s1, 1);
        s1 += __shfl_xor_sync(0xffffffffu, s1, 2);
        if ((lane & 3) == 0) {
            atomicAdd(&sexp_s[r0], s0);
            atomicAdd(&sexp_s[r1], s1);
        }
    }
    __syncthreads();
    for (int i = tid; i < 128; i += 256) atomicAdd(&g_sumexp[i], sexp_s[i]);
}

// ---------------- K6: final reduction ----------------
__global__ void finalize_kernel(float* __restrict__ out) {
    int tid = threadIdx.x;
    float v = g_picked[tid] - logf(g_sumexp[tid]);
    __shared__ float red[4];
    int w = tid >> 5, l = tid & 31;
#pragma unroll
    for (int o = 16; o; o >>= 1) v += __shfl_xor_sync(0xffffffffu, v, o);
    if (l == 0) red[w] = v;
    __syncthreads();
    if (tid == 0) out[0] = red[0] + red[1] + red[2] + red[3];
}

// ---------------- launch ----------------
extern "C" void kernel_launch(void* const* d_in, const int* in_sizes, int n_in,
                              void* d_out, int out_size) {
    const int* fnums = (const int*)d_in[0];
    const int* enums = (const int*)d_in[1];
    const float* emb_f = (const float*)d_in[2];
    const float* Wih_e = (const float*)d_in[3];
    const float* Whh_e = (const float*)d_in[4];
    const float* b_e = (const float*)d_in[5];
    const float* h0_e = (const float*)d_in[6];
    const float* emb_d = (const float*)d_in[7];
    const float* Wih_d = (const float*)d_in[8];
    const float* Whh_d = (const float*)d_in[9];
    const float* b_d = (const float*)d_in[10];
    const float* h0_d = (const float*)d_in[11];
    const float* Wm = (const float*)d_in[12];
    const float* bm = (const float*)d_in[13];
    const float* Wo = (const float*)d_in[14];
    const float* bo = (const float*)d_in[15];
    float* out = (float*)d_out;

    static int inited = 0;
    static float *p_xpre, *p_epre, *p_CH;
    static __nv_bfloat16* p_Mbf;
    if (!inited) {
        cudaFuncSetAttribute(logits_kernel, cudaFuncAttributeMaxDynamicSharedMemorySize,
                             LOGITS_SMEM);
        cudaGetSymbolAddress((void**)&p_xpre, g_xpre);
        cudaGetSymbolAddress((void**)&p_epre, g_epre);
        cudaGetSymbolAddress((void**)&p_CH, g_CH);
        cudaGetSymbolAddress((void**)&p_Mbf, g_Mbf);
        inited = 1;
    }

    // pre-activations: encoder (z=0) + decoder (z=1) concurrently
    gemm_kernel<<<dim3(8, 4, 2), 256>>>(emb_f, fnums, Wih_e, b_e,
                                        emb_d, enums, Wih_d, b_d,
                                        p_xpre, p_epre, nullptr, D, 0);
    // recur (y=0,1) + Wo->bf16 conversion (y=2..) overlapped in one launch
    recur_kernel<<<dim3(8, 2 + CONV_YS), 512>>>(Whh_e, Whh_d, h0_e, h0_d, Wo);
    // fused attention: scores + softmax + context + CH assembly
    attn_kernel<<<128, 256>>>();
    // M = tanh(CH @ Wm^T + bm) -> bf16 (also zeroes g_sumexp)
    gemm_kernel<<<dim3(8, 4, 1), 256>>>(p_CH, nullptr, Wm, bm,
                                        p_CH, nullptr, Wm, bm,
                                        nullptr, nullptr, p_Mbf, 2 * D, 1);
    logits_kernel<<<(VOCAB + 127) / 128, 256, LOGITS_SMEM>>>(bo, enums);
    finalize_kernel<<<1, 128>>>(out);
}

// round 12
// speedup vs baseline: 1.4346x; 1.0082x over previous
#include <cuda_runtime.h>
#include <cuda_bf16.h>
#include <cstdint>

#define D 512
#define SRC 128
#define TGT_STEPS 128
#define VOCAB 50000

typedef unsigned long long u64;

// ---------------- scratch (device globals; no allocation allowed) ----------------
__device__ __align__(16) float g_xpre[SRC * D];
__device__ __align__(16) float g_epre[TGT_STEPS * D];
__device__ __align__(16) float g_fencs[SRC * D];
__device__ __align__(16) float g_H[TGT_STEPS * D];
__device__ __align__(16) float g_CH[TGT_STEPS * 2 * D];
__device__ __align__(16) __nv_bfloat16 g_Mbf[TGT_STEPS * D];
__device__ __align__(16) __nv_bfloat16 g_Wobf[VOCAB * D];
__device__ float g_sumexp[TGT_STEPS];
__device__ float g_picked[TGT_STEPS];

// ---------------- helpers ----------------
__device__ __forceinline__ u64 pk2(float x, float y) {
    u64 r;
    asm("mov.b64 %0, {%1, %2};" : "=l"(r) : "f"(x), "f"(y));
    return r;
}
__device__ __forceinline__ float2 upk2(u64 v) {
    float2 r;
    asm("mov.b64 {%0, %1}, %2;" : "=f"(r.x), "=f"(r.y) : "l"(v));
    return r;
}
__device__ __forceinline__ void fma2(u64& d, u64 a, u64 b) {
    asm volatile("fma.rn.f32x2 %0, %1, %2, %0;" : "+l"(d) : "l"(a), "l"(b));
}
__device__ __forceinline__ uint32_t smem_u32(const void* p) {
    uint32_t a;
    asm("{ .reg .u64 t; cvta.to.shared.u64 t, %1; cvt.u32.u64 %0, t; }" : "=r"(a) : "l"(p));
    return a;
}
__device__ __forceinline__ uint32_t mapa_u32(uint32_t saddr, uint32_t rank) {
    uint32_t r;
    asm volatile("mapa.shared::cluster.u32 %0, %1, %2;" : "=r"(r) : "r"(saddr), "r"(rank));
    return r;
}
__device__ __forceinline__ void st_async_f32(uint32_t raddr, uint32_t rmbar, float v) {
    asm volatile(
        "st.async.shared::cluster.mbarrier::complete_tx::bytes.b32 [%0], %1, [%2];"
        :: "r"(raddr), "r"(__float_as_uint(v)), "r"(rmbar) : "memory");
}
__device__ __forceinline__ void mbar_init(uint32_t addr, uint32_t cnt) {
    asm volatile("mbarrier.init.shared.b64 [%0], %1;" :: "r"(addr), "r"(cnt) : "memory");
}
__device__ __forceinline__ void mbar_expect_tx(uint32_t addr, uint32_t bytes) {
    asm volatile("mbarrier.arrive.expect_tx.shared.b64 _, [%0], %1;"
                 :: "r"(addr), "r"(bytes) : "memory");
}
__device__ __forceinline__ void mbar_wait(uint32_t addr, int parity) {
    asm volatile(
        "{\n\t.reg .pred P;\n\t"
        "W_%=:\n\t"
        "mbarrier.try_wait.parity.acquire.cta.shared::cta.b64 P, [%0], %1;\n\t"
        "@!P bra W_%=;\n\t}"
        :: "r"(addr), "r"(parity) : "memory");
}
__device__ __forceinline__ void ldsm4(uint32_t& r0, uint32_t& r1, uint32_t& r2, uint32_t& r3,
                                      uint32_t addr) {
    asm volatile("ldmatrix.sync.aligned.m8n8.x4.shared.b16 {%0,%1,%2,%3}, [%4];"
                 : "=r"(r0), "=r"(r1), "=r"(r2), "=r"(r3) : "r"(addr));
}
__device__ __forceinline__ void mma_bf16(float* c, uint32_t a0, uint32_t a1, uint32_t a2,
                                         uint32_t a3, uint32_t b0, uint32_t b1) {
    asm volatile(
        "mma.sync.aligned.m16n8k16.row.col.f32.bf16.bf16.f32 "
        "{%0,%1,%2,%3}, {%4,%5,%6,%7}, {%8,%9}, {%0,%1,%2,%3};"
        : "+f"(c[0]), "+f"(c[1]), "+f"(c[2]), "+f"(c[3])
        : "r"(a0), "r"(a1), "r"(a2), "r"(a3), "r"(b0), "r"(b1));
}
__device__ __forceinline__ uint32_t sw128(uint32_t off) { return off ^ ((off >> 3) & 0x70); }
__device__ __forceinline__ float fast_tanh(float x) {
    float e = __expf(2.f * x);
    return __fdividef(e - 1.f, e + 1.f);
}

// ---------------- K1/K4: tiled SGEMM  out[m, n] = act(Xrow(m) . W[n,:] + bias[n]) ----
// 16x64 output tile, 256 threads (16x16), 1x4 micro-tile, f32x2 packed FMA.
__global__ void __launch_bounds__(256) gemm_kernel(
    const float* __restrict__ X0, const int* __restrict__ idx0,
    const float* __restrict__ W0, const float* __restrict__ b0,
    const float* __restrict__ X1, const int* __restrict__ idx1,
    const float* __restrict__ W1, const float* __restrict__ b1,
    float* __restrict__ oF0, float* __restrict__ oF1,
    __nv_bfloat16* __restrict__ oB,
    int K, int applyTanh) {
    const int z = blockIdx.z;
    const float* X = z ? X1 : X0;
    const int* idx = z ? idx1 : idx0;
    const float* W = z ? W1 : W0;
    const float* bias = z ? b1 : b0;
    float* outF = z ? oF1 : oF0;

    __shared__ __align__(16) float Xs[64][17];
    __shared__ __align__(16) float Ws[64][68];
    __shared__ int roff[16];

    const int tid = threadIdx.x;
    const int tx = tid & 15, ty = tid >> 4;
    const int mbase = blockIdx.y * 16;
    const int nbase = blockIdx.x * 64;

    // fold init: zero g_sumexp before logits runs (this kernel precedes logits)
    if (oB && blockIdx.x == 0 && blockIdx.y == 0 && z == 0 && tid < TGT_STEPS)
        g_sumexp[tid] = 0.f;

    if (tid < 16) {
        int m = mbase + tid;
        roff[tid] = (idx ? idx[m] : m) * K;
    }
    __syncthreads();

    u64 acc[2] = {0ull, 0ull};

    for (int kt = 0; kt < K; kt += 64) {
        {
            int m = tid >> 4, kq = tid & 15;
            float4 v = *(const float4*)&X[roff[m] + kt + kq * 4];
            Xs[kq * 4 + 0][m] = v.x;
            Xs[kq * 4 + 1][m] = v.y;
            Xs[kq * 4 + 2][m] = v.z;
            Xs[kq * 4 + 3][m] = v.w;
        }
#pragma unroll
        for (int j = 0; j < 4; j++) {
            int id = tid + 256 * j;
            int n = id >> 4, kq = id & 15;
            float4 v = *(const float4*)&W[(size_t)(nbase + n) * K + kt + kq * 4];
            Ws[kq * 4 + 0][n] = v.x;
            Ws[kq * 4 + 1][n] = v.y;
            Ws[kq * 4 + 2][n] = v.z;
            Ws[kq * 4 + 3][n] = v.w;
        }
        __syncthreads();
#pragma unroll
        for (int k = 0; k < 64; k++) {
            float a = Xs[k][ty];
            float4 b = *(const float4*)&Ws[k][tx * 4];
            u64 aa = pk2(a, a);
            fma2(acc[0], aa, pk2(b.x, b.y));
            fma2(acc[1], aa, pk2(b.z, b.w));
        }
        __syncthreads();
    }
    {
        int m = mbase + ty;
        float2 v0 = upk2(acc[0]), v1 = upk2(acc[1]);
        float o[4] = {v0.x, v0.y, v1.x, v1.y};
#pragma unroll
        for (int i = 0; i < 4; i++) {
            int n = nbase + tx * 4 + i;
            float val = o[i] + bias[n];
            if (applyTanh) val = fast_tanh(val);
            if (outF) outF[m * D + n] = val;
            else oB[m * D + n] = __float2bfloat16(val);
        }
    }
}

// ---------------- K2: recurrences (y=0,1: 8-CTA clusters, mbarrier pipeline)
//                    + Wo->bf16 convert (y>=2) ----------------
#define CONV_YS 6
__global__ void __cluster_dims__(8, 1, 1) __launch_bounds__(512, 1)
recur_kernel(const float* __restrict__ Whh_e, const float* __restrict__ Whh_d,
             const float* __restrict__ h0_e, const float* __restrict__ h0_d,
             const float* __restrict__ Wo) {
    const int tid = threadIdx.x;

    if (blockIdx.y >= 2) {
        // ---- Wo fp32 -> bf16 converter ----
        const size_t n4 = (size_t)VOCAB * D / 4;
        const size_t gt = (size_t)((blockIdx.y - 2) * 8 + blockIdx.x) * 512 + tid;
        const size_t stride = (size_t)CONV_YS * 8 * 512;
        const float4* src = (const float4*)Wo;
        uint2* dst = (uint2*)g_Wobf;
        for (size_t i = gt; i < n4; i += stride) {
            float4 f = src[i];
            __nv_bfloat162 lo = __float22bfloat162_rn(make_float2(f.x, f.y));
            __nv_bfloat162 hi = __float22bfloat162_rn(make_float2(f.z, f.w));
            uint2 u;
            u.x = *(uint32_t*)&lo;
            u.y = *(uint32_t*)&hi;
            dst[i] = u;
        }
        return;
    }

    const int ph = blockIdx.y;
    const float* W = ph ? Whh_d : Whh_e;
    const float* h0 = ph ? h0_d : h0_e;
    const float* pre = ph ? g_epre : g_xpre;
    float* outg = ph ? g_H : g_fencs;

    __shared__ __align__(16) float hbuf[3][D];
    __shared__ __align__(8) u64 mbar[3];
    __shared__ float pre_s[128 * 64];

    const int rl = tid >> 3;
    const int sub = tid & 7;
    const uint32_t rank = blockIdx.x;
    const int row = rank * 64 + rl;

    u64 wv2[32];
#pragma unroll
    for (int j = 0; j < 16; j++) {
        ulonglong2 t = *(const ulonglong2*)&W[row * D + j * 32 + sub * 4];
        wv2[2 * j] = t.x;
        wv2[2 * j + 1] = t.y;
    }

    for (int i = tid; i < 128 * 64; i += 512) {
        int t = i >> 6, r = i & 63;
        pre_s[i] = pre[t * D + rank * 64 + r];
    }
    hbuf[0][tid] = h0[tid];
    if (tid < 3) mbar_init(smem_u32(&mbar[tid]), 1);
    __syncthreads();
    // all CTAs' hbuf[0] + mbarriers must be ready before any remote store
    asm volatile("barrier.cluster.arrive.aligned;" ::: "memory");
    asm volatile("barrier.cluster.wait.aligned;" ::: "memory");

    const uint32_t mb_local = smem_u32(&mbar[0]);
    const uint32_t dst_remote0 = mapa_u32(smem_u32(&hbuf[0][row]), (uint32_t)sub);
    const uint32_t mb_remote0 = mapa_u32(mb_local, (uint32_t)sub);

#pragma unroll 1
    for (int t = 0; t < 128; t++) {
        const int b = t % 3;
        const int bn = (t + 1) % 3;
        if (tid == 0 && t < 127) mbar_expect_tx(mb_local + bn * 8, (uint32_t)(D * 4));
        if (t > 0) mbar_wait(mb_local + b * 8, ((t - 1) / 3) & 1);

        const float* hp = hbuf[b];
        u64 A0 = 0ull, A1 = 0ull;
#pragma unroll
        for (int j = 0; j < 16; j++) {
            ulonglong2 hv = *(const ulonglong2*)&hp[j * 32 + sub * 4];
            fma2(A0, wv2[2 * j], hv.x);
            fma2(A1, wv2[2 * j + 1], hv.y);
        }
        float2 f0 = upk2(A0), f1 = upk2(A1);
        float acc = (f0.x + f0.y) + (f1.x + f1.y);
#pragma unroll
        for (int o = 4; o; o >>= 1) acc += __shfl_xor_sync(0xffffffffu, acc, o);
        float h = fast_tanh(acc + pre_s[t * 64 + rl]);
        if (t < 127) st_async_f32(dst_remote0 + bn * (D * 4), mb_remote0 + bn * 8, h);
        if (sub == 0) outg[t * D + row] = h;
    }
    // no CTA may exit while peers might still target its SMEM
    asm volatile("barrier.cluster.arrive.aligned;" ::: "memory");
    asm volatile("barrier.cluster.wait.aligned;" ::: "memory");
}

// ---------------- K3: fused attention per t: scores + softmax + context + CH ----
__global__ void __launch_bounds__(256) attn_kernel() {
    int t = blockIdx.x;
    int tid = threadIdx.x, w = tid >> 5, l = tid & 31;
    __shared__ __align__(16) float hs[D];
    __shared__ float al[SRC];
    __shared__ float red[16];
    __shared__ __align__(16) float cpart[D];

    *(float2*)&hs[tid * 2] = *(const float2*)&g_H[t * D + tid * 2];
    __syncthreads();

    // scores: warp w computes 16 scores
#pragma unroll 1
    for (int si = 0; si < 16; si++) {
        int s2 = w * 16 + si;
        float acc = 0.f;
#pragma unroll
        for (int j = 0; j < 4; j++) {
            float4 fv = *(const float4*)&g_fencs[s2 * D + l * 4 + j * 128];
            float4 hv = *(const float4*)&hs[l * 4 + j * 128];
            acc += fv.x * hv.x + fv.y * hv.y + fv.z * hv.z + fv.w * hv.w;
        }
#pragma unroll
        for (int o = 16; o; o >>= 1) acc += __shfl_xor_sync(0xffffffffu, acc, o);
        if (l == 0) al[s2] = acc;
    }
    __syncthreads();

    // softmax over 128 scores
    float v = (tid < SRC) ? al[tid] : -1e30f;
    float mx = v;
#pragma unroll
    for (int o = 16; o; o >>= 1) mx = fmaxf(mx, __shfl_xor_sync(0xffffffffu, mx, o));
    if (l == 0) red[w] = mx;
    __syncthreads();
    mx = fmaxf(fmaxf(red[0], red[1]), fmaxf(red[2], red[3]));
    float e = (tid < SRC) ? __expf(v - mx) : 0.f;
    float sm = e;
#pragma unroll
    for (int o = 16; o; o >>= 1) sm += __shfl_xor_sync(0xffffffffu, sm, o);
    if (l == 0) red[8 + w] = sm;
    __syncthreads();
    sm = red[8] + red[9] + red[10] + red[11];
    if (tid < SRC) al[tid] = e / sm;
    __syncthreads();

    // context: thread (d4 = tid&127, shalf = tid>>7) sums 64 s values (fencs L1-hot)
    const int d4 = tid & 127, shalf = tid >> 7;
    const float4* f4 = (const float4*)g_fencs;
    float4 c = make_float4(0.f, 0.f, 0.f, 0.f);
    int s0 = shalf * 64;
#pragma unroll 8
    for (int s = s0; s < s0 + 64; s++) {
        float a = al[s];
        float4 fv = f4[s * (D / 4) + d4];
        c.x = fmaf(a, fv.x, c.x);
        c.y = fmaf(a, fv.y, c.y);
        c.z = fmaf(a, fv.z, c.z);
        c.w = fmaf(a, fv.w, c.w);
    }
    if (shalf == 1) *(float4*)&cpart[d4 * 4] = c;
    __syncthreads();
    if (shalf == 0) {
        float4 p = *(const float4*)&cpart[d4 * 4];
        c.x += p.x; c.y += p.y; c.z += p.z; c.w += p.w;
        *(float4*)&g_CH[t * 2 * D + d4 * 4] = c;
    }
    // H half of CH
    *(float2*)&g_CH[t * 2 * D + D + tid * 2] = *(const float2*)&hs[tid * 2];
}

// ---------------- K5: logits via mma.sync bf16 (B pre-converted) ----------------
#define OFF_BO 0
#define OFF_TGT 512
#define OFF_SEXP 1024
#define OFF_B 2048
#define OFF_A (2048 + 2 * 16384)
#define LOGITS_SMEM (OFF_A + 8 * 16384)

__global__ void __launch_bounds__(256, 1) logits_kernel(const float* __restrict__ bo,
                                                        const int* __restrict__ enums) {
    extern __shared__ char smem[];
    const uint32_t sb = smem_u32(smem);
    const int tid = threadIdx.x;
    const int lane = tid & 31;
    const int wm = (tid >> 5) & 3;
    const int wn = tid >> 7;
    const int vb = blockIdx.x * 128;

    float* bo_s = (float*)(smem + OFF_BO);
    int* tgt_s = (int*)(smem + OFF_TGT);
    float* sexp_s = (float*)(smem + OFF_SEXP);

    for (int i = tid; i < 128; i += 256) {
        int v = vb + i;
        bo_s[i] = (v < VOCAB) ? bo[v] : 0.f;
        tgt_s[i] = enums[i + 1];
        sexp_s[i] = 0.f;
    }

    for (int i = tid * 8; i < TGT_STEPS * D; i += 256 * 8) {
        int t = i >> 9, k = i & 511;
        uint4 v = *(const uint4*)&g_Mbf[i];
        int c = k >> 6, kk = k & 63;
        uint32_t sw = sw128(t * 128 + kk * 2);
        *(uint4*)(smem + OFF_A + c * 16384 + sw) = v;
    }

    const int rowl = tid >> 1, q = tid & 1;
    const bool vok = (vb + rowl) < VOCAB;
    const uint4* wsrc = (const uint4*)&g_Wobf[(size_t)(vb + rowl) * D];
    const uint4 Z = make_uint4(0u, 0u, 0u, 0u);

    uint4 pf[4];
#pragma unroll
    for (int j = 0; j < 4; j++) pf[j] = vok ? wsrc[q * 4 + j] : Z;

    float cacc[2][8][4];
#pragma unroll
    for (int mi = 0; mi < 2; mi++)
#pragma unroll
        for (int nn = 0; nn < 8; nn++)
#pragma unroll
            for (int e = 0; e < 4; e++) cacc[mi][nn][e] = 0.f;

    const int rowA = wm * 32 + (lane & 15);
    const int kselA = (lane >> 4) << 4;
    const int rowB = wn * 64 + (lane & 7) + ((lane & 16) >> 1);
    const int kselB = (lane & 8) << 1;

#pragma unroll 1
    for (int c = 0; c < 8; c++) {
        char* bbuf = smem + OFF_B + (c & 1) * 16384;
#pragma unroll
        for (int j = 0; j < 4; j++) {
            uint32_t sw = sw128(rowl * 128 + q * 64 + j * 16);
            *(uint4*)(bbuf + sw) = pf[j];
        }
        __syncthreads();
        if (c < 7) {
#pragma unroll
            for (int j = 0; j < 4; j++)
                pf[j] = vok ? wsrc[(c + 1) * 8 + q * 4 + j] : Z;
        }
        const uint32_t aBase = sb + OFF_A + c * 16384;
        const uint32_t bBase = sb + OFF_B + (c & 1) * 16384;
#pragma unroll
        for (int kk = 0; kk < 4; kk++) {
            uint32_t a[2][4];
#pragma unroll
            for (int mi = 0; mi < 2; mi++) {
                uint32_t off = (rowA + mi * 16) * 128 + kk * 32 + kselA;
                ldsm4(a[mi][0], a[mi][1], a[mi][2], a[mi][3], aBase + sw128(off));
            }
            uint32_t bf[4][4];
#pragma unroll
            for (int n2 = 0; n2 < 4; n2++) {
                uint32_t off = (rowB + n2 * 16) * 128 + kk * 32 + kselB;
                ldsm4(bf[n2][0], bf[n2][1], bf[n2][2], bf[n2][3], bBase + sw128(off));
            }
#pragma unroll
            for (int mi = 0; mi < 2; mi++)
#pragma unroll
                for (int nn = 0; nn < 8; nn++) {
                    uint32_t b0 = bf[nn >> 1][(nn & 1) * 2];
                    uint32_t b1 = bf[nn >> 1][(nn & 1) * 2 + 1];
                    mma_bf16(cacc[mi][nn], a[mi][0], a[mi][1], a[mi][2], a[mi][3], b0, b1);
                }
        }
    }

#pragma unroll
    for (int mi = 0; mi < 2; mi++) {
        int r0 = wm * 32 + mi * 16 + (lane >> 2);
        int r1 = r0 + 8;
        float s0 = 0.f, s1 = 0.f;
#pragma unroll
        for (int nn = 0; nn < 8; nn++) {
            int col = wn * 64 + nn * 8 + 2 * (lane & 3);
            const float* cc = cacc[mi][nn];
#pragma unroll
            for (int e = 0; e < 2; e++) {
                int v = vb + col + e;
                if (v < VOCAB) {
                    float lg0 = cc[e] + bo_s[col + e];
                    float lg1 = cc[2 + e] + bo_s[col + e];
                    s0 += __expf(lg0);
                    s1 += __expf(lg1);
                    if (v == tgt_s[r0]) g_picked[r0] = lg0;
                    if (v == tgt_s[r1]) g_picked[r1] = lg1;
                }
            }
        }
        s0 += __shfl_xor_sync(0xffffffffu, s0, 1);
        s0 += __shfl_xor_sync(0xffffffffu, s0, 2);
        s1 += __shfl_xor_sync(0xffffffffu, s1, 1);
        s1 += __shfl_xor_sync(0xffffffffu, s1, 2);
        if ((lane & 3) == 0) {
            atomicAdd(&sexp_s[r0], s0);
            atomicAdd(&sexp_s[r1], s1);
        }
    }
    __syncthreads();
    for (int i = tid; i < 128; i += 256) atomicAdd(&g_sumexp[i], sexp_s[i]);
}

// ---------------- K6: final reduction ----------------
__global__ void finalize_kernel(float* __restrict__ out) {
    int tid = threadIdx.x;
    float v = g_picked[tid] - logf(g_sumexp[tid]);
    __shared__ float red[4];
    int w = tid >> 5, l = tid & 31;
#pragma unroll
    for (int o = 16; o; o >>= 1) v += __shfl_xor_sync(0xffffffffu, v, o);
    if (l == 0) red[w] = v;
    __syncthreads();
    if (tid == 0) out[0] = red[0] + red[1] + red[2] + red[3];
}

// ---------------- launch ----------------
extern "C" void kernel_launch(void* const* d_in, const int* in_sizes, int n_in,
                              void* d_out, int out_size) {
    const int* fnums = (const int*)d_in[0];
    const int* enums = (const int*)d_in[1];
    const float* emb_f = (const float*)d_in[2];
    const float* Wih_e = (const float*)d_in[3];
    const float* Whh_e = (const float*)d_in[4];
    const float* b_e = (const float*)d_in[5];
    const float* h0_e = (const float*)d_in[6];
    const float* emb_d = (const float*)d_in[7];
    const float* Wih_d = (const float*)d_in[8];
    const float* Whh_d = (const float*)d_in[9];
    const float* b_d = (const float*)d_in[10];
    const float* h0_d = (const float*)d_in[11];
    const float* Wm = (const float*)d_in[12];
    const float* bm = (const float*)d_in[13];
    const float* Wo = (const float*)d_in[14];
    const float* bo = (const float*)d_in[15];
    float* out = (float*)d_out;

    static int inited = 0;
    static float *p_xpre, *p_epre, *p_CH;
    static __nv_bfloat16* p_Mbf;
    if (!inited) {
        cudaFuncSetAttribute(logits_kernel, cudaFuncAttributeMaxDynamicSharedMemorySize,
                             LOGITS_SMEM);
        cudaGetSymbolAddress((void**)&p_xpre, g_xpre);
        cudaGetSymbolAddress((void**)&p_epre, g_epre);
        cudaGetSymbolAddress((void**)&p_CH, g_CH);
        cudaGetSymbolAddress((void**)&p_Mbf, g_Mbf);
        inited = 1;
    }

    // pre-activations: encoder (z=0) + decoder (z=1) concurrently; 128 CTAs
    gemm_kernel<<<dim3(8, 8, 2), 256>>>(emb_f, fnums, Wih_e, b_e,
                                        emb_d, enums, Wih_d, b_d,
                                        p_xpre, p_epre, nullptr, D, 0);
    // recur (y=0,1) + Wo->bf16 conversion (y=2..) overlapped in one launch
    recur_kernel<<<dim3(8, 2 + CONV_YS), 512>>>(Whh_e, Whh_d, h0_e, h0_d, Wo);
    // fused attention: scores + softmax + context + CH assembly
    attn_kernel<<<128, 256>>>();
    // M = tanh(CH @ Wm^T + bm) -> bf16 (also zeroes g_sumexp); 64 CTAs
    gemm_kernel<<<dim3(8, 8, 1), 256>>>(p_CH, nullptr, Wm, bm,
                                        p_CH, nullptr, Wm, bm,
                                        nullptr, nullptr, p_Mbf, 2 * D, 1);
    logits_kernel<<<(VOCAB + 127) / 128, 256, LOGITS_SMEM>>>(bo, enums);
    finalize_kernel<<<1, 128>>>(out);
}

// round 13
// speedup vs baseline: 1.5335x; 1.0690x over previous
#include <cuda_runtime.h>
#include <cuda_bf16.h>
#include <cstdint>

#define D 512
#define SRC 128
#define TGT_STEPS 128
#define VOCAB 50000

typedef unsigned long long u64;

// ---------------- scratch (device globals; no allocation allowed) ----------------
__device__ __align__(16) float g_xpre[SRC * D];
__device__ __align__(16) float g_epre[TGT_STEPS * D];
__device__ __align__(16) float g_fencs[SRC * D];
__device__ __align__(16) float g_H[TGT_STEPS * D];
__device__ __align__(16) __nv_bfloat16 g_CHbf[TGT_STEPS * 2 * D];
__device__ __align__(16) __nv_bfloat16 g_Mbf[TGT_STEPS * D];
__device__ __align__(16) __nv_bfloat16 g_Wmbf[D * 2 * D];
__device__ __align__(16) __nv_bfloat16 g_Wobf[VOCAB * D];
__device__ float g_sumexp[TGT_STEPS];
__device__ float g_picked[TGT_STEPS];

// ---------------- helpers ----------------
__device__ __forceinline__ u64 pk2(float x, float y) {
    u64 r;
    asm("mov.b64 %0, {%1, %2};" : "=l"(r) : "f"(x), "f"(y));
    return r;
}
__device__ __forceinline__ float2 upk2(u64 v) {
    float2 r;
    asm("mov.b64 {%0, %1}, %2;" : "=f"(r.x), "=f"(r.y) : "l"(v));
    return r;
}
__device__ __forceinline__ void fma2(u64& d, u64 a, u64 b) {
    asm volatile("fma.rn.f32x2 %0, %1, %2, %0;" : "+l"(d) : "l"(a), "l"(b));
}
__device__ __forceinline__ uint32_t smem_u32(const void* p) {
    uint32_t a;
    asm("{ .reg .u64 t; cvta.to.shared.u64 t, %1; cvt.u32.u64 %0, t; }" : "=r"(a) : "l"(p));
    return a;
}
__device__ __forceinline__ uint32_t mapa_u32(uint32_t saddr, uint32_t rank) {
    uint32_t r;
    asm volatile("mapa.shared::cluster.u32 %0, %1, %2;" : "=r"(r) : "r"(saddr), "r"(rank));
    return r;
}
__device__ __forceinline__ void st_async_f32(uint32_t raddr, uint32_t rmbar, float v) {
    asm volatile(
        "st.async.shared::cluster.mbarrier::complete_tx::bytes.b32 [%0], %1, [%2];"
        :: "r"(raddr), "r"(__float_as_uint(v)), "r"(rmbar) : "memory");
}
__device__ __forceinline__ void mbar_init(uint32_t addr, uint32_t cnt) {
    asm volatile("mbarrier.init.shared.b64 [%0], %1;" :: "r"(addr), "r"(cnt) : "memory");
}
__device__ __forceinline__ void mbar_expect_tx(uint32_t addr, uint32_t bytes) {
    asm volatile("mbarrier.arrive.expect_tx.shared.b64 _, [%0], %1;"
                 :: "r"(addr), "r"(bytes) : "memory");
}
__device__ __forceinline__ void mbar_wait(uint32_t addr, int parity) {
    asm volatile(
        "{\n\t.reg .pred P;\n\t"
        "W_%=:\n\t"
        "mbarrier.try_wait.parity.acquire.cta.shared::cta.b64 P, [%0], %1;\n\t"
        "@!P bra W_%=;\n\t}"
        :: "r"(addr), "r"(parity) : "memory");
}
__device__ __forceinline__ void ldsm4(uint32_t& r0, uint32_t& r1, uint32_t& r2, uint32_t& r3,
                                      uint32_t addr) {
    asm volatile("ldmatrix.sync.aligned.m8n8.x4.shared.b16 {%0,%1,%2,%3}, [%4];"
                 : "=r"(r0), "=r"(r1), "=r"(r2), "=r"(r3) : "r"(addr));
}
__device__ __forceinline__ void mma_bf16(float* c, uint32_t a0, uint32_t a1, uint32_t a2,
                                         uint32_t a3, uint32_t b0, uint32_t b1) {
    asm volatile(
        "mma.sync.aligned.m16n8k16.row.col.f32.bf16.bf16.f32 "
        "{%0,%1,%2,%3}, {%4,%5,%6,%7}, {%8,%9}, {%0,%1,%2,%3};"
        : "+f"(c[0]), "+f"(c[1]), "+f"(c[2]), "+f"(c[3])
        : "r"(a0), "r"(a1), "r"(a2), "r"(a3), "r"(b0), "r"(b1));
}
__device__ __forceinline__ uint32_t sw128(uint32_t off) { return off ^ ((off >> 3) & 0x70); }
__device__ __forceinline__ float fast_tanh(float x) {
    float e = __expf(2.f * x);
    return __fdividef(e - 1.f, e + 1.f);
}

// ---------------- K1: pre-activation SGEMM (fp32 kept for recurrence precision) ----
// 16x64 output tile, 256 threads, 1x4 micro-tile, f32x2 packed FMA.
__global__ void __launch_bounds__(256) gemm_kernel(
    const float* __restrict__ X0, const int* __restrict__ idx0,
    const float* __restrict__ W0, const float* __restrict__ b0,
    const float* __restrict__ X1, const int* __restrict__ idx1,
    const float* __restrict__ W1, const float* __restrict__ b1,
    float* __restrict__ oF0, float* __restrict__ oF1,
    int K) {
    const int z = blockIdx.z;
    const float* X = z ? X1 : X0;
    const int* idx = z ? idx1 : idx0;
    const float* W = z ? W1 : W0;
    const float* bias = z ? b1 : b0;
    float* outF = z ? oF1 : oF0;

    __shared__ __align__(16) float Xs[64][17];
    __shared__ __align__(16) float Ws[64][68];
    __shared__ int roff[16];

    const int tid = threadIdx.x;
    const int tx = tid & 15, ty = tid >> 4;
    const int mbase = blockIdx.y * 16;
    const int nbase = blockIdx.x * 64;

    if (tid < 16) {
        int m = mbase + tid;
        roff[tid] = (idx ? idx[m] : m) * K;
    }
    __syncthreads();

    u64 acc[2] = {0ull, 0ull};

    for (int kt = 0; kt < K; kt += 64) {
        {
            int m = tid >> 4, kq = tid & 15;
            float4 v = *(const float4*)&X[roff[m] + kt + kq * 4];
            Xs[kq * 4 + 0][m] = v.x;
            Xs[kq * 4 + 1][m] = v.y;
            Xs[kq * 4 + 2][m] = v.z;
            Xs[kq * 4 + 3][m] = v.w;
        }
#pragma unroll
        for (int j = 0; j < 4; j++) {
            int id = tid + 256 * j;
            int n = id >> 4, kq = id & 15;
            float4 v = *(const float4*)&W[(size_t)(nbase + n) * K + kt + kq * 4];
            Ws[kq * 4 + 0][n] = v.x;
            Ws[kq * 4 + 1][n] = v.y;
            Ws[kq * 4 + 2][n] = v.z;
            Ws[kq * 4 + 3][n] = v.w;
        }
        __syncthreads();
#pragma unroll
        for (int k = 0; k < 64; k++) {
            float a = Xs[k][ty];
            float4 b = *(const float4*)&Ws[k][tx * 4];
            u64 aa = pk2(a, a);
            fma2(acc[0], aa, pk2(b.x, b.y));
            fma2(acc[1], aa, pk2(b.z, b.w));
        }
        __syncthreads();
    }
    {
        int m = mbase + ty;
        float2 v0 = upk2(acc[0]), v1 = upk2(acc[1]);
        float o[4] = {v0.x, v0.y, v1.x, v1.y};
#pragma unroll
        for (int i = 0; i < 4; i++) {
            int n = nbase + tx * 4 + i;
            outF[m * D + n] = o[i] + bias[n];
        }
    }
}

// ---------------- K2: recurrences (y=0,1: 8-CTA clusters, mbarrier pipeline)
//                    + Wo/Wm->bf16 convert (y>=2) ----------------
#define CONV_YS 6
__global__ void __cluster_dims__(8, 1, 1) __launch_bounds__(512, 1)
recur_kernel(const float* __restrict__ Whh_e, const float* __restrict__ Whh_d,
             const float* __restrict__ h0_e, const float* __restrict__ h0_d,
             const float* __restrict__ Wo, const float* __restrict__ Wm) {
    const int tid = threadIdx.x;

    if (blockIdx.y >= 2) {
        // ---- Wo + Wm fp32 -> bf16 converters ----
        const size_t gt = (size_t)((blockIdx.y - 2) * 8 + blockIdx.x) * 512 + tid;
        const size_t stride = (size_t)CONV_YS * 8 * 512;
        {
            const size_t n4 = (size_t)VOCAB * D / 4;
            const float4* src = (const float4*)Wo;
            uint2* dst = (uint2*)g_Wobf;
            for (size_t i = gt; i < n4; i += stride) {
                float4 f = src[i];
                __nv_bfloat162 lo = __float22bfloat162_rn(make_float2(f.x, f.y));
                __nv_bfloat162 hi = __float22bfloat162_rn(make_float2(f.z, f.w));
                uint2 u;
                u.x = *(uint32_t*)&lo;
                u.y = *(uint32_t*)&hi;
                dst[i] = u;
            }
        }
        {
            const size_t n4 = (size_t)D * 2 * D / 4;
            const float4* src = (const float4*)Wm;
            uint2* dst = (uint2*)g_Wmbf;
            for (size_t i = gt; i < n4; i += stride) {
                float4 f = src[i];
                __nv_bfloat162 lo = __float22bfloat162_rn(make_float2(f.x, f.y));
                __nv_bfloat162 hi = __float22bfloat162_rn(make_float2(f.z, f.w));
                uint2 u;
                u.x = *(uint32_t*)&lo;
                u.y = *(uint32_t*)&hi;
                dst[i] = u;
            }
        }
        return;
    }

    const int ph = blockIdx.y;
    const float* W = ph ? Whh_d : Whh_e;
    const float* h0 = ph ? h0_d : h0_e;
    const float* pre = ph ? g_epre : g_xpre;
    float* outg = ph ? g_H : g_fencs;

    __shared__ __align__(16) float hbuf[3][D];
    __shared__ __align__(8) u64 mbar[3];
    __shared__ float pre_s[128 * 64];

    const int rl = tid >> 3;
    const int sub = tid & 7;
    const uint32_t rank = blockIdx.x;
    const int row = rank * 64 + rl;

    u64 wv2[32];
#pragma unroll
    for (int j = 0; j < 16; j++) {
        ulonglong2 t = *(const ulonglong2*)&W[row * D + j * 32 + sub * 4];
        wv2[2 * j] = t.x;
        wv2[2 * j + 1] = t.y;
    }

    for (int i = tid; i < 128 * 64; i += 512) {
        int t = i >> 6, r = i & 63;
        pre_s[i] = pre[t * D + rank * 64 + r];
    }
    hbuf[0][tid] = h0[tid];
    if (tid < 3) mbar_init(smem_u32(&mbar[tid]), 1);
    __syncthreads();
    asm volatile("barrier.cluster.arrive.aligned;" ::: "memory");
    asm volatile("barrier.cluster.wait.aligned;" ::: "memory");

    const uint32_t mb_local = smem_u32(&mbar[0]);
    const uint32_t dst_remote0 = mapa_u32(smem_u32(&hbuf[0][row]), (uint32_t)sub);
    const uint32_t mb_remote0 = mapa_u32(mb_local, (uint32_t)sub);

#pragma unroll 1
    for (int t = 0; t < 128; t++) {
        const int b = t % 3;
        const int bn = (t + 1) % 3;
        if (tid == 0 && t < 127) mbar_expect_tx(mb_local + bn * 8, (uint32_t)(D * 4));
        if (t > 0) mbar_wait(mb_local + b * 8, ((t - 1) / 3) & 1);

        const float* hp = hbuf[b];
        u64 A0 = 0ull, A1 = 0ull;
#pragma unroll
        for (int j = 0; j < 16; j++) {
            ulonglong2 hv = *(const ulonglong2*)&hp[j * 32 + sub * 4];
            fma2(A0, wv2[2 * j], hv.x);
            fma2(A1, wv2[2 * j + 1], hv.y);
        }
        float2 f0 = upk2(A0), f1 = upk2(A1);
        float acc = (f0.x + f0.y) + (f1.x + f1.y);
#pragma unroll
        for (int o = 4; o; o >>= 1) acc += __shfl_xor_sync(0xffffffffu, acc, o);
        float h = fast_tanh(acc + pre_s[t * 64 + rl]);
        if (t < 127) st_async_f32(dst_remote0 + bn * (D * 4), mb_remote0 + bn * 8, h);
        if (sub == 0) outg[t * D + row] = h;
    }
    asm volatile("barrier.cluster.arrive.aligned;" ::: "memory");
    asm volatile("barrier.cluster.wait.aligned;" ::: "memory");
}

// ---------------- K3: fused attention per t -> CH in bf16 ----------------
__global__ void __launch_bounds__(256) attn_kernel() {
    int t = blockIdx.x;
    int tid = threadIdx.x, w = tid >> 5, l = tid & 31;
    __shared__ __align__(16) float hs[D];
    __shared__ float al[SRC];
    __shared__ float red[16];
    __shared__ __align__(16) float cpart[D];

    if (blockIdx.x == 0 && tid < TGT_STEPS) g_sumexp[tid] = 0.f;

    *(float2*)&hs[tid * 2] = *(const float2*)&g_H[t * D + tid * 2];
    __syncthreads();

    // scores: warp w computes 16 scores
#pragma unroll 1
    for (int si = 0; si < 16; si++) {
        int s2 = w * 16 + si;
        float acc = 0.f;
#pragma unroll
        for (int j = 0; j < 4; j++) {
            float4 fv = *(const float4*)&g_fencs[s2 * D + l * 4 + j * 128];
            float4 hv = *(const float4*)&hs[l * 4 + j * 128];
            acc += fv.x * hv.x + fv.y * hv.y + fv.z * hv.z + fv.w * hv.w;
        }
#pragma unroll
        for (int o = 16; o; o >>= 1) acc += __shfl_xor_sync(0xffffffffu, acc, o);
        if (l == 0) al[s2] = acc;
    }
    __syncthreads();

    // softmax over 128 scores
    float v = (tid < SRC) ? al[tid] : -1e30f;
    float mx = v;
#pragma unroll
    for (int o = 16; o; o >>= 1) mx = fmaxf(mx, __shfl_xor_sync(0xffffffffu, mx, o));
    if (l == 0) red[w] = mx;
    __syncthreads();
    mx = fmaxf(fmaxf(red[0], red[1]), fmaxf(red[2], red[3]));
    float e = (tid < SRC) ? __expf(v - mx) : 0.f;
    float sm = e;
#pragma unroll
    for (int o = 16; o; o >>= 1) sm += __shfl_xor_sync(0xffffffffu, sm, o);
    if (l == 0) red[8 + w] = sm;
    __syncthreads();
    sm = red[8] + red[9] + red[10] + red[11];
    if (tid < SRC) al[tid] = e / sm;
    __syncthreads();

    // context: thread (d4 = tid&127, shalf = tid>>7) sums 64 s values
    const int d4 = tid & 127, shalf = tid >> 7;
    const float4* f4 = (const float4*)g_fencs;
    float4 c = make_float4(0.f, 0.f, 0.f, 0.f);
    int s0 = shalf * 64;
#pragma unroll 8
    for (int s = s0; s < s0 + 64; s++) {
        float a = al[s];
        float4 fv = f4[s * (D / 4) + d4];
        c.x = fmaf(a, fv.x, c.x);
        c.y = fmaf(a, fv.y, c.y);
        c.z = fmaf(a, fv.z, c.z);
        c.w = fmaf(a, fv.w, c.w);
    }
    if (shalf == 1) *(float4*)&cpart[d4 * 4] = c;
    __syncthreads();
    if (shalf == 0) {
        float4 p = *(const float4*)&cpart[d4 * 4];
        c.x += p.x; c.y += p.y; c.z += p.z; c.w += p.w;
        __nv_bfloat162 lo = __float22bfloat162_rn(make_float2(c.x, c.y));
        __nv_bfloat162 hi = __float22bfloat162_rn(make_float2(c.z, c.w));
        uint2 u;
        u.x = *(uint32_t*)&lo;
        u.y = *(uint32_t*)&hi;
        *(uint2*)&g_CHbf[t * 2 * D + d4 * 4] = u;
    }
    // H half of CH (bf16)
    {
        float2 hv = *(const float2*)&hs[tid * 2];
        __nv_bfloat162 hb = __float22bfloat162_rn(hv);
        *(uint32_t*)&g_CHbf[t * 2 * D + D + tid * 2] = *(uint32_t*)&hb;
    }
}

// ---------------- K4: M = tanh(CHbf @ Wmbf^T + bm) via mma.sync bf16 ----------------
// grid 4 CTAs (N=128/CTA), 256 threads; K=1024 in 16 double-buffered chunks.
#define M_OFF_B 0
#define M_OFF_A (2 * 16384)
#define M_SMEM (4 * 16384)

__global__ void __launch_bounds__(256, 1) m_hmma_kernel(const float* __restrict__ bm) {
    extern __shared__ char smem[];
    const uint32_t sb = smem_u32(smem);
    const int tid = threadIdx.x;
    const int lane = tid & 31;
    const int wm = (tid >> 5) & 3;
    const int wn = tid >> 7;
    const int nbase = blockIdx.x * 128;

    const int rowl = tid >> 1, q = tid & 1;
    const uint4* asrc = (const uint4*)&g_CHbf[(size_t)rowl * 2 * D + q * 32];
    const uint4* bsrc = (const uint4*)&g_Wmbf[(size_t)(nbase + rowl) * 2 * D + q * 32];

    uint4 pfa[4], pfb[4];
#pragma unroll
    for (int j = 0; j < 4; j++) {
        pfa[j] = asrc[j];
        pfb[j] = bsrc[j];
    }

    float cacc[2][8][4];
#pragma unroll
    for (int mi = 0; mi < 2; mi++)
#pragma unroll
        for (int nn = 0; nn < 8; nn++)
#pragma unroll
            for (int e = 0; e < 4; e++) cacc[mi][nn][e] = 0.f;

    const int rowA = wm * 32 + (lane & 15);
    const int kselA = (lane >> 4) << 4;
    const int rowB = wn * 64 + (lane & 7) + ((lane & 16) >> 1);
    const int kselB = (lane & 8) << 1;

#pragma unroll 1
    for (int c = 0; c < 16; c++) {
        char* abuf = smem + M_OFF_A + (c & 1) * 16384;
        char* bbuf = smem + M_OFF_B + (c & 1) * 16384;
#pragma unroll
        for (int j = 0; j < 4; j++) {
            uint32_t sw = sw128(rowl * 128 + q * 64 + j * 16);
            *(uint4*)(abuf + sw) = pfa[j];
            *(uint4*)(bbuf + sw) = pfb[j];
        }
        __syncthreads();
        if (c < 15) {
            // chunk c+1 starts at k = (c+1)*64 bf16 = (c+1)*8 uint4
#pragma unroll
            for (int j = 0; j < 4; j++) {
                pfa[j] = asrc[(c + 1) * 8 + j];
                pfb[j] = bsrc[(c + 1) * 8 + j];
            }
        }
        const uint32_t aBase = sb + M_OFF_A + (c & 1) * 16384;
        const uint32_t bBase = sb + M_OFF_B + (c & 1) * 16384;
#pragma unroll
        for (int kk = 0; kk < 4; kk++) {
            uint32_t a[2][4];
#pragma unroll
            for (int mi = 0; mi < 2; mi++) {
                uint32_t off = (rowA + mi * 16) * 128 + kk * 32 + kselA;
                ldsm4(a[mi][0], a[mi][1], a[mi][2], a[mi][3], aBase + sw128(off));
            }
            uint32_t bf[4][4];
#pragma unroll
            for (int n2 = 0; n2 < 4; n2++) {
                uint32_t off = (rowB + n2 * 16) * 128 + kk * 32 + kselB;
                ldsm4(bf[n2][0], bf[n2][1], bf[n2][2], bf[n2][3], bBase + sw128(off));
            }
#pragma unroll
            for (int mi = 0; mi < 2; mi++)
#pragma unroll
                for (int nn = 0; nn < 8; nn++) {
                    uint32_t b0 = bf[nn >> 1][(nn & 1) * 2];
                    uint32_t b1 = bf[nn >> 1][(nn & 1) * 2 + 1];
                    mma_bf16(cacc[mi][nn], a[mi][0], a[mi][1], a[mi][2], a[mi][3], b0, b1);
                }
        }
    }

    // epilogue: tanh(acc + bm) -> g_Mbf
#pragma unroll
    for (int mi = 0; mi < 2; mi++) {
        int r0 = wm * 32 + mi * 16 + (lane >> 2);
        int r1 = r0 + 8;
#pragma unroll
        for (int nn = 0; nn < 8; nn++) {
            int col = wn * 64 + nn * 8 + 2 * (lane & 3);
            const float* cc = cacc[mi][nn];
#pragma unroll
            for (int e = 0; e < 2; e++) {
                int n = nbase + col + e;
                float b = bm[n];
                g_Mbf[r0 * D + n] = __float2bfloat16(fast_tanh(cc[e] + b));
                g_Mbf[r1 * D + n] = __float2bfloat16(fast_tanh(cc[2 + e] + b));
            }
        }
    }
}

// ---------------- K5: logits via mma.sync bf16 (B pre-converted) ----------------
#define OFF_BO 0
#define OFF_TGT 512
#define OFF_SEXP 1024
#define OFF_B 2048
#define OFF_A (2048 + 2 * 16384)
#define LOGITS_SMEM (OFF_A + 8 * 16384)

__global__ void __launch_bounds__(256, 1) logits_kernel(const float* __restrict__ bo,
                                                        const int* __restrict__ enums) {
    extern __shared__ char smem[];
    const uint32_t sb = smem_u32(smem);
    const int tid = threadIdx.x;
    const int lane = tid & 31;
    const int wm = (tid >> 5) & 3;
    const int wn = tid >> 7;
    const int vb = blockIdx.x * 128;

    float* bo_s = (float*)(smem + OFF_BO);
    int* tgt_s = (int*)(smem + OFF_TGT);
    float* sexp_s = (float*)(smem + OFF_SEXP);

    for (int i = tid; i < 128; i += 256) {
        int v = vb + i;
        bo_s[i] = (v < VOCAB) ? bo[v] : 0.f;
        tgt_s[i] = enums[i + 1];
        sexp_s[i] = 0.f;
    }

    for (int i = tid * 8; i < TGT_STEPS * D; i += 256 * 8) {
        int t = i >> 9, k = i & 511;
        uint4 v = *(const uint4*)&g_Mbf[i];
        int c = k >> 6, kk = k & 63;
        uint32_t sw = sw128(t * 128 + kk * 2);
        *(uint4*)(smem + OFF_A + c * 16384 + sw) = v;
    }

    const int rowl = tid >> 1, q = tid & 1;
    const bool vok = (vb + rowl) < VOCAB;
    const uint4* wsrc = (const uint4*)&g_Wobf[(size_t)(vb + rowl) * D];
    const uint4 Z = make_uint4(0u, 0u, 0u, 0u);

    uint4 pf[4];
#pragma unroll
    for (int j = 0; j < 4; j++) pf[j] = vok ? wsrc[q * 4 + j] : Z;

    float cacc[2][8][4];
#pragma unroll
    for (int mi = 0; mi < 2; mi++)
#pragma unroll
        for (int nn = 0; nn < 8; nn++)
#pragma unroll
            for (int e = 0; e < 4; e++) cacc[mi][nn][e] = 0.f;

    const int rowA = wm * 32 + (lane & 15);
    const int kselA = (lane >> 4) << 4;
    const int rowB = wn * 64 + (lane & 7) + ((lane & 16) >> 1);
    const int kselB = (lane & 8) << 1;

#pragma unroll 1
    for (int c = 0; c < 8; c++) {
        char* bbuf = smem + OFF_B + (c & 1) * 16384;
#pragma unroll
        for (int j = 0; j < 4; j++) {
            uint32_t sw = sw128(rowl * 128 + q * 64 + j * 16);
            *(uint4*)(bbuf + sw) = pf[j];
        }
        __syncthreads();
        if (c < 7) {
#pragma unroll
            for (int j = 0; j < 4; j++)
                pf[j] = vok ? wsrc[(c + 1) * 8 + q * 4 + j] : Z;
        }
        const uint32_t aBase = sb + OFF_A + c * 16384;
        const uint32_t bBase = sb + OFF_B + (c & 1) * 16384;
#pragma unroll
        for (int kk = 0; kk < 4; kk++) {
            uint32_t a[2][4];
#pragma unroll
            for (int mi = 0; mi < 2; mi++) {
                uint32_t off = (rowA + mi * 16) * 128 + kk * 32 + kselA;
                ldsm4(a[mi][0], a[mi][1], a[mi][2], a[mi][3], aBase + sw128(off));
            }
            uint32_t bf[4][4];
#pragma unroll
            for (int n2 = 0; n2 < 4; n2++) {
                uint32_t off = (rowB + n2 * 16) * 128 + kk * 32 + kselB;
                ldsm4(bf[n2][0], bf[n2][1], bf[n2][2], bf[n2][3], bBase + sw128(off));
            }
#pragma unroll
            for (int mi = 0; mi < 2; mi++)
#pragma unroll
                for (int nn = 0; nn < 8; nn++) {
                    uint32_t b0 = bf[nn >> 1][(nn & 1) * 2];
                    uint32_t b1 = bf[nn >> 1][(nn & 1) * 2 + 1];
                    mma_bf16(cacc[mi][nn], a[mi][0], a[mi][1], a[mi][2], a[mi][3], b0, b1);
                }
        }
    }

#pragma unroll
    for (int mi = 0; mi < 2; mi++) {
        int r0 = wm * 32 + mi * 16 + (lane >> 2);
        int r1 = r0 + 8;
        float s0 = 0.f, s1 = 0.f;
#pragma unroll
        for (int nn = 0; nn < 8; nn++) {
            int col = wn * 64 + nn * 8 + 2 * (lane & 3);
            const float* cc = cacc[mi][nn];
#pragma unroll
            for (int e = 0; e < 2; e++) {
                int v = vb + col + e;
                if (v < VOCAB) {
                    float lg0 = cc[e] + bo_s[col + e];
                    float lg1 = cc[2 + e] + bo_s[col + e];
                    s0 += __expf(lg0);
                    s1 += __expf(lg1);
                    if (v == tgt_s[r0]) g_picked[r0] = lg0;
                    if (v == tgt_s[r1]) g_picked[r1] = lg1;
                }
            }
        }
        s0 += __shfl_xor_sync(0xffffffffu, s0, 1);
        s0 += __shfl_xor_sync(0xffffffffu, s0, 2);
        s1 += __shfl_xor_sync(0xffffffffu, s1, 1);
        s1 += __shfl_xor_sync(0xffffffffu, s1, 2);
        if ((lane & 3) == 0) {
            atomicAdd(&sexp_s[r0], s0);
            atomicAdd(&sexp_s[r1], s1);
        }
    }
    __syncthreads();
    for (int i = tid; i < 128; i += 256) atomicAdd(&g_sumexp[i], sexp_s[i]);
}

// ---------------- K6: final reduction ----------------
__global__ void finalize_kernel(float* __restrict__ out) {
    int tid = threadIdx.x;
    float v = g_picked[tid] - logf(g_sumexp[tid]);
    __shared__ float red[4];
    int w = tid >> 5, l = tid & 31;
#pragma unroll
    for (int o = 16; o; o >>= 1) v += __shfl_xor_sync(0xffffffffu, v, o);
    if (l == 0) red[w] = v;
    __syncthreads();
    if (tid == 0) out[0] = red[0] + red[1] + red[2] + red[3];
}

// ---------------- launch ----------------
extern "C" void kernel_launch(void* const* d_in, const int* in_sizes, int n_in,
                              void* d_out, int out_size) {
    const int* fnums = (const int*)d_in[0];
    const int* enums = (const int*)d_in[1];
    const float* emb_f = (const float*)d_in[2];
    const float* Wih_e = (const float*)d_in[3];
    const float* Whh_e = (const float*)d_in[4];
    const float* b_e = (const float*)d_in[5];
    const float* h0_e = (const float*)d_in[6];
    const float* emb_d = (const float*)d_in[7];
    const float* Wih_d = (const float*)d_in[8];
    const float* Whh_d = (const float*)d_in[9];
    const float* b_d = (const float*)d_in[10];
    const float* h0_d = (const float*)d_in[11];
    const float* Wm = (const float*)d_in[12];
    const float* bm = (const float*)d_in[13];
    const float* Wo = (const float*)d_in[14];
    const float* bo = (const float*)d_in[15];
    float* out = (float*)d_out;

    static int inited = 0;
    static float *p_xpre, *p_epre;
    if (!inited) {
        cudaFuncSetAttribute(logits_kernel, cudaFuncAttributeMaxDynamicSharedMemorySize,
                             LOGITS_SMEM);
        cudaFuncSetAttribute(m_hmma_kernel, cudaFuncAttributeMaxDynamicSharedMemorySize,
                             M_SMEM);
        cudaGetSymbolAddress((void**)&p_xpre, g_xpre);
        cudaGetSymbolAddress((void**)&p_epre, g_epre);
        inited = 1;
    }

    // pre-activations: encoder (z=0) + decoder (z=1) concurrently; 128 CTAs
    gemm_kernel<<<dim3(8, 8, 2), 256>>>(emb_f, fnums, Wih_e, b_e,
                                        emb_d, enums, Wih_d, b_d,
                                        p_xpre, p_epre, D);
    // recur (y=0,1) + Wo/Wm->bf16 conversion (y=2..) overlapped in one launch
    recur_kernel<<<dim3(8, 2 + CONV_YS), 512>>>(Whh_e, Whh_d, h0_e, h0_d, Wo, Wm);
    // fused attention: scores + softmax + context + CHbf assembly (+ sumexp init)
    attn_kernel<<<128, 256>>>();
    // M = tanh(CHbf @ Wmbf^T + bm) -> bf16, tensor cores
    m_hmma_kernel<<<4, 256, M_SMEM>>>(bm);
    logits_kernel<<<(VOCAB + 127) / 128, 256, LOGITS_SMEM>>>(bo, enums);
    finalize_kernel<<<1, 128>>>(out);
}

// round 14
// speedup vs baseline: 1.5626x; 1.0190x over previous
#include <cuda_runtime.h>
#include <cuda_bf16.h>
#include <cstdint>

#define D 512
#define SRC 128
#define TGT_STEPS 128
#define VOCAB 50000

typedef unsigned long long u64;

// ---------------- scratch (device globals; no allocation allowed) ----------------
__device__ __align__(16) float g_xpre[SRC * D];
__device__ __align__(16) float g_epre[TGT_STEPS * D];
__device__ __align__(16) float g_fencs[SRC * D];
__device__ __align__(16) float g_H[TGT_STEPS * D];
__device__ __align__(16) __nv_bfloat16 g_CHbf[TGT_STEPS * 2 * D];
__device__ __align__(16) __nv_bfloat16 g_Mbf[TGT_STEPS * D];
__device__ __align__(16) __nv_bfloat16 g_Wmbf[D * 2 * D];
__device__ __align__(16) __nv_bfloat16 g_Wobf[VOCAB * D];
__device__ float g_sumexp[TGT_STEPS];
__device__ float g_picked[TGT_STEPS];

// ---------------- helpers ----------------
__device__ __forceinline__ u64 pk2(float x, float y) {
    u64 r;
    asm("mov.b64 %0, {%1, %2};" : "=l"(r) : "f"(x), "f"(y));
    return r;
}
__device__ __forceinline__ float2 upk2(u64 v) {
    float2 r;
    asm("mov.b64 {%0, %1}, %2;" : "=f"(r.x), "=f"(r.y) : "l"(v));
    return r;
}
__device__ __forceinline__ void fma2(u64& d, u64 a, u64 b) {
    asm volatile("fma.rn.f32x2 %0, %1, %2, %0;" : "+l"(d) : "l"(a), "l"(b));
}
__device__ __forceinline__ uint32_t smem_u32(const void* p) {
    uint32_t a;
    asm("{ .reg .u64 t; cvta.to.shared.u64 t, %1; cvt.u32.u64 %0, t; }" : "=r"(a) : "l"(p));
    return a;
}
__device__ __forceinline__ uint32_t mapa_u32(uint32_t saddr, uint32_t rank) {
    uint32_t r;
    asm volatile("mapa.shared::cluster.u32 %0, %1, %2;" : "=r"(r) : "r"(saddr), "r"(rank));
    return r;
}
__device__ __forceinline__ void st_async_f32(uint32_t raddr, uint32_t rmbar, float v) {
    asm volatile(
        "st.async.shared::cluster.mbarrier::complete_tx::bytes.b32 [%0], %1, [%2];"
        :: "r"(raddr), "r"(__float_as_uint(v)), "r"(rmbar) : "memory");
}
__device__ __forceinline__ void mbar_init(uint32_t addr, uint32_t cnt) {
    asm volatile("mbarrier.init.shared.b64 [%0], %1;" :: "r"(addr), "r"(cnt) : "memory");
}
__device__ __forceinline__ void mbar_expect_tx(uint32_t addr, uint32_t bytes) {
    asm volatile("mbarrier.arrive.expect_tx.shared.b64 _, [%0], %1;"
                 :: "r"(addr), "r"(bytes) : "memory");
}
__device__ __forceinline__ void mbar_wait(uint32_t addr, int parity) {
    asm volatile(
        "{\n\t.reg .pred P;\n\t"
        "W_%=:\n\t"
        "mbarrier.try_wait.parity.acquire.cta.shared::cta.b64 P, [%0], %1;\n\t"
        "@!P bra W_%=;\n\t}"
        :: "r"(addr), "r"(parity) : "memory");
}
__device__ __forceinline__ void ldsm4(uint32_t& r0, uint32_t& r1, uint32_t& r2, uint32_t& r3,
                                      uint32_t addr) {
    asm volatile("ldmatrix.sync.aligned.m8n8.x4.shared.b16 {%0,%1,%2,%3}, [%4];"
                 : "=r"(r0), "=r"(r1), "=r"(r2), "=r"(r3) : "r"(addr));
}
__device__ __forceinline__ void mma_bf16(float* c, uint32_t a0, uint32_t a1, uint32_t a2,
                                         uint32_t a3, uint32_t b0, uint32_t b1) {
    asm volatile(
        "mma.sync.aligned.m16n8k16.row.col.f32.bf16.bf16.f32 "
        "{%0,%1,%2,%3}, {%4,%5,%6,%7}, {%8,%9}, {%0,%1,%2,%3};"
        : "+f"(c[0]), "+f"(c[1]), "+f"(c[2]), "+f"(c[3])
        : "r"(a0), "r"(a1), "r"(a2), "r"(a3), "r"(b0), "r"(b1));
}
__device__ __forceinline__ uint32_t sw128(uint32_t off) { return off ^ ((off >> 3) & 0x70); }
__device__ __forceinline__ float fast_tanh(float x) {
    float e = __expf(2.f * x);
    return __fdividef(e - 1.f, e + 1.f);
}

// ---------------- K1: pre-activation SGEMM (fp32 kept for recurrence precision) ----
__global__ void __launch_bounds__(256) gemm_kernel(
    const float* __restrict__ X0, const int* __restrict__ idx0,
    const float* __restrict__ W0, const float* __restrict__ b0,
    const float* __restrict__ X1, const int* __restrict__ idx1,
    const float* __restrict__ W1, const float* __restrict__ b1,
    float* __restrict__ oF0, float* __restrict__ oF1,
    int K) {
    const int z = blockIdx.z;
    const float* X = z ? X1 : X0;
    const int* idx = z ? idx1 : idx0;
    const float* W = z ? W1 : W0;
    const float* bias = z ? b1 : b0;
    float* outF = z ? oF1 : oF0;

    __shared__ __align__(16) float Xs[64][17];
    __shared__ __align__(16) float Ws[64][68];
    __shared__ int roff[16];

    const int tid = threadIdx.x;
    const int tx = tid & 15, ty = tid >> 4;
    const int mbase = blockIdx.y * 16;
    const int nbase = blockIdx.x * 64;

    if (tid < 16) {
        int m = mbase + tid;
        roff[tid] = (idx ? idx[m] : m) * K;
    }
    __syncthreads();

    u64 acc[2] = {0ull, 0ull};

    for (int kt = 0; kt < K; kt += 64) {
        {
            int m = tid >> 4, kq = tid & 15;
            float4 v = *(const float4*)&X[roff[m] + kt + kq * 4];
            Xs[kq * 4 + 0][m] = v.x;
            Xs[kq * 4 + 1][m] = v.y;
            Xs[kq * 4 + 2][m] = v.z;
            Xs[kq * 4 + 3][m] = v.w;
        }
#pragma unroll
        for (int j = 0; j < 4; j++) {
            int id = tid + 256 * j;
            int n = id >> 4, kq = id & 15;
            float4 v = *(const float4*)&W[(size_t)(nbase + n) * K + kt + kq * 4];
            Ws[kq * 4 + 0][n] = v.x;
            Ws[kq * 4 + 1][n] = v.y;
            Ws[kq * 4 + 2][n] = v.z;
            Ws[kq * 4 + 3][n] = v.w;
        }
        __syncthreads();
#pragma unroll
        for (int k = 0; k < 64; k++) {
            float a = Xs[k][ty];
            float4 b = *(const float4*)&Ws[k][tx * 4];
            u64 aa = pk2(a, a);
            fma2(acc[0], aa, pk2(b.x, b.y));
            fma2(acc[1], aa, pk2(b.z, b.w));
        }
        __syncthreads();
    }
    {
        int m = mbase + ty;
        float2 v0 = upk2(acc[0]), v1 = upk2(acc[1]);
        float o[4] = {v0.x, v0.y, v1.x, v1.y};
#pragma unroll
        for (int i = 0; i < 4; i++) {
            int n = nbase + tx * 4 + i;
            outF[m * D + n] = o[i] + bias[n];
        }
    }
}

// ---------------- K2: recurrences (y=0,1: 8-CTA clusters, mbarrier pipeline)
//                    + Wo/Wm->bf16 convert (y>=2) ----------------
#define CONV_YS 6
__global__ void __cluster_dims__(8, 1, 1) __launch_bounds__(512, 1)
recur_kernel(const float* __restrict__ Whh_e, const float* __restrict__ Whh_d,
             const float* __restrict__ h0_e, const float* __restrict__ h0_d,
             const float* __restrict__ Wo, const float* __restrict__ Wm) {
    const int tid = threadIdx.x;

    if (blockIdx.y >= 2) {
        const size_t gt = (size_t)((blockIdx.y - 2) * 8 + blockIdx.x) * 512 + tid;
        const size_t stride = (size_t)CONV_YS * 8 * 512;
        {
            const size_t n4 = (size_t)VOCAB * D / 4;
            const float4* src = (const float4*)Wo;
            uint2* dst = (uint2*)g_Wobf;
            for (size_t i = gt; i < n4; i += stride) {
                float4 f = src[i];
                __nv_bfloat162 lo = __float22bfloat162_rn(make_float2(f.x, f.y));
                __nv_bfloat162 hi = __float22bfloat162_rn(make_float2(f.z, f.w));
                uint2 u;
                u.x = *(uint32_t*)&lo;
                u.y = *(uint32_t*)&hi;
                dst[i] = u;
            }
        }
        {
            const size_t n4 = (size_t)D * 2 * D / 4;
            const float4* src = (const float4*)Wm;
            uint2* dst = (uint2*)g_Wmbf;
            for (size_t i = gt; i < n4; i += stride) {
                float4 f = src[i];
                __nv_bfloat162 lo = __float22bfloat162_rn(make_float2(f.x, f.y));
                __nv_bfloat162 hi = __float22bfloat162_rn(make_float2(f.z, f.w));
                uint2 u;
                u.x = *(uint32_t*)&lo;
                u.y = *(uint32_t*)&hi;
                dst[i] = u;
            }
        }
        return;
    }

    const int ph = blockIdx.y;
    const float* W = ph ? Whh_d : Whh_e;
    const float* h0 = ph ? h0_d : h0_e;
    const float* pre = ph ? g_epre : g_xpre;
    float* outg = ph ? g_H : g_fencs;

    __shared__ __align__(16) float hbuf[3][D];
    __shared__ __align__(8) u64 mbar[3];
    __shared__ float pre_s[128 * 64];

    const int rl = tid >> 3;
    const int sub = tid & 7;
    const uint32_t rank = blockIdx.x;
    const int row = rank * 64 + rl;

    u64 wv2[32];
#pragma unroll
    for (int j = 0; j < 16; j++) {
        ulonglong2 t = *(const ulonglong2*)&W[row * D + j * 32 + sub * 4];
        wv2[2 * j] = t.x;
        wv2[2 * j + 1] = t.y;
    }

    for (int i = tid; i < 128 * 64; i += 512) {
        int t = i >> 6, r = i & 63;
        pre_s[i] = pre[t * D + rank * 64 + r];
    }
    hbuf[0][tid] = h0[tid];
    if (tid < 3) mbar_init(smem_u32(&mbar[tid]), 1);
    __syncthreads();
    asm volatile("barrier.cluster.arrive.aligned;" ::: "memory");
    asm volatile("barrier.cluster.wait.aligned;" ::: "memory");

    const uint32_t mb_local = smem_u32(&mbar[0]);
    const uint32_t dst_remote0 = mapa_u32(smem_u32(&hbuf[0][row]), (uint32_t)sub);
    const uint32_t mb_remote0 = mapa_u32(mb_local, (uint32_t)sub);

#pragma unroll 1
    for (int t = 0; t < 128; t++) {
        const int b = t % 3;
        const int bn = (t + 1) % 3;
        if (tid == 0 && t < 127) mbar_expect_tx(mb_local + bn * 8, (uint32_t)(D * 4));
        if (t > 0) mbar_wait(mb_local + b * 8, ((t - 1) / 3) & 1);

        const float* hp = hbuf[b];
        u64 A0 = 0ull, A1 = 0ull;
#pragma unroll
        for (int j = 0; j < 16; j++) {
            ulonglong2 hv = *(const ulonglong2*)&hp[j * 32 + sub * 4];
            fma2(A0, wv2[2 * j], hv.x);
            fma2(A1, wv2[2 * j + 1], hv.y);
        }
        float2 f0 = upk2(A0), f1 = upk2(A1);
        float acc = (f0.x + f0.y) + (f1.x + f1.y);
#pragma unroll
        for (int o = 4; o; o >>= 1) acc += __shfl_xor_sync(0xffffffffu, acc, o);
        float h = fast_tanh(acc + pre_s[t * 64 + rl]);
        if (t < 127) st_async_f32(dst_remote0 + bn * (D * 4), mb_remote0 + bn * 8, h);
        if (sub == 0) outg[t * D + row] = h;
    }
    asm volatile("barrier.cluster.arrive.aligned;" ::: "memory");
    asm volatile("barrier.cluster.wait.aligned;" ::: "memory");
}

// ---------------- K3: fused attention per t -> CH in bf16 ----------------
__global__ void __launch_bounds__(256) attn_kernel() {
    int t = blockIdx.x;
    int tid = threadIdx.x, w = tid >> 5, l = tid & 31;
    __shared__ __align__(16) float hs[D];
    __shared__ float al[SRC];
    __shared__ float red[16];
    __shared__ __align__(16) float cpart[D];

    if (blockIdx.x == 0 && tid < TGT_STEPS) g_sumexp[tid] = 0.f;

    *(float2*)&hs[tid * 2] = *(const float2*)&g_H[t * D + tid * 2];
    __syncthreads();

#pragma unroll 1
    for (int si = 0; si < 16; si++) {
        int s2 = w * 16 + si;
        float acc = 0.f;
#pragma unroll
        for (int j = 0; j < 4; j++) {
            float4 fv = *(const float4*)&g_fencs[s2 * D + l * 4 + j * 128];
            float4 hv = *(const float4*)&hs[l * 4 + j * 128];
            acc += fv.x * hv.x + fv.y * hv.y + fv.z * hv.z + fv.w * hv.w;
        }
#pragma unroll
        for (int o = 16; o; o >>= 1) acc += __shfl_xor_sync(0xffffffffu, acc, o);
        if (l == 0) al[s2] = acc;
    }
    __syncthreads();

    float v = (tid < SRC) ? al[tid] : -1e30f;
    float mx = v;
#pragma unroll
    for (int o = 16; o; o >>= 1) mx = fmaxf(mx, __shfl_xor_sync(0xffffffffu, mx, o));
    if (l == 0) red[w] = mx;
    __syncthreads();
    mx = fmaxf(fmaxf(red[0], red[1]), fmaxf(red[2], red[3]));
    float e = (tid < SRC) ? __expf(v - mx) : 0.f;
    float sm = e;
#pragma unroll
    for (int o = 16; o; o >>= 1) sm += __shfl_xor_sync(0xffffffffu, sm, o);
    if (l == 0) red[8 + w] = sm;
    __syncthreads();
    sm = red[8] + red[9] + red[10] + red[11];
    if (tid < SRC) al[tid] = e / sm;
    __syncthreads();

    const int d4 = tid & 127, shalf = tid >> 7;
    const float4* f4 = (const float4*)g_fencs;
    float4 c = make_float4(0.f, 0.f, 0.f, 0.f);
    int s0 = shalf * 64;
#pragma unroll 8
    for (int s = s0; s < s0 + 64; s++) {
        float a = al[s];
        float4 fv = f4[s * (D / 4) + d4];
        c.x = fmaf(a, fv.x, c.x);
        c.y = fmaf(a, fv.y, c.y);
        c.z = fmaf(a, fv.z, c.z);
        c.w = fmaf(a, fv.w, c.w);
    }
    if (shalf == 1) *(float4*)&cpart[d4 * 4] = c;
    __syncthreads();
    if (shalf == 0) {
        float4 p = *(const float4*)&cpart[d4 * 4];
        c.x += p.x; c.y += p.y; c.z += p.z; c.w += p.w;
        __nv_bfloat162 lo = __float22bfloat162_rn(make_float2(c.x, c.y));
        __nv_bfloat162 hi = __float22bfloat162_rn(make_float2(c.z, c.w));
        uint2 u;
        u.x = *(uint32_t*)&lo;
        u.y = *(uint32_t*)&hi;
        *(uint2*)&g_CHbf[t * 2 * D + d4 * 4] = u;
    }
    {
        float2 hv = *(const float2*)&hs[tid * 2];
        __nv_bfloat162 hb = __float22bfloat162_rn(hv);
        *(uint32_t*)&g_CHbf[t * 2 * D + D + tid * 2] = *(uint32_t*)&hb;
    }
}

// ---------------- K4: M = tanh(CHbf @ Wmbf^T + bm) via mma.sync bf16 ----------------
// grid 8 CTAs (N=64/CTA), 256 threads = 8 warps along M (16 rows each).
// K=1024 in 16 double-buffered chunks of 64.
#define M_OFF_B 0
#define M_OFF_A (2 * 8192)
#define M_SMEM (M_OFF_A + 2 * 16384)

__global__ void __launch_bounds__(256, 1) m_hmma_kernel(const float* __restrict__ bm) {
    extern __shared__ char smem[];
    const uint32_t sb = smem_u32(smem);
    const int tid = threadIdx.x;
    const int lane = tid & 31;
    const int w = tid >> 5;          // 8 warps, each owns 16 M-rows
    const int nbase = blockIdx.x * 64;

    // A loader: thread (rowl 0..127, q 0..1), 32 bf16 = 4 uint4 per chunk
    const int rowl = tid >> 1, q = tid & 1;
    const uint4* asrc = (const uint4*)&g_CHbf[(size_t)rowl * 2 * D + q * 32];
    // B loader: thread (rb 0..63, qb 0..3), 16 bf16 = 2 uint4 per chunk
    const int rb = tid & 63, qb = tid >> 6;
    const uint4* bsrc = (const uint4*)&g_Wmbf[(size_t)(nbase + rb) * 2 * D + qb * 16];

    uint4 pfa[4], pfb[2];
#pragma unroll
    for (int j = 0; j < 4; j++) pfa[j] = asrc[j];
#pragma unroll
    for (int j = 0; j < 2; j++) pfb[j] = bsrc[j];

    float cacc[8][4];
#pragma unroll
    for (int nn = 0; nn < 8; nn++)
#pragma unroll
        for (int e = 0; e < 4; e++) cacc[nn][e] = 0.f;

    const int rowA = w * 16 + (lane & 15);
    const int kselA = (lane >> 4) << 4;
    const int rowB = (lane & 7) + ((lane & 16) >> 1);
    const int kselB = (lane & 8) << 1;

#pragma unroll 1
    for (int c = 0; c < 16; c++) {
        char* abuf = smem + M_OFF_A + (c & 1) * 16384;
        char* bbuf = smem + M_OFF_B + (c & 1) * 8192;
#pragma unroll
        for (int j = 0; j < 4; j++) {
            uint32_t sw = sw128(rowl * 128 + q * 64 + j * 16);
            *(uint4*)(abuf + sw) = pfa[j];
        }
#pragma unroll
        for (int j = 0; j < 2; j++) {
            uint32_t sw = sw128(rb * 128 + qb * 32 + j * 16);
            *(uint4*)(bbuf + sw) = pfb[j];
        }
        __syncthreads();
        if (c < 15) {
#pragma unroll
            for (int j = 0; j < 4; j++) pfa[j] = asrc[(c + 1) * 8 + j];
#pragma unroll
            for (int j = 0; j < 2; j++) pfb[j] = bsrc[(c + 1) * 8 + j];
        }
        const uint32_t aBase = sb + M_OFF_A + (c & 1) * 16384;
        const uint32_t bBase = sb + M_OFF_B + (c & 1) * 8192;
#pragma unroll
        for (int kk = 0; kk < 4; kk++) {
            uint32_t a[4];
            {
                uint32_t off = rowA * 128 + kk * 32 + kselA;
                ldsm4(a[0], a[1], a[2], a[3], aBase + sw128(off));
            }
            uint32_t bf[4][4];
#pragma unroll
            for (int n2 = 0; n2 < 4; n2++) {
                uint32_t off = (rowB + n2 * 16) * 128 + kk * 32 + kselB;
                ldsm4(bf[n2][0], bf[n2][1], bf[n2][2], bf[n2][3], bBase + sw128(off));
            }
#pragma unroll
            for (int nn = 0; nn < 8; nn++) {
                uint32_t b0 = bf[nn >> 1][(nn & 1) * 2];
                uint32_t b1 = bf[nn >> 1][(nn & 1) * 2 + 1];
                mma_bf16(cacc[nn], a[0], a[1], a[2], a[3], b0, b1);
            }
        }
        __syncthreads();
    }

    // epilogue: tanh(acc + bm) -> g_Mbf; rows r0 = w*16 + lane>>2, r1 = r0+8
    {
        int r0 = w * 16 + (lane >> 2);
        int r1 = r0 + 8;
#pragma unroll
        for (int nn = 0; nn < 8; nn++) {
            int col = nn * 8 + 2 * (lane & 3);
            const float* cc = cacc[nn];
#pragma unroll
            for (int e = 0; e < 2; e++) {
                int n = nbase + col + e;
                float b = bm[n];
                g_Mbf[r0 * D + n] = __float2bfloat16(fast_tanh(cc[e] + b));
                g_Mbf[r1 * D + n] = __float2bfloat16(fast_tanh(cc[2 + e] + b));
            }
        }
    }
}

// ---------------- K5: logits via mma.sync bf16 (B pre-converted) ----------------
#define OFF_BO 0
#define OFF_TGT 512
#define OFF_SEXP 1024
#define OFF_B 2048
#define OFF_A (2048 + 2 * 16384)
#define LOGITS_SMEM (OFF_A + 8 * 16384)

__global__ void __launch_bounds__(256, 1) logits_kernel(const float* __restrict__ bo,
                                                        const int* __restrict__ enums) {
    extern __shared__ char smem[];
    const uint32_t sb = smem_u32(smem);
    const int tid = threadIdx.x;
    const int lane = tid & 31;
    const int wm = (tid >> 5) & 3;
    const int wn = tid >> 7;
    const int vb = blockIdx.x * 128;

    float* bo_s = (float*)(smem + OFF_BO);
    int* tgt_s = (int*)(smem + OFF_TGT);
    float* sexp_s = (float*)(smem + OFF_SEXP);

    for (int i = tid; i < 128; i += 256) {
        int v = vb + i;
        bo_s[i] = (v < VOCAB) ? bo[v] : 0.f;
        tgt_s[i] = enums[i + 1];
        sexp_s[i] = 0.f;
    }

    for (int i = tid * 8; i < TGT_STEPS * D; i += 256 * 8) {
        int t = i >> 9, k = i & 511;
        uint4 v = *(const uint4*)&g_Mbf[i];
        int c = k >> 6, kk = k & 63;
        uint32_t sw = sw128(t * 128 + kk * 2);
        *(uint4*)(smem + OFF_A + c * 16384 + sw) = v;
    }

    const int rowl = tid >> 1, q = tid & 1;
    const bool vok = (vb + rowl) < VOCAB;
    const uint4* wsrc = (const uint4*)&g_Wobf[(size_t)(vb + rowl) * D];
    const uint4 Z = make_uint4(0u, 0u, 0u, 0u);

    uint4 pf[4];
#pragma unroll
    for (int j = 0; j < 4; j++) pf[j] = vok ? wsrc[q * 4 + j] : Z;

    float cacc[2][8][4];
#pragma unroll
    for (int mi = 0; mi < 2; mi++)
#pragma unroll
        for (int nn = 0; nn < 8; nn++)
#pragma unroll
            for (int e = 0; e < 4; e++) cacc[mi][nn][e] = 0.f;

    const int rowA = wm * 32 + (lane & 15);
    const int kselA = (lane >> 4) << 4;
    const int rowB = wn * 64 + (lane & 7) + ((lane & 16) >> 1);
    const int kselB = (lane & 8) << 1;

#pragma unroll 1
    for (int c = 0; c < 8; c++) {
        char* bbuf = smem + OFF_B + (c & 1) * 16384;
#pragma unroll
        for (int j = 0; j < 4; j++) {
            uint32_t sw = sw128(rowl * 128 + q * 64 + j * 16);
            *(uint4*)(bbuf + sw) = pf[j];
        }
        __syncthreads();
        if (c < 7) {
#pragma unroll
            for (int j = 0; j < 4; j++)
                pf[j] = vok ? wsrc[(c + 1) * 8 + q * 4 + j] : Z;
        }
        const uint32_t aBase = sb + OFF_A + c * 16384;
        const uint32_t bBase = sb + OFF_B + (c & 1) * 16384;
#pragma unroll
        for (int kk = 0; kk < 4; kk++) {
            uint32_t a[2][4];
#pragma unroll
            for (int mi = 0; mi < 2; mi++) {
                uint32_t off = (rowA + mi * 16) * 128 + kk * 32 + kselA;
                ldsm4(a[mi][0], a[mi][1], a[mi][2], a[mi][3], aBase + sw128(off));
            }
            uint32_t bf[4][4];
#pragma unroll
            for (int n2 = 0; n2 < 4; n2++) {
                uint32_t off = (rowB + n2 * 16) * 128 + kk * 32 + kselB;
                ldsm4(bf[n2][0], bf[n2][1], bf[n2][2], bf[n2][3], bBase + sw128(off));
            }
#pragma unroll
            for (int mi = 0; mi < 2; mi++)
#pragma unroll
                for (int nn = 0; nn < 8; nn++) {
                    uint32_t b0 = bf[nn >> 1][(nn & 1) * 2];
                    uint32_t b1 = bf[nn >> 1][(nn & 1) * 2 + 1];
                    mma_bf16(cacc[mi][nn], a[mi][0], a[mi][1], a[mi][2], a[mi][3], b0, b1);
                }
        }
    }

#pragma unroll
    for (int mi = 0; mi < 2; mi++) {
        int r0 = wm * 32 + mi * 16 + (lane >> 2);
        int r1 = r0 + 8;
        float s0 = 0.f, s1 = 0.f;
#pragma unroll
        for (int nn = 0; nn < 8; nn++) {
            int col = wn * 64 + nn * 8 + 2 * (lane & 3);
            const float* cc = cacc[mi][nn];
#pragma unroll
            for (int e = 0; e < 2; e++) {
                int v = vb + col + e;
                if (v < VOCAB) {
                    float lg0 = cc[e] + bo_s[col + e];
                    float lg1 = cc[2 + e] + bo_s[col + e];
                    s0 += __expf(lg0);
                    s1 += __expf(lg1);
                    if (v == tgt_s[r0]) g_picked[r0] = lg0;
                    if (v == tgt_s[r1]) g_picked[r1] = lg1;
                }
            }
        }
        s0 += __shfl_xor_sync(0xffffffffu, s0, 1);
        s0 += __shfl_xor_sync(0xffffffffu, s0, 2);
        s1 += __shfl_xor_sync(0xffffffffu, s1, 1);
        s1 += __shfl_xor_sync(0xffffffffu, s1, 2);
        if ((lane & 3) == 0) {
            atomicAdd(&sexp_s[r0], s0);
            atomicAdd(&sexp_s[r1], s1);
        }
    }
    __syncthreads();
    for (int i = tid; i < 128; i += 256) atomicAdd(&g_sumexp[i], sexp_s[i]);
}

// ---------------- K6: final reduction ----------------
__global__ void finalize_kernel(float* __restrict__ out) {
    int tid = threadIdx.x;
    float v = g_picked[tid] - logf(g_sumexp[tid]);
    __shared__ float red[4];
    int w = tid >> 5, l = tid & 31;
#pragma unroll
    for (int o = 16; o; o >>= 1) v += __shfl_xor_sync(0xffffffffu, v, o);
    if (l == 0) red[w] = v;
    __syncthreads();
    if (tid == 0) out[0] = red[0] + red[1] + red[2] + red[3];
}

// ---------------- launch ----------------
extern "C" void kernel_launch(void* const* d_in, const int* in_sizes, int n_in,
                              void* d_out, int out_size) {
    const int* fnums = (const int*)d_in[0];
    const int* enums = (const int*)d_in[1];
    const float* emb_f = (const float*)d_in[2];
    const float* Wih_e = (const float*)d_in[3];
    const float* Whh_e = (const float*)d_in[4];
    const float* b_e = (const float*)d_in[5];
    const float* h0_e = (const float*)d_in[6];
    const float* emb_d = (const float*)d_in[7];
    const float* Wih_d = (const float*)d_in[8];
    const float* Whh_d = (const float*)d_in[9];
    const float* b_d = (const float*)d_in[10];
    const float* h0_d = (const float*)d_in[11];
    const float* Wm = (const float*)d_in[12];
    const float* bm = (const float*)d_in[13];
    const float* Wo = (const float*)d_in[14];
    const float* bo = (const float*)d_in[15];
    float* out = (float*)d_out;

    static int inited = 0;
    static float *p_xpre, *p_epre;
    if (!inited) {
        cudaFuncSetAttribute(logits_kernel, cudaFuncAttributeMaxDynamicSharedMemorySize,
                             LOGITS_SMEM);
        cudaFuncSetAttribute(m_hmma_kernel, cudaFuncAttributeMaxDynamicSharedMemorySize,
                             M_SMEM);
        cudaGetSymbolAddress((void**)&p_xpre, g_xpre);
        cudaGetSymbolAddress((void**)&p_epre, g_epre);
        inited = 1;
    }

    // pre-activations: encoder (z=0) + decoder (z=1) concurrently; 128 CTAs
    gemm_kernel<<<dim3(8, 8, 2), 256>>>(emb_f, fnums, Wih_e, b_e,
                                        emb_d, enums, Wih_d, b_d,
                                        p_xpre, p_epre, D);
    // recur (y=0,1) + Wo/Wm->bf16 conversion (y=2..) overlapped in one launch
    recur_kernel<<<dim3(8, 2 + CONV_YS), 512>>>(Whh_e, Whh_d, h0_e, h0_d, Wo, Wm);
    // fused attention: scores + softmax + context + CHbf assembly (+ sumexp init)
    attn_kernel<<<128, 256>>>();
    // M = tanh(CHbf @ Wmbf^T + bm) -> bf16, tensor cores (grid 8)
    m_hmma_kernel<<<8, 256, M_SMEM>>>(bm);
    logits_kernel<<<(VOCAB + 127) / 128, 256, LOGITS_SMEM>>>(bo, enums);
    finalize_kernel<<<1, 128>>>(out);
}

// round 15
// speedup vs baseline: 1.5911x; 1.0182x over previous
#include <cuda_runtime.h>
#include <cuda_bf16.h>
#include <cstdint>

#define D 512
#define SRC 128
#define TGT_STEPS 128
#define VOCAB 50000

typedef unsigned long long u64;

// ---------------- scratch (device globals; no allocation allowed) ----------------
__device__ __align__(16) float g_xpre[SRC * D];
__device__ __align__(16) float g_epre[TGT_STEPS * D];
__device__ __align__(16) float g_fencs[SRC * D];
__device__ __align__(16) float g_H[TGT_STEPS * D];
__device__ __align__(16) __nv_bfloat16 g_CHbf[TGT_STEPS * 2 * D];
__device__ __align__(16) __nv_bfloat16 g_Mbf[TGT_STEPS * D];
__device__ __align__(16) __nv_bfloat16 g_Wmbf[D * 2 * D];
__device__ __align__(16) __nv_bfloat16 g_Wobf[VOCAB * D];
__device__ float g_sumexp[TGT_STEPS];
__device__ float g_picked[TGT_STEPS];

// ---------------- helpers ----------------
__device__ __forceinline__ u64 pk2(float x, float y) {
    u64 r;
    asm("mov.b64 %0, {%1, %2};" : "=l"(r) : "f"(x), "f"(y));
    return r;
}
__device__ __forceinline__ float2 upk2(u64 v) {
    float2 r;
    asm("mov.b64 {%0, %1}, %2;" : "=f"(r.x), "=f"(r.y) : "l"(v));
    return r;
}
__device__ __forceinline__ void fma2(u64& d, u64 a, u64 b) {
    asm volatile("fma.rn.f32x2 %0, %1, %2, %0;" : "+l"(d) : "l"(a), "l"(b));
}
__device__ __forceinline__ uint32_t smem_u32(const void* p) {
    uint32_t a;
    asm("{ .reg .u64 t; cvta.to.shared.u64 t, %1; cvt.u32.u64 %0, t; }" : "=r"(a) : "l"(p));
    return a;
}
__device__ __forceinline__ uint32_t mapa_u32(uint32_t saddr, uint32_t rank) {
    uint32_t r;
    asm volatile("mapa.shared::cluster.u32 %0, %1, %2;" : "=r"(r) : "r"(saddr), "r"(rank));
    return r;
}
__device__ __forceinline__ void st_async_f32(uint32_t raddr, uint32_t rmbar, float v) {
    asm volatile(
        "st.async.shared::cluster.mbarrier::complete_tx::bytes.b32 [%0], %1, [%2];"
        :: "r"(raddr), "r"(__float_as_uint(v)), "r"(rmbar) : "memory");
}
__device__ __forceinline__ void mbar_init(uint32_t addr, uint32_t cnt) {
    asm volatile("mbarrier.init.shared.b64 [%0], %1;" :: "r"(addr), "r"(cnt) : "memory");
}
__device__ __forceinline__ void mbar_expect_tx(uint32_t addr, uint32_t bytes) {
    asm volatile("mbarrier.arrive.expect_tx.shared.b64 _, [%0], %1;"
                 :: "r"(addr), "r"(bytes) : "memory");
}
__device__ __forceinline__ void mbar_wait(uint32_t addr, int parity) {
    asm volatile(
        "{\n\t.reg .pred P;\n\t"
        "W_%=:\n\t"
        "mbarrier.try_wait.parity.acquire.cta.shared::cta.b64 P, [%0], %1;\n\t"
        "@!P bra W_%=;\n\t}"
        :: "r"(addr), "r"(parity) : "memory");
}
__device__ __forceinline__ void ldsm4(uint32_t& r0, uint32_t& r1, uint32_t& r2, uint32_t& r3,
                                      uint32_t addr) {
    asm volatile("ldmatrix.sync.aligned.m8n8.x4.shared.b16 {%0,%1,%2,%3}, [%4];"
                 : "=r"(r0), "=r"(r1), "=r"(r2), "=r"(r3) : "r"(addr));
}
__device__ __forceinline__ void mma_bf16(float* c, uint32_t a0, uint32_t a1, uint32_t a2,
                                         uint32_t a3, uint32_t b0, uint32_t b1) {
    asm volatile(
        "mma.sync.aligned.m16n8k16.row.col.f32.bf16.bf16.f32 "
        "{%0,%1,%2,%3}, {%4,%5,%6,%7}, {%8,%9}, {%0,%1,%2,%3};"
        : "+f"(c[0]), "+f"(c[1]), "+f"(c[2]), "+f"(c[3])
        : "r"(a0), "r"(a1), "r"(a2), "r"(a3), "r"(b0), "r"(b1));
}
__device__ __forceinline__ void cp16(uint32_t smem, const void* g) {
    asm volatile("cp.async.cg.shared.global [%0], [%1], 16;" :: "r"(smem), "l"(g) : "memory");
}
__device__ __forceinline__ uint32_t sw128(uint32_t off) { return off ^ ((off >> 3) & 0x70); }
__device__ __forceinline__ float fast_tanh(float x) {
    float e = __expf(2.f * x);
    return __fdividef(e - 1.f, e + 1.f);
}

// ---------------- K1: pre-activation SGEMM (fp32 kept for recurrence precision) ----
__global__ void __launch_bounds__(256) gemm_kernel(
    const float* __restrict__ X0, const int* __restrict__ idx0,
    const float* __restrict__ W0, const float* __restrict__ b0,
    const float* __restrict__ X1, const int* __restrict__ idx1,
    const float* __restrict__ W1, const float* __restrict__ b1,
    float* __restrict__ oF0, float* __restrict__ oF1,
    int K) {
    const int z = blockIdx.z;
    const float* X = z ? X1 : X0;
    const int* idx = z ? idx1 : idx0;
    const float* W = z ? W1 : W0;
    const float* bias = z ? b1 : b0;
    float* outF = z ? oF1 : oF0;

    __shared__ __align__(16) float Xs[64][17];
    __shared__ __align__(16) float Ws[64][68];
    __shared__ int roff[16];

    const int tid = threadIdx.x;
    const int tx = tid & 15, ty = tid >> 4;
    const int mbase = blockIdx.y * 16;
    const int nbase = blockIdx.x * 64;

    if (tid < 16) {
        int m = mbase + tid;
        roff[tid] = (idx ? idx[m] : m) * K;
    }
    __syncthreads();

    u64 acc[2] = {0ull, 0ull};

    for (int kt = 0; kt < K; kt += 64) {
        {
            int m = tid >> 4, kq = tid & 15;
            float4 v = *(const float4*)&X[roff[m] + kt + kq * 4];
            Xs[kq * 4 + 0][m] = v.x;
            Xs[kq * 4 + 1][m] = v.y;
            Xs[kq * 4 + 2][m] = v.z;
            Xs[kq * 4 + 3][m] = v.w;
        }
#pragma unroll
        for (int j = 0; j < 4; j++) {
            int id = tid + 256 * j;
            int n = id >> 4, kq = id & 15;
            float4 v = *(const float4*)&W[(size_t)(nbase + n) * K + kt + kq * 4];
            Ws[kq * 4 + 0][n] = v.x;
            Ws[kq * 4 + 1][n] = v.y;
            Ws[kq * 4 + 2][n] = v.z;
            Ws[kq * 4 + 3][n] = v.w;
        }
        __syncthreads();
#pragma unroll
        for (int k = 0; k < 64; k++) {
            float a = Xs[k][ty];
            float4 b = *(const float4*)&Ws[k][tx * 4];
            u64 aa = pk2(a, a);
            fma2(acc[0], aa, pk2(b.x, b.y));
            fma2(acc[1], aa, pk2(b.z, b.w));
        }
        __syncthreads();
    }
    {
        int m = mbase + ty;
        float2 v0 = upk2(acc[0]), v1 = upk2(acc[1]);
        float o[4] = {v0.x, v0.y, v1.x, v1.y};
#pragma unroll
        for (int i = 0; i < 4; i++) {
            int n = nbase + tx * 4 + i;
            outF[m * D + n] = o[i] + bias[n];
        }
    }
}

// ---------------- K2: recurrences (y=0,1: 8-CTA clusters, mbarrier pipeline)
//                    + Wo/Wm->bf16 convert (y>=2) ----------------
#define CONV_YS 6
__global__ void __cluster_dims__(8, 1, 1) __launch_bounds__(512, 1)
recur_kernel(const float* __restrict__ Whh_e, const float* __restrict__ Whh_d,
             const float* __restrict__ h0_e, const float* __restrict__ h0_d,
             const float* __restrict__ Wo, const float* __restrict__ Wm) {
    const int tid = threadIdx.x;

    if (blockIdx.y >= 2) {
        const size_t gt = (size_t)((blockIdx.y - 2) * 8 + blockIdx.x) * 512 + tid;
        const size_t stride = (size_t)CONV_YS * 8 * 512;
        {
            const size_t n4 = (size_t)VOCAB * D / 4;
            const float4* src = (const float4*)Wo;
            uint2* dst = (uint2*)g_Wobf;
            for (size_t i = gt; i < n4; i += stride) {
                float4 f = src[i];
                __nv_bfloat162 lo = __float22bfloat162_rn(make_float2(f.x, f.y));
                __nv_bfloat162 hi = __float22bfloat162_rn(make_float2(f.z, f.w));
                uint2 u;
                u.x = *(uint32_t*)&lo;
                u.y = *(uint32_t*)&hi;
                dst[i] = u;
            }
        }
        {
            const size_t n4 = (size_t)D * 2 * D / 4;
            const float4* src = (const float4*)Wm;
            uint2* dst = (uint2*)g_Wmbf;
            for (size_t i = gt; i < n4; i += stride) {
                float4 f = src[i];
                __nv_bfloat162 lo = __float22bfloat162_rn(make_float2(f.x, f.y));
                __nv_bfloat162 hi = __float22bfloat162_rn(make_float2(f.z, f.w));
                uint2 u;
                u.x = *(uint32_t*)&lo;
                u.y = *(uint32_t*)&hi;
                dst[i] = u;
            }
        }
        return;
    }

    const int ph = blockIdx.y;
    const float* W = ph ? Whh_d : Whh_e;
    const float* h0 = ph ? h0_d : h0_e;
    const float* pre = ph ? g_epre : g_xpre;
    float* outg = ph ? g_H : g_fencs;

    __shared__ __align__(16) float hbuf[3][D];
    __shared__ __align__(8) u64 mbar[3];
    __shared__ float pre_s[128 * 64];

    const int rl = tid >> 3;
    const int sub = tid & 7;
    const uint32_t rank = blockIdx.x;
    const int row = rank * 64 + rl;

    u64 wv2[32];
#pragma unroll
    for (int j = 0; j < 16; j++) {
        ulonglong2 t = *(const ulonglong2*)&W[row * D + j * 32 + sub * 4];
        wv2[2 * j] = t.x;
        wv2[2 * j + 1] = t.y;
    }

    for (int i = tid; i < 128 * 64; i += 512) {
        int t = i >> 6, r = i & 63;
        pre_s[i] = pre[t * D + rank * 64 + r];
    }
    hbuf[0][tid] = h0[tid];
    if (tid < 3) mbar_init(smem_u32(&mbar[tid]), 1);
    __syncthreads();
    asm volatile("barrier.cluster.arrive.aligned;" ::: "memory");
    asm volatile("barrier.cluster.wait.aligned;" ::: "memory");

    const uint32_t mb_local = smem_u32(&mbar[0]);
    const uint32_t dst_remote0 = mapa_u32(smem_u32(&hbuf[0][row]), (uint32_t)sub);
    const uint32_t mb_remote0 = mapa_u32(mb_local, (uint32_t)sub);

#pragma unroll 1
    for (int t = 0; t < 128; t++) {
        const int b = t % 3;
        const int bn = (t + 1) % 3;
        if (tid == 0 && t < 127) mbar_expect_tx(mb_local + bn * 8, (uint32_t)(D * 4));
        if (t > 0) mbar_wait(mb_local + b * 8, ((t - 1) / 3) & 1);

        const float* hp = hbuf[b];
        u64 A0 = 0ull, A1 = 0ull;
#pragma unroll
        for (int j = 0; j < 16; j++) {
            ulonglong2 hv = *(const ulonglong2*)&hp[j * 32 + sub * 4];
            fma2(A0, wv2[2 * j], hv.x);
            fma2(A1, wv2[2 * j + 1], hv.y);
        }
        float2 f0 = upk2(A0), f1 = upk2(A1);
        float acc = (f0.x + f0.y) + (f1.x + f1.y);
#pragma unroll
        for (int o = 4; o; o >>= 1) acc += __shfl_xor_sync(0xffffffffu, acc, o);
        float h = fast_tanh(acc + pre_s[t * 64 + rl]);
        if (t < 127) st_async_f32(dst_remote0 + bn * (D * 4), mb_remote0 + bn * 8, h);
        if (sub == 0) outg[t * D + row] = h;
    }
    asm volatile("barrier.cluster.arrive.aligned;" ::: "memory");
    asm volatile("barrier.cluster.wait.aligned;" ::: "memory");
}

// ---------------- K3: fused attention per t -> CH in bf16 ----------------
__global__ void __launch_bounds__(256) attn_kernel() {
    int t = blockIdx.x;
    int tid = threadIdx.x, w = tid >> 5, l = tid & 31;
    __shared__ __align__(16) float hs[D];
    __shared__ float al[SRC];
    __shared__ float red[16];
    __shared__ __align__(16) float cpart[D];

    if (blockIdx.x == 0 && tid < TGT_STEPS) g_sumexp[tid] = 0.f;

    *(float2*)&hs[tid * 2] = *(const float2*)&g_H[t * D + tid * 2];
    __syncthreads();

#pragma unroll 1
    for (int si = 0; si < 16; si++) {
        int s2 = w * 16 + si;
        float acc = 0.f;
#pragma unroll
        for (int j = 0; j < 4; j++) {
            float4 fv = *(const float4*)&g_fencs[s2 * D + l * 4 + j * 128];
            float4 hv = *(const float4*)&hs[l * 4 + j * 128];
            acc += fv.x * hv.x + fv.y * hv.y + fv.z * hv.z + fv.w * hv.w;
        }
#pragma unroll
        for (int o = 16; o; o >>= 1) acc += __shfl_xor_sync(0xffffffffu, acc, o);
        if (l == 0) al[s2] = acc;
    }
    __syncthreads();

    float v = (tid < SRC) ? al[tid] : -1e30f;
    float mx = v;
#pragma unroll
    for (int o = 16; o; o >>= 1) mx = fmaxf(mx, __shfl_xor_sync(0xffffffffu, mx, o));
    if (l == 0) red[w] = mx;
    __syncthreads();
    mx = fmaxf(fmaxf(red[0], red[1]), fmaxf(red[2], red[3]));
    float e = (tid < SRC) ? __expf(v - mx) : 0.f;
    float sm = e;
#pragma unroll
    for (int o = 16; o; o >>= 1) sm += __shfl_xor_sync(0xffffffffu, sm, o);
    if (l == 0) red[8 + w] = sm;
    __syncthreads();
    sm = red[8] + red[9] + red[10] + red[11];
    if (tid < SRC) al[tid] = e / sm;
    __syncthreads();

    const int d4 = tid & 127, shalf = tid >> 7;
    const float4* f4 = (const float4*)g_fencs;
    float4 c = make_float4(0.f, 0.f, 0.f, 0.f);
    int s0 = shalf * 64;
#pragma unroll 8
    for (int s = s0; s < s0 + 64; s++) {
        float a = al[s];
        float4 fv = f4[s * (D / 4) + d4];
        c.x = fmaf(a, fv.x, c.x);
        c.y = fmaf(a, fv.y, c.y);
        c.z = fmaf(a, fv.z, c.z);
        c.w = fmaf(a, fv.w, c.w);
    }
    if (shalf == 1) *(float4*)&cpart[d4 * 4] = c;
    __syncthreads();
    if (shalf == 0) {
        float4 p = *(const float4*)&cpart[d4 * 4];
        c.x += p.x; c.y += p.y; c.z += p.z; c.w += p.w;
        __nv_bfloat162 lo = __float22bfloat162_rn(make_float2(c.x, c.y));
        __nv_bfloat162 hi = __float22bfloat162_rn(make_float2(c.z, c.w));
        uint2 u;
        u.x = *(uint32_t*)&lo;
        u.y = *(uint32_t*)&hi;
        *(uint2*)&g_CHbf[t * 2 * D + d4 * 4] = u;
    }
    {
        float2 hv = *(const float2*)&hs[tid * 2];
        __nv_bfloat162 hb = __float22bfloat162_rn(hv);
        *(uint32_t*)&g_CHbf[t * 2 * D + D + tid * 2] = *(uint32_t*)&hb;
    }
}

// ---------------- K4: M = tanh(CHbf @ Wmbf^T + bm), mma.sync + 4-stage cp.async ----
// grid 8 CTAs (N=64/CTA), 256 threads = 8 warps along M (16 rows each).
// K=1024 in 16 chunks of 64; 4 SMEM stages, 3 chunks in flight.
#define M_STAGES 4
#define M_ABUF 16384
#define M_BBUF 8192
#define M_OFF_B 0
#define M_OFF_A (M_STAGES * M_BBUF)
#define M_SMEM (M_OFF_A + M_STAGES * M_ABUF)

__global__ void __launch_bounds__(256, 1) m_hmma_kernel(const float* __restrict__ bm) {
    extern __shared__ char smem[];
    const uint32_t sb = smem_u32(smem);
    const int tid = threadIdx.x;
    const int lane = tid & 31;
    const int w = tid >> 5;
    const int nbase = blockIdx.x * 64;

    // A: thread (rowl, q) covers bytes q*64 + j*16 of each 128B chunk-row
    const int rowl = tid >> 1, q = tid & 1;
    const char* abase = (const char*)g_CHbf + (size_t)rowl * 2 * D * 2;
    // B: thread (rb, qb) covers bytes qb*32 + j*16
    const int rb = tid & 63, qb = tid >> 6;
    const char* bbase = (const char*)g_Wmbf + (size_t)(nbase + rb) * 2 * D * 2;

    const uint32_t aswA[4] = {sw128(rowl * 128 + q * 64 + 0), sw128(rowl * 128 + q * 64 + 16),
                              sw128(rowl * 128 + q * 64 + 32), sw128(rowl * 128 + q * 64 + 48)};
    const uint32_t bswB[2] = {sw128(rb * 128 + qb * 32 + 0), sw128(rb * 128 + qb * 32 + 16)};

#define M_ISSUE(c)                                                                 \
    do {                                                                           \
        uint32_t aB = sb + M_OFF_A + ((c) & 3) * M_ABUF;                           \
        uint32_t bB = sb + M_OFF_B + ((c) & 3) * M_BBUF;                           \
        _Pragma("unroll") for (int j = 0; j < 4; j++)                              \
            cp16(aB + aswA[j], abase + (size_t)(c) * 128 + q * 64 + j * 16);       \
        _Pragma("unroll") for (int j = 0; j < 2; j++)                              \
            cp16(bB + bswB[j], bbase + (size_t)(c) * 128 + qb * 32 + j * 16);      \
    } while (0)

    // prologue: 3 chunks in flight
#pragma unroll
    for (int s = 0; s < 3; s++) {
        M_ISSUE(s);
        asm volatile("cp.async.commit_group;" ::: "memory");
    }

    float cacc[8][4];
#pragma unroll
    for (int nn = 0; nn < 8; nn++)
#pragma unroll
        for (int e = 0; e < 4; e++) cacc[nn][e] = 0.f;

    const int rowA = w * 16 + (lane & 15);
    const int kselA = (lane >> 4) << 4;
    const int rowB = (lane & 7) + ((lane & 16) >> 1);
    const int kselB = (lane & 8) << 1;

#pragma unroll 1
    for (int c = 0; c < 16; c++) {
        asm volatile("cp.async.wait_group 2;" ::: "memory");
        __syncthreads();
        if (c + 3 < 16) M_ISSUE(c + 3);
        asm volatile("cp.async.commit_group;" ::: "memory");

        const uint32_t aBase = sb + M_OFF_A + (c & 3) * M_ABUF;
        const uint32_t bBase = sb + M_OFF_B + (c & 3) * M_BBUF;
#pragma unroll
        for (int kk = 0; kk < 4; kk++) {
            uint32_t a[4];
            {
                uint32_t off = rowA * 128 + kk * 32 + kselA;
                ldsm4(a[0], a[1], a[2], a[3], aBase + sw128(off));
            }
            uint32_t bf[4][4];
#pragma unroll
            for (int n2 = 0; n2 < 4; n2++) {
                uint32_t off = (rowB + n2 * 16) * 128 + kk * 32 + kselB;
                ldsm4(bf[n2][0], bf[n2][1], bf[n2][2], bf[n2][3], bBase + sw128(off));
            }
#pragma unroll
            for (int nn = 0; nn < 8; nn++) {
                uint32_t b0 = bf[nn >> 1][(nn & 1) * 2];
                uint32_t b1 = bf[nn >> 1][(nn & 1) * 2 + 1];
                mma_bf16(cacc[nn], a[0], a[1], a[2], a[3], b0, b1);
            }
        }
        __syncthreads();
    }

    // epilogue: tanh(acc + bm) -> g_Mbf
    {
        int r0 = w * 16 + (lane >> 2);
        int r1 = r0 + 8;
#pragma unroll
        for (int nn = 0; nn < 8; nn++) {
            int col = nn * 8 + 2 * (lane & 3);
            const float* cc = cacc[nn];
#pragma unroll
            for (int e = 0; e < 2; e++) {
                int n = nbase + col + e;
                float b = bm[n];
                g_Mbf[r0 * D + n] = __float2bfloat16(fast_tanh(cc[e] + b));
                g_Mbf[r1 * D + n] = __float2bfloat16(fast_tanh(cc[2 + e] + b));
            }
        }
    }
#undef M_ISSUE
}

// ---------------- K5: logits via mma.sync bf16 (B pre-converted) ----------------
#define OFF_BO 0
#define OFF_TGT 512
#define OFF_SEXP 1024
#define OFF_B 2048
#define OFF_A (2048 + 2 * 16384)
#define LOGITS_SMEM (OFF_A + 8 * 16384)

__global__ void __launch_bounds__(256, 1) logits_kernel(const float* __restrict__ bo,
                                                        const int* __restrict__ enums) {
    extern __shared__ char smem[];
    const uint32_t sb = smem_u32(smem);
    const int tid = threadIdx.x;
    const int lane = tid & 31;
    const int wm = (tid >> 5) & 3;
    const int wn = tid >> 7;
    const int vb = blockIdx.x * 128;

    float* bo_s = (float*)(smem + OFF_BO);
    int* tgt_s = (int*)(smem + OFF_TGT);
    float* sexp_s = (float*)(smem + OFF_SEXP);

    for (int i = tid; i < 128; i += 256) {
        int v = vb + i;
        bo_s[i] = (v < VOCAB) ? bo[v] : 0.f;
        tgt_s[i] = enums[i + 1];
        sexp_s[i] = 0.f;
    }

    for (int i = tid * 8; i < TGT_STEPS * D; i += 256 * 8) {
        int t = i >> 9, k = i & 511;
        uint4 v = *(const uint4*)&g_Mbf[i];
        int c = k >> 6, kk = k & 63;
        uint32_t sw = sw128(t * 128 + kk * 2);
        *(uint4*)(smem + OFF_A + c * 16384 + sw) = v;
    }

    const int rowl = tid >> 1, q = tid & 1;
    const bool vok = (vb + rowl) < VOCAB;
    const uint4* wsrc = (const uint4*)&g_Wobf[(size_t)(vb + rowl) * D];
    const uint4 Z = make_uint4(0u, 0u, 0u, 0u);

    uint4 pf[4];
#pragma unroll
    for (int j = 0; j < 4; j++) pf[j] = vok ? wsrc[q * 4 + j] : Z;

    float cacc[2][8][4];
#pragma unroll
    for (int mi = 0; mi < 2; mi++)
#pragma unroll
        for (int nn = 0; nn < 8; nn++)
#pragma unroll
            for (int e = 0; e < 4; e++) cacc[mi][nn][e] = 0.f;

    const int rowA = wm * 32 + (lane & 15);
    const int kselA = (lane >> 4) << 4;
    const int rowB = wn * 64 + (lane & 7) + ((lane & 16) >> 1);
    const int kselB = (lane & 8) << 1;

#pragma unroll 1
    for (int c = 0; c < 8; c++) {
        char* bbuf = smem + OFF_B + (c & 1) * 16384;
#pragma unroll
        for (int j = 0; j < 4; j++) {
            uint32_t sw = sw128(rowl * 128 + q * 64 + j * 16);
            *(uint4*)(bbuf + sw) = pf[j];
        }
        __syncthreads();
        if (c < 7) {
#pragma unroll
            for (int j = 0; j < 4; j++)
                pf[j] = vok ? wsrc[(c + 1) * 8 + q * 4 + j] : Z;
        }
        const uint32_t aBase = sb + OFF_A + c * 16384;
        const uint32_t bBase = sb + OFF_B + (c & 1) * 16384;
#pragma unroll
        for (int kk = 0; kk < 4; kk++) {
            uint32_t a[2][4];
#pragma unroll
            for (int mi = 0; mi < 2; mi++) {
                uint32_t off = (rowA + mi * 16) * 128 + kk * 32 + kselA;
                ldsm4(a[mi][0], a[mi][1], a[mi][2], a[mi][3], aBase + sw128(off));
            }
            uint32_t bf[4][4];
#pragma unroll
            for (int n2 = 0; n2 < 4; n2++) {
                uint32_t off = (rowB + n2 * 16) * 128 + kk * 32 + kselB;
                ldsm4(bf[n2][0], bf[n2][1], bf[n2][2], bf[n2][3], bBase + sw128(off));
            }
#pragma unroll
            for (int mi = 0; mi < 2; mi++)
#pragma unroll
                for (int nn = 0; nn < 8; nn++) {
                    uint32_t b0 = bf[nn >> 1][(nn & 1) * 2];
                    uint32_t b1 = bf[nn >> 1][(nn & 1) * 2 + 1];
                    mma_bf16(cacc[mi][nn], a[mi][0], a[mi][1], a[mi][2], a[mi][3], b0, b1);
                }
        }
    }

#pragma unroll
    for (int mi = 0; mi < 2; mi++) {
        int r0 = wm * 32 + mi * 16 + (lane >> 2);
        int r1 = r0 + 8;
        float s0 = 0.f, s1 = 0.f;
#pragma unroll
        for (int nn = 0; nn < 8; nn++) {
            int col = wn * 64 + nn * 8 + 2 * (lane & 3);
            const float* cc = cacc[mi][nn];
#pragma unroll
            for (int e = 0; e < 2; e++) {
                int v = vb + col + e;
                if (v < VOCAB) {
                    float lg0 = cc[e] + bo_s[col + e];
                    float lg1 = cc[2 + e] + bo_s[col + e];
                    s0 += __expf(lg0);
                    s1 += __expf(lg1);
                    if (v == tgt_s[r0]) g_picked[r0] = lg0;
                    if (v == tgt_s[r1]) g_picked[r1] = lg1;
                }
            }
        }
        s0 += __shfl_xor_sync(0xffffffffu, s0, 1);
        s0 += __shfl_xor_sync(0xffffffffu, s0, 2);
        s1 += __shfl_xor_sync(0xffffffffu, s1, 1);
        s1 += __shfl_xor_sync(0xffffffffu, s1, 2);
        if ((lane & 3) == 0) {
            atomicAdd(&sexp_s[r0], s0);
            atomicAdd(&sexp_s[r1], s1);
        }
    }
    __syncthreads();
    for (int i = tid; i < 128; i += 256) atomicAdd(&g_sumexp[i], sexp_s[i]);
}

// ---------------- K6: final reduction ----------------
__global__ void finalize_kernel(float* __restrict__ out) {
    int tid = threadIdx.x;
    float v = g_picked[tid] - logf(g_sumexp[tid]);
    __shared__ float red[4];
    int w = tid >> 5, l = tid & 31;
#pragma unroll
    for (int o = 16; o; o >>= 1) v += __shfl_xor_sync(0xffffffffu, v, o);
    if (l == 0) red[w] = v;
    __syncthreads();
    if (tid == 0) out[0] = red[0] + red[1] + red[2] + red[3];
}

// ---------------- launch ----------------
extern "C" void kernel_launch(void* const* d_in, const int* in_sizes, int n_in,
                              void* d_out, int out_size) {
    const int* fnums = (const int*)d_in[0];
    const int* enums = (const int*)d_in[1];
    const float* emb_f = (const float*)d_in[2];
    const float* Wih_e = (const float*)d_in[3];
    const float* Whh_e = (const float*)d_in[4];
    const float* b_e = (const float*)d_in[5];
    const float* h0_e = (const float*)d_in[6];
    const float* emb_d = (const float*)d_in[7];
    const float* Wih_d = (const float*)d_in[8];
    const float* Whh_d = (const float*)d_in[9];
    const float* b_d = (const float*)d_in[10];
    const float* h0_d = (const float*)d_in[11];
    const float* Wm = (const float*)d_in[12];
    const float* bm = (const float*)d_in[13];
    const float* Wo = (const float*)d_in[14];
    const float* bo = (const float*)d_in[15];
    float* out = (float*)d_out;

    static int inited = 0;
    static float *p_xpre, *p_epre;
    if (!inited) {
        cudaFuncSetAttribute(logits_kernel, cudaFuncAttributeMaxDynamicSharedMemorySize,
                             LOGITS_SMEM);
        cudaFuncSetAttribute(m_hmma_kernel, cudaFuncAttributeMaxDynamicSharedMemorySize,
                             M_SMEM);
        cudaGetSymbolAddress((void**)&p_xpre, g_xpre);
        cudaGetSymbolAddress((void**)&p_epre, g_epre);
        inited = 1;
    }

    // pre-activations: encoder (z=0) + decoder (z=1) concurrently; 128 CTAs
    gemm_kernel<<<dim3(8, 8, 2), 256>>>(emb_f, fnums, Wih_e, b_e,
                                        emb_d, enums, Wih_d, b_d,
                                        p_xpre, p_epre, D);
    // recur (y=0,1) + Wo/Wm->bf16 conversion (y=2..) overlapped in one launch
    recur_kernel<<<dim3(8, 2 + CONV_YS), 512>>>(Whh_e, Whh_d, h0_e, h0_d, Wo, Wm);
    // fused attention: scores + softmax + context + CHbf assembly (+ sumexp init)
    attn_kernel<<<128, 256>>>();
    // M = tanh(CHbf @ Wmbf^T + bm) -> bf16, tensor cores + cp.async pipeline
    m_hmma_kernel<<<8, 256, M_SMEM>>>(bm);
    logits_kernel<<<(VOCAB + 127) / 128, 256, LOGITS_SMEM>>>(bo, enums);
    finalize_kernel<<<1, 128>>>(out);
}

// round 16
// speedup vs baseline: 1.6163x; 1.0159x over previous
#include <cuda_runtime.h>
#include <cuda_bf16.h>
#include <cstdint>

#define D 512
#define SRC 128
#define TGT_STEPS 128
#define VOCAB 50000

typedef unsigned long long u64;

// ---------------- scratch (device globals; no allocation allowed) ----------------
__device__ __align__(16) float g_xpre[SRC * D];
__device__ __align__(16) float g_epre[TGT_STEPS * D];
__device__ __align__(16) float g_fencs[SRC * D];
__device__ __align__(16) float g_H[TGT_STEPS * D];
__device__ __align__(16) __nv_bfloat16 g_CHbf[TGT_STEPS * 2 * D];
__device__ __align__(16) __nv_bfloat16 g_Mbf[TGT_STEPS * D];
__device__ __align__(16) __nv_bfloat16 g_Wmbf[D * 2 * D];
__device__ __align__(16) __nv_bfloat16 g_Wobf[VOCAB * D];
__device__ float g_sumexp[TGT_STEPS];
__device__ float g_picked[TGT_STEPS];

// ---------------- helpers ----------------
__device__ __forceinline__ u64 pk2(float x, float y) {
    u64 r;
    asm("mov.b64 %0, {%1, %2};" : "=l"(r) : "f"(x), "f"(y));
    return r;
}
__device__ __forceinline__ float2 upk2(u64 v) {
    float2 r;
    asm("mov.b64 {%0, %1}, %2;" : "=f"(r.x), "=f"(r.y) : "l"(v));
    return r;
}
__device__ __forceinline__ void fma2(u64& d, u64 a, u64 b) {
    asm volatile("fma.rn.f32x2 %0, %1, %2, %0;" : "+l"(d) : "l"(a), "l"(b));
}
__device__ __forceinline__ uint32_t smem_u32(const void* p) {
    uint32_t a;
    asm("{ .reg .u64 t; cvta.to.shared.u64 t, %1; cvt.u32.u64 %0, t; }" : "=r"(a) : "l"(p));
    return a;
}
__device__ __forceinline__ uint32_t mapa_u32(uint32_t saddr, uint32_t rank) {
    uint32_t r;
    asm volatile("mapa.shared::cluster.u32 %0, %1, %2;" : "=r"(r) : "r"(saddr), "r"(rank));
    return r;
}
__device__ __forceinline__ void st_async_f32(uint32_t raddr, uint32_t rmbar, float v) {
    asm volatile(
        "st.async.shared::cluster.mbarrier::complete_tx::bytes.b32 [%0], %1, [%2];"
        :: "r"(raddr), "r"(__float_as_uint(v)), "r"(rmbar) : "memory");
}
__device__ __forceinline__ void mbar_init(uint32_t addr, uint32_t cnt) {
    asm volatile("mbarrier.init.shared.b64 [%0], %1;" :: "r"(addr), "r"(cnt) : "memory");
}
__device__ __forceinline__ void mbar_expect_tx(uint32_t addr, uint32_t bytes) {
    asm volatile("mbarrier.arrive.expect_tx.shared.b64 _, [%0], %1;"
                 :: "r"(addr), "r"(bytes) : "memory");
}
__device__ __forceinline__ void mbar_wait(uint32_t addr, int parity) {
    asm volatile(
        "{\n\t.reg .pred P;\n\t"
        "W_%=:\n\t"
        "mbarrier.try_wait.parity.acquire.cta.shared::cta.b64 P, [%0], %1;\n\t"
        "@!P bra W_%=;\n\t}"
        :: "r"(addr), "r"(parity) : "memory");
}
__device__ __forceinline__ void ldsm4(uint32_t& r0, uint32_t& r1, uint32_t& r2, uint32_t& r3,
                                      uint32_t addr) {
    asm volatile("ldmatrix.sync.aligned.m8n8.x4.shared.b16 {%0,%1,%2,%3}, [%4];"
                 : "=r"(r0), "=r"(r1), "=r"(r2), "=r"(r3) : "r"(addr));
}
__device__ __forceinline__ void mma_bf16(float* c, uint32_t a0, uint32_t a1, uint32_t a2,
                                         uint32_t a3, uint32_t b0, uint32_t b1) {
    asm volatile(
        "mma.sync.aligned.m16n8k16.row.col.f32.bf16.bf16.f32 "
        "{%0,%1,%2,%3}, {%4,%5,%6,%7}, {%8,%9}, {%0,%1,%2,%3};"
        : "+f"(c[0]), "+f"(c[1]), "+f"(c[2]), "+f"(c[3])
        : "r"(a0), "r"(a1), "r"(a2), "r"(a3), "r"(b0), "r"(b1));
}
__device__ __forceinline__ void cp16(uint32_t smem, const void* g) {
    asm volatile("cp.async.cg.shared.global [%0], [%1], 16;" :: "r"(smem), "l"(g) : "memory");
}
__device__ __forceinline__ void cp16z(uint32_t smem, const void* g, int srcsize) {
    asm volatile("cp.async.cg.shared.global [%0], [%1], 16, %2;"
                 :: "r"(smem), "l"(g), "r"(srcsize) : "memory");
}
__device__ __forceinline__ uint32_t sw128(uint32_t off) { return off ^ ((off >> 3) & 0x70); }
__device__ __forceinline__ float fast_tanh(float x) {
    float e = __expf(2.f * x);
    return __fdividef(e - 1.f, e + 1.f);
}

// ---------------- K1: pre-activation SGEMM (fp32 kept for recurrence precision) ----
__global__ void __launch_bounds__(256) gemm_kernel(
    const float* __restrict__ X0, const int* __restrict__ idx0,
    const float* __restrict__ W0, const float* __restrict__ b0,
    const float* __restrict__ X1, const int* __restrict__ idx1,
    const float* __restrict__ W1, const float* __restrict__ b1,
    float* __restrict__ oF0, float* __restrict__ oF1,
    int K) {
    const int z = blockIdx.z;
    const float* X = z ? X1 : X0;
    const int* idx = z ? idx1 : idx0;
    const float* W = z ? W1 : W0;
    const float* bias = z ? b1 : b0;
    float* outF = z ? oF1 : oF0;

    __shared__ __align__(16) float Xs[64][17];
    __shared__ __align__(16) float Ws[64][68];
    __shared__ int roff[16];

    const int tid = threadIdx.x;
    const int tx = tid & 15, ty = tid >> 4;
    const int mbase = blockIdx.y * 16;
    const int nbase = blockIdx.x * 64;

    if (tid < 16) {
        int m = mbase + tid;
        roff[tid] = (idx ? idx[m] : m) * K;
    }
    __syncthreads();

    u64 acc[2] = {0ull, 0ull};

    for (int kt = 0; kt < K; kt += 64) {
        {
            int m = tid >> 4, kq = tid & 15;
            float4 v = *(const float4*)&X[roff[m] + kt + kq * 4];
            Xs[kq * 4 + 0][m] = v.x;
            Xs[kq * 4 + 1][m] = v.y;
            Xs[kq * 4 + 2][m] = v.z;
            Xs[kq * 4 + 3][m] = v.w;
        }
#pragma unroll
        for (int j = 0; j < 4; j++) {
            int id = tid + 256 * j;
            int n = id >> 4, kq = id & 15;
            float4 v = *(const float4*)&W[(size_t)(nbase + n) * K + kt + kq * 4];
            Ws[kq * 4 + 0][n] = v.x;
            Ws[kq * 4 + 1][n] = v.y;
            Ws[kq * 4 + 2][n] = v.z;
            Ws[kq * 4 + 3][n] = v.w;
        }
        __syncthreads();
#pragma unroll
        for (int k = 0; k < 64; k++) {
            float a = Xs[k][ty];
            float4 b = *(const float4*)&Ws[k][tx * 4];
            u64 aa = pk2(a, a);
            fma2(acc[0], aa, pk2(b.x, b.y));
            fma2(acc[1], aa, pk2(b.z, b.w));
        }
        __syncthreads();
    }
    {
        int m = mbase + ty;
        float2 v0 = upk2(acc[0]), v1 = upk2(acc[1]);
        float o[4] = {v0.x, v0.y, v1.x, v1.y};
#pragma unroll
        for (int i = 0; i < 4; i++) {
            int n = nbase + tx * 4 + i;
            outF[m * D + n] = o[i] + bias[n];
        }
    }
}

// ---------------- K2: recurrences (y=0,1: 8-CTA clusters, mbarrier pipeline)
//                    + Wo/Wm->bf16 convert (y>=2) ----------------
#define CONV_YS 6
__global__ void __cluster_dims__(8, 1, 1) __launch_bounds__(512, 1)
recur_kernel(const float* __restrict__ Whh_e, const float* __restrict__ Whh_d,
             const float* __restrict__ h0_e, const float* __restrict__ h0_d,
             const float* __restrict__ Wo, const float* __restrict__ Wm) {
    const int tid = threadIdx.x;

    if (blockIdx.y >= 2) {
        const size_t gt = (size_t)((blockIdx.y - 2) * 8 + blockIdx.x) * 512 + tid;
        const size_t stride = (size_t)CONV_YS * 8 * 512;
        {
            const size_t n4 = (size_t)VOCAB * D / 4;
            const float4* src = (const float4*)Wo;
            uint2* dst = (uint2*)g_Wobf;
            for (size_t i = gt; i < n4; i += stride) {
                float4 f = src[i];
                __nv_bfloat162 lo = __float22bfloat162_rn(make_float2(f.x, f.y));
                __nv_bfloat162 hi = __float22bfloat162_rn(make_float2(f.z, f.w));
                uint2 u;
                u.x = *(uint32_t*)&lo;
                u.y = *(uint32_t*)&hi;
                dst[i] = u;
            }
        }
        {
            const size_t n4 = (size_t)D * 2 * D / 4;
            const float4* src = (const float4*)Wm;
            uint2* dst = (uint2*)g_Wmbf;
            for (size_t i = gt; i < n4; i += stride) {
                float4 f = src[i];
                __nv_bfloat162 lo = __float22bfloat162_rn(make_float2(f.x, f.y));
                __nv_bfloat162 hi = __float22bfloat162_rn(make_float2(f.z, f.w));
                uint2 u;
                u.x = *(uint32_t*)&lo;
                u.y = *(uint32_t*)&hi;
                dst[i] = u;
            }
        }
        return;
    }

    const int ph = blockIdx.y;
    const float* W = ph ? Whh_d : Whh_e;
    const float* h0 = ph ? h0_d : h0_e;
    const float* pre = ph ? g_epre : g_xpre;
    float* outg = ph ? g_H : g_fencs;

    __shared__ __align__(16) float hbuf[3][D];
    __shared__ __align__(8) u64 mbar[3];
    __shared__ float pre_s[128 * 64];

    const int rl = tid >> 3;
    const int sub = tid & 7;
    const uint32_t rank = blockIdx.x;
    const int row = rank * 64 + rl;

    u64 wv2[32];
#pragma unroll
    for (int j = 0; j < 16; j++) {
        ulonglong2 t = *(const ulonglong2*)&W[row * D + j * 32 + sub * 4];
        wv2[2 * j] = t.x;
        wv2[2 * j + 1] = t.y;
    }

    for (int i = tid; i < 128 * 64; i += 512) {
        int t = i >> 6, r = i & 63;
        pre_s[i] = pre[t * D + rank * 64 + r];
    }
    hbuf[0][tid] = h0[tid];
    if (tid < 3) mbar_init(smem_u32(&mbar[tid]), 1);
    __syncthreads();
    asm volatile("barrier.cluster.arrive.aligned;" ::: "memory");
    asm volatile("barrier.cluster.wait.aligned;" ::: "memory");

    const uint32_t mb_local = smem_u32(&mbar[0]);
    const uint32_t dst_remote0 = mapa_u32(smem_u32(&hbuf[0][row]), (uint32_t)sub);
    const uint32_t mb_remote0 = mapa_u32(mb_local, (uint32_t)sub);

#pragma unroll 1
    for (int t = 0; t < 128; t++) {
        const int b = t % 3;
        const int bn = (t + 1) % 3;
        if (tid == 0 && t < 127) mbar_expect_tx(mb_local + bn * 8, (uint32_t)(D * 4));
        if (t > 0) mbar_wait(mb_local + b * 8, ((t - 1) / 3) & 1);

        const float* hp = hbuf[b];
        u64 A0 = 0ull, A1 = 0ull;
#pragma unroll
        for (int j = 0; j < 16; j++) {
            ulonglong2 hv = *(const ulonglong2*)&hp[j * 32 + sub * 4];
            fma2(A0, wv2[2 * j], hv.x);
            fma2(A1, wv2[2 * j + 1], hv.y);
        }
        float2 f0 = upk2(A0), f1 = upk2(A1);
        float acc = (f0.x + f0.y) + (f1.x + f1.y);
#pragma unroll
        for (int o = 4; o; o >>= 1) acc += __shfl_xor_sync(0xffffffffu, acc, o);
        float h = fast_tanh(acc + pre_s[t * 64 + rl]);
        if (t < 127) st_async_f32(dst_remote0 + bn * (D * 4), mb_remote0 + bn * 8, h);
        if (sub == 0) outg[t * D + row] = h;
    }
    asm volatile("barrier.cluster.arrive.aligned;" ::: "memory");
    asm volatile("barrier.cluster.wait.aligned;" ::: "memory");
}

// ---------------- K3: fused attention per t -> CH in bf16 ----------------
__global__ void __launch_bounds__(256) attn_kernel() {
    int t = blockIdx.x;
    int tid = threadIdx.x, w = tid >> 5, l = tid & 31;
    __shared__ __align__(16) float hs[D];
    __shared__ float al[SRC];
    __shared__ float red[16];
    __shared__ __align__(16) float cpart[D];

    if (blockIdx.x == 0 && tid < TGT_STEPS) g_sumexp[tid] = 0.f;

    *(float2*)&hs[tid * 2] = *(const float2*)&g_H[t * D + tid * 2];
    __syncthreads();

#pragma unroll 1
    for (int si = 0; si < 16; si++) {
        int s2 = w * 16 + si;
        float acc = 0.f;
#pragma unroll
        for (int j = 0; j < 4; j++) {
            float4 fv = *(const float4*)&g_fencs[s2 * D + l * 4 + j * 128];
            float4 hv = *(const float4*)&hs[l * 4 + j * 128];
            acc += fv.x * hv.x + fv.y * hv.y + fv.z * hv.z + fv.w * hv.w;
        }
#pragma unroll
        for (int o = 16; o; o >>= 1) acc += __shfl_xor_sync(0xffffffffu, acc, o);
        if (l == 0) al[s2] = acc;
    }
    __syncthreads();

    float v = (tid < SRC) ? al[tid] : -1e30f;
    float mx = v;
#pragma unroll
    for (int o = 16; o; o >>= 1) mx = fmaxf(mx, __shfl_xor_sync(0xffffffffu, mx, o));
    if (l == 0) red[w] = mx;
    __syncthreads();
    mx = fmaxf(fmaxf(red[0], red[1]), fmaxf(red[2], red[3]));
    float e = (tid < SRC) ? __expf(v - mx) : 0.f;
    float sm = e;
#pragma unroll
    for (int o = 16; o; o >>= 1) sm += __shfl_xor_sync(0xffffffffu, sm, o);
    if (l == 0) red[8 + w] = sm;
    __syncthreads();
    sm = red[8] + red[9] + red[10] + red[11];
    if (tid < SRC) al[tid] = e / sm;
    __syncthreads();

    const int d4 = tid & 127, shalf = tid >> 7;
    const float4* f4 = (const float4*)g_fencs;
    float4 c = make_float4(0.f, 0.f, 0.f, 0.f);
    int s0 = shalf * 64;
#pragma unroll 8
    for (int s = s0; s < s0 + 64; s++) {
        float a = al[s];
        float4 fv = f4[s * (D / 4) + d4];
        c.x = fmaf(a, fv.x, c.x);
        c.y = fmaf(a, fv.y, c.y);
        c.z = fmaf(a, fv.z, c.z);
        c.w = fmaf(a, fv.w, c.w);
    }
    if (shalf == 1) *(float4*)&cpart[d4 * 4] = c;
    __syncthreads();
    if (shalf == 0) {
        float4 p = *(const float4*)&cpart[d4 * 4];
        c.x += p.x; c.y += p.y; c.z += p.z; c.w += p.w;
        __nv_bfloat162 lo = __float22bfloat162_rn(make_float2(c.x, c.y));
        __nv_bfloat162 hi = __float22bfloat162_rn(make_float2(c.z, c.w));
        uint2 u;
        u.x = *(uint32_t*)&lo;
        u.y = *(uint32_t*)&hi;
        *(uint2*)&g_CHbf[t * 2 * D + d4 * 4] = u;
    }
    {
        float2 hv = *(const float2*)&hs[tid * 2];
        __nv_bfloat162 hb = __float22bfloat162_rn(hv);
        *(uint32_t*)&g_CHbf[t * 2 * D + D + tid * 2] = *(uint32_t*)&hb;
    }
}

// ---------------- K4: M = tanh(CHbf @ Wmbf^T + bm), mma.sync + 4-stage cp.async ----
#define M_STAGES 4
#define M_ABUF 16384
#define M_BBUF 8192
#define M_OFF_B 0
#define M_OFF_A (M_STAGES * M_BBUF)
#define M_SMEM (M_OFF_A + M_STAGES * M_ABUF)

__global__ void __launch_bounds__(256, 1) m_hmma_kernel(const float* __restrict__ bm) {
    extern __shared__ char smem[];
    const uint32_t sb = smem_u32(smem);
    const int tid = threadIdx.x;
    const int lane = tid & 31;
    const int w = tid >> 5;
    const int nbase = blockIdx.x * 64;

    const int rowl = tid >> 1, q = tid & 1;
    const char* abase = (const char*)g_CHbf + (size_t)rowl * 2 * D * 2;
    const int rb = tid & 63, qb = tid >> 6;
    const char* bbase = (const char*)g_Wmbf + (size_t)(nbase + rb) * 2 * D * 2;

    const uint32_t aswA[4] = {sw128(rowl * 128 + q * 64 + 0), sw128(rowl * 128 + q * 64 + 16),
                              sw128(rowl * 128 + q * 64 + 32), sw128(rowl * 128 + q * 64 + 48)};
    const uint32_t bswB[2] = {sw128(rb * 128 + qb * 32 + 0), sw128(rb * 128 + qb * 32 + 16)};

#define M_ISSUE(c)                                                                 \
    do {                                                                           \
        uint32_t aB = sb + M_OFF_A + ((c) & 3) * M_ABUF;                           \
        uint32_t bB = sb + M_OFF_B + ((c) & 3) * M_BBUF;                           \
        _Pragma("unroll") for (int j = 0; j < 4; j++)                              \
            cp16(aB + aswA[j], abase + (size_t)(c) * 128 + q * 64 + j * 16);       \
        _Pragma("unroll") for (int j = 0; j < 2; j++)                              \
            cp16(bB + bswB[j], bbase + (size_t)(c) * 128 + qb * 32 + j * 16);      \
    } while (0)

#pragma unroll
    for (int s = 0; s < 3; s++) {
        M_ISSUE(s);
        asm volatile("cp.async.commit_group;" ::: "memory");
    }

    float cacc[8][4];
#pragma unroll
    for (int nn = 0; nn < 8; nn++)
#pragma unroll
        for (int e = 0; e < 4; e++) cacc[nn][e] = 0.f;

    const int rowA = w * 16 + (lane & 15);
    const int kselA = (lane >> 4) << 4;
    const int rowB = (lane & 7) + ((lane & 16) >> 1);
    const int kselB = (lane & 8) << 1;

#pragma unroll 1
    for (int c = 0; c < 16; c++) {
        asm volatile("cp.async.wait_group 2;" ::: "memory");
        __syncthreads();
        if (c + 3 < 16) M_ISSUE(c + 3);
        asm volatile("cp.async.commit_group;" ::: "memory");

        const uint32_t aBase = sb + M_OFF_A + (c & 3) * M_ABUF;
        const uint32_t bBase = sb + M_OFF_B + (c & 3) * M_BBUF;
#pragma unroll
        for (int kk = 0; kk < 4; kk++) {
            uint32_t a[4];
            {
                uint32_t off = rowA * 128 + kk * 32 + kselA;
                ldsm4(a[0], a[1], a[2], a[3], aBase + sw128(off));
            }
            uint32_t bf[4][4];
#pragma unroll
            for (int n2 = 0; n2 < 4; n2++) {
                uint32_t off = (rowB + n2 * 16) * 128 + kk * 32 + kselB;
                ldsm4(bf[n2][0], bf[n2][1], bf[n2][2], bf[n2][3], bBase + sw128(off));
            }
#pragma unroll
            for (int nn = 0; nn < 8; nn++) {
                uint32_t b0 = bf[nn >> 1][(nn & 1) * 2];
                uint32_t b1 = bf[nn >> 1][(nn & 1) * 2 + 1];
                mma_bf16(cacc[nn], a[0], a[1], a[2], a[3], b0, b1);
            }
        }
        __syncthreads();
    }

    {
        int r0 = w * 16 + (lane >> 2);
        int r1 = r0 + 8;
#pragma unroll
        for (int nn = 0; nn < 8; nn++) {
            int col = nn * 8 + 2 * (lane & 3);
            const float* cc = cacc[nn];
#pragma unroll
            for (int e = 0; e < 2; e++) {
                int n = nbase + col + e;
                float b = bm[n];
                g_Mbf[r0 * D + n] = __float2bfloat16(fast_tanh(cc[e] + b));
                g_Mbf[r1 * D + n] = __float2bfloat16(fast_tanh(cc[2 + e] + b));
            }
        }
    }
#undef M_ISSUE
}

// ---------------- K5: logits via mma.sync bf16, 4-stage cp.async B-stream ----------
#define L_STAGES 4
#define L_BBUF 16384
#define OFF_BO 0
#define OFF_TGT 512
#define OFF_SEXP 1024
#define OFF_B 2048
#define OFF_A (OFF_B + L_STAGES * L_BBUF)
#define LOGITS_SMEM (OFF_A + 8 * 16384)

__global__ void __launch_bounds__(256, 1) logits_kernel(const float* __restrict__ bo,
                                                        const int* __restrict__ enums) {
    extern __shared__ char smem[];
    const uint32_t sb = smem_u32(smem);
    const int tid = threadIdx.x;
    const int lane = tid & 31;
    const int wm = (tid >> 5) & 3;
    const int wn = tid >> 7;
    const int vb = blockIdx.x * 128;

    float* bo_s = (float*)(smem + OFF_BO);
    int* tgt_s = (int*)(smem + OFF_TGT);
    float* sexp_s = (float*)(smem + OFF_SEXP);

    // B-stream setup: thread (rowl, q) covers bytes q*64 + j*16 of its vocab row
    const int rowl = tid >> 1, q = tid & 1;
    const bool vok = (vb + rowl) < VOCAB;
    const int szB = vok ? 16 : 0;
    const char* bbase = (const char*)g_Wobf + (size_t)(vb + rowl) * D * 2;
    const uint32_t bsw[4] = {sw128(rowl * 128 + q * 64 + 0), sw128(rowl * 128 + q * 64 + 16),
                             sw128(rowl * 128 + q * 64 + 32), sw128(rowl * 128 + q * 64 + 48)};

#define L_ISSUE(c)                                                                  \
    do {                                                                            \
        uint32_t bB = sb + OFF_B + ((c) & 3) * L_BBUF;                              \
        _Pragma("unroll") for (int j = 0; j < 4; j++)                               \
            cp16z(bB + bsw[j], bbase + (size_t)(c) * 128 + q * 64 + j * 16, szB);   \
    } while (0)

#pragma unroll
    for (int s = 0; s < 3; s++) {
        L_ISSUE(s);
        asm volatile("cp.async.commit_group;" ::: "memory");
    }

    for (int i = tid; i < 128; i += 256) {
        int v = vb + i;
        bo_s[i] = (v < VOCAB) ? bo[v] : 0.f;
        tgt_s[i] = enums[i + 1];
        sexp_s[i] = 0.f;
    }

    // A: g_Mbf -> 8 swizzled SMEM chunks
    for (int i = tid * 8; i < TGT_STEPS * D; i += 256 * 8) {
        int t = i >> 9, k = i & 511;
        uint4 v = *(const uint4*)&g_Mbf[i];
        int c = k >> 6, kk = k & 63;
        uint32_t sw = sw128(t * 128 + kk * 2);
        *(uint4*)(smem + OFF_A + c * 16384 + sw) = v;
    }

    float cacc[2][8][4];
#pragma unroll
    for (int mi = 0; mi < 2; mi++)
#pragma unroll
        for (int nn = 0; nn < 8; nn++)
#pragma unroll
            for (int e = 0; e < 4; e++) cacc[mi][nn][e] = 0.f;

    const int rowA = wm * 32 + (lane & 15);
    const int kselA = (lane >> 4) << 4;
    const int rowB = wn * 64 + (lane & 7) + ((lane & 16) >> 1);
    const int kselB = (lane & 8) << 1;

#pragma unroll 1
    for (int c = 0; c < 8; c++) {
        asm volatile("cp.async.wait_group 2;" ::: "memory");
        __syncthreads();
        if (c + 3 < 8) L_ISSUE(c + 3);
        asm volatile("cp.async.commit_group;" ::: "memory");

        const uint32_t aBase = sb + OFF_A + c * 16384;
        const uint32_t bBase = sb + OFF_B + (c & 3) * L_BBUF;
#pragma unroll
        for (int kk = 0; kk < 4; kk++) {
            uint32_t a[2][4];
#pragma unroll
            for (int mi = 0; mi < 2; mi++) {
                uint32_t off = (rowA + mi * 16) * 128 + kk * 32 + kselA;
                ldsm4(a[mi][0], a[mi][1], a[mi][2], a[mi][3], aBase + sw128(off));
            }
            uint32_t bf[4][4];
#pragma unroll
            for (int n2 = 0; n2 < 4; n2++) {
                uint32_t off = (rowB + n2 * 16) * 128 + kk * 32 + kselB;
                ldsm4(bf[n2][0], bf[n2][1], bf[n2][2], bf[n2][3], bBase + sw128(off));
            }
#pragma unroll
            for (int mi = 0; mi < 2; mi++)
#pragma unroll
                for (int nn = 0; nn < 8; nn++) {
                    uint32_t b0 = bf[nn >> 1][(nn & 1) * 2];
                    uint32_t b1 = bf[nn >> 1][(nn & 1) * 2 + 1];
                    mma_bf16(cacc[mi][nn], a[mi][0], a[mi][1], a[mi][2], a[mi][3], b0, b1);
                }
        }
        __syncthreads();
    }
#undef L_ISSUE

#pragma unroll
    for (int mi = 0; mi < 2; mi++) {
        int r0 = wm * 32 + mi * 16 + (lane >> 2);
        int r1 = r0 + 8;
        float s0 = 0.f, s1 = 0.f;
#pragma unroll
        for (int nn = 0; nn < 8; nn++) {
            int col = wn * 64 + nn * 8 + 2 * (lane & 3);
            const float* cc = cacc[mi][nn];
#pragma unroll
            for (int e = 0; e < 2; e++) {
                int v = vb + col + e;
                if (v < VOCAB) {
                    float lg0 = cc[e] + bo_s[col + e];
                    float lg1 = cc[2 + e] + bo_s[col + e];
                    s0 += __expf(lg0);
                    s1 += __expf(lg1);
                    if (v == tgt_s[r0]) g_picked[r0] = lg0;
                    if (v == tgt_s[r1]) g_picked[r1] = lg1;
                }
            }
        }
        s0 += __shfl_xor_sync(0xffffffffu, s0, 1);
        s0 += __shfl_xor_sync(0xffffffffu, s0, 2);
        s1 += __shfl_xor_sync(0xffffffffu, s1, 1);
        s1 += __shfl_xor_sync(0xffffffffu, s1, 2);
        if ((lane & 3) == 0) {
            atomicAdd(&sexp_s[r0], s0);
            atomicAdd(&sexp_s[r1], s1);
        }
    }
    __syncthreads();
    for (int i = tid; i < 128; i += 256) atomicAdd(&g_sumexp[i], sexp_s[i]);
}

// ---------------- K6: final reduction ----------------
__global__ void finalize_kernel(float* __restrict__ out) {
    int tid = threadIdx.x;
    float v = g_picked[tid] - logf(g_sumexp[tid]);
    __shared__ float red[4];
    int w = tid >> 5, l = tid & 31;
#pragma unroll
    for (int o = 16; o; o >>= 1) v += __shfl_xor_sync(0xffffffffu, v, o);
    if (l == 0) red[w] = v;
    __syncthreads();
    if (tid == 0) out[0] = red[0] + red[1] + red[2] + red[3];
}

// ---------------- launch ----------------
extern "C" void kernel_launch(void* const* d_in, const int* in_sizes, int n_in,
                              void* d_out, int out_size) {
    const int* fnums = (const int*)d_in[0];
    const int* enums = (const int*)d_in[1];
    const float* emb_f = (const float*)d_in[2];
    const float* Wih_e = (const float*)d_in[3];
    const float* Whh_e = (const float*)d_in[4];
    const float* b_e = (const float*)d_in[5];
    const float* h0_e = (const float*)d_in[6];
    const float* emb_d = (const float*)d_in[7];
    const float* Wih_d = (const float*)d_in[8];
    const float* Whh_d = (const float*)d_in[9];
    const float* b_d = (const float*)d_in[10];
    const float* h0_d = (const float*)d_in[11];
    const float* Wm = (const float*)d_in[12];
    const float* bm = (const float*)d_in[13];
    const float* Wo = (const float*)d_in[14];
    const float* bo = (const float*)d_in[15];
    float* out = (float*)d_out;

    static int inited = 0;
    static float *p_xpre, *p_epre;
    if (!inited) {
        cudaFuncSetAttribute(logits_kernel, cudaFuncAttributeMaxDynamicSharedMemorySize,
                             LOGITS_SMEM);
        cudaFuncSetAttribute(m_hmma_kernel, cudaFuncAttributeMaxDynamicSharedMemorySize,
                             M_SMEM);
        cudaGetSymbolAddress((void**)&p_xpre, g_xpre);
        cudaGetSymbolAddress((void**)&p_epre, g_epre);
        inited = 1;
    }

    // pre-activations: encoder (z=0) + decoder (z=1) concurrently; 128 CTAs
    gemm_kernel<<<dim3(8, 8, 2), 256>>>(emb_f, fnums, Wih_e, b_e,
                                        emb_d, enums, Wih_d, b_d,
                                        p_xpre, p_epre, D);
    // recur (y=0,1) + Wo/Wm->bf16 conversion (y=2..) overlapped in one launch
    recur_kernel<<<dim3(8, 2 + CONV_YS), 512>>>(Whh_e, Whh_d, h0_e, h0_d, Wo, Wm);
    // fused attention: scores + softmax + context + CHbf assembly (+ sumexp init)
    attn_kernel<<<128, 256>>>();
    // M = tanh(CHbf @ Wmbf^T + bm) -> bf16, tensor cores + cp.async pipeline
    m_hmma_kernel<<<8, 256, M_SMEM>>>(bm);
    // logits: tensor cores + 4-stage cp.async Wobf stream
    logits_kernel<<<(VOCAB + 127) / 128, 256, LOGITS_SMEM>>>(bo, enums);
    finalize_kernel<<<1, 128>>>(out);
}